// round 9
// baseline (speedup 1.0000x reference)
#include <cuda_runtime.h>
#include <cuda_bf16.h>
#include <math.h>
#include <stdint.h>

// ---------------- problem constants ----------------
#define N_   4
#define C1_  256
#define C2_  256
#define CH_  128
#define H_   80
#define W_   80
#define HW_  6400
#define M_   (N_*HW_)      // 25600 pixels total
#define PL   124           // smem plane stride (floats) per ci: 10 rows x 12 + pad

// ---------------- scratch (referenced ONLY inside device code!) ----------------
__device__ float g_xn[M_*C1_];        // x in NHWC
__device__ float g_w1d[C1_*9*CH_*2];  // conv1 w, [ci][kk][oc] BN-folded, duplicated pairs
__device__ float g_b1f[CH_];
__device__ float g_w2t[CH_*C2_];      // conv2 w transposed [k][o], BN-folded
__device__ float g_b2f[C2_];
__device__ float g_inwt[C2_*C2_];     // in_w transposed [k][o]
__device__ float g_outwt[C2_*C2_];    // out_w transposed [k][o], BN3-folded
__device__ float g_obf[C2_];          // folded output bias
__device__ float g_y1[M_*CH_];        // conv1 out NHWC
__device__ float g_y2[M_*C2_];        // conv2 out NHWC
__device__ float g_dw[M_*C2_];        // dw+LN+GELU out NHWC
__device__ float g_xproj[M_*C2_];     // input_proj out NHWC
__device__ float g_dcn[M_*C2_];       // dcn out NHWC
__device__ float g_off[M_*18];
__device__ float g_msk[M_*9];

__device__ __forceinline__ float silu_f(float v) { return v / (1.0f + expf(-v)); }

// ---- f32x2 helpers ----
typedef unsigned long long ull;
__device__ __forceinline__ ull pk2(float lo, float hi) {
    ull r; asm("mov.b64 %0, {%1, %2};" : "=l"(r) : "f"(lo), "f"(hi)); return r;
}
__device__ __forceinline__ void fma2(ull& d, ull a, ull b) {
    asm("fma.rn.f32x2 %0, %1, %2, %0;" : "+l"(d) : "l"(a), "l"(b));
}
__device__ __forceinline__ float2 upk2(ull v) {
    float2 r; asm("mov.b64 {%0, %1}, %2;" : "=f"(r.x), "=f"(r.y) : "l"(v)); return r;
}
__device__ __forceinline__ uint32_t smem_u32(const void* p) {
    uint32_t a;
    asm("{ .reg .u64 t; cvta.to.shared.u64 t, %1; cvt.u32.u64 %0, t; }" : "=r"(a) : "l"(p));
    return a;
}
__device__ __forceinline__ void cp4(uint32_t sa, const float* ga, uint32_t sz) {
    asm volatile("cp.async.ca.shared.global [%0], [%1], 4, %2;\n"
                 :: "r"(sa), "l"(ga), "r"(sz));
}

// ================= pack kernels =================
__global__ void pk_w1(const float* __restrict__ w1, const float* __restrict__ g1,
                      const float* __restrict__ b1, const float* __restrict__ m1,
                      const float* __restrict__ v1) {
    int i = blockIdx.x * blockDim.x + threadIdx.x;
    if (i >= C1_*9*CH_) return;
    int oc = i & (CH_-1);
    int kidx = i >> 7;          // ci*9 + kk
    int ci = kidx / 9, kk = kidx - ci*9;
    float s = g1[oc] * rsqrtf(v1[oc] + 1e-5f);
    float val = w1[(size_t)(oc*C1_ + ci)*9 + kk] * s;
    g_w1d[(size_t)i*2]     = val;
    g_w1d[(size_t)i*2 + 1] = val;
    if (i < CH_) g_b1f[i] = b1[i] - m1[i]*s;
}

__global__ void pk_lin(const float* __restrict__ w2, const float* __restrict__ g2,
                       const float* __restrict__ b2, const float* __restrict__ m2,
                       const float* __restrict__ v2, const float* __restrict__ inw,
                       const float* __restrict__ outw, const float* __restrict__ outb,
                       const float* __restrict__ g3, const float* __restrict__ b3,
                       const float* __restrict__ m3, const float* __restrict__ v3) {
    int i = blockIdx.x * blockDim.x + threadIdx.x;
    if (i >= C2_*C2_) return;
    int o = i & 255, k = i >> 8;
    g_inwt[i] = inw[(size_t)o*C2_ + k];
    float s3 = g3[o] * rsqrtf(v3[o] + 1e-5f);
    g_outwt[i] = outw[(size_t)o*C2_ + k] * s3;
    if (k < CH_) {
        float s2 = g2[o] * rsqrtf(v2[o] + 1e-5f);
        g_w2t[(size_t)k*C2_ + o] = w2[(size_t)o*CH_ + k] * s2;
    }
    if (i < C2_) {
        float s2 = g2[i] * rsqrtf(v2[i] + 1e-5f);
        g_b2f[i] = b2[i] - m2[i]*s2;
        float s3b = g3[i] * rsqrtf(v3[i] + 1e-5f);
        g_obf[i] = outb[i]*s3b + b3[i] - m3[i]*s3b;
    }
}

// ================= NCHW -> NHWC transpose =================
__global__ void k_tr(const float* __restrict__ x) {
    __shared__ float tile[32][33];
    int n  = blockIdx.z;
    int c0 = blockIdx.y * 32, p0 = blockIdx.x * 32;
    for (int r = threadIdx.y; r < 32; r += 8)
        tile[r][threadIdx.x] = x[(size_t)(n*C1_ + c0 + r)*HW_ + p0 + threadIdx.x];
    __syncthreads();
    for (int r = threadIdx.y; r < 32; r += 8)
        g_xn[(size_t)(n*HW_ + p0 + r)*C1_ + c0 + threadIdx.x] = tile[threadIdx.x][r];
}

// ================= conv1: 3x3 256->128, BN+SiLU, f32x2, NHWC =================
// 8x8 px tile x 128 oc. 256 threads: py = tid>>5 (warp-uniform row), ocg = tid&31.
// Thread: 4 px-pairs x 4 oc {2ocg, 2ocg+1, 2ocg+64, 2ocg+65}
// -> each weight LDG.128 spans a contiguous 512B warp window (4 wavefronts).
// Input rows broadcast from smem planes; cp.async double-buffered staging.
__global__ __launch_bounds__(256, 2) void c1_fast() {
    __shared__ float sIn[2][32*PL];
    int tid = threadIdx.x;
    int n = blockIdx.z;
    int by = blockIdx.y * 8, bx = blockIdx.x * 8;
    int py   = tid >> 5;          // 0..7, warp-uniform
    int lane = tid & 31;          // ocg for compute, ci for loading
    uint32_t sbase = smem_u32(sIn);

    // loader precompute: pak = ((pixel*256 + lane) << 7) | (hy*12 + hx)
    int pak[13]; unsigned ebits = 0, vbits = 0;
    #pragma unroll
    for (int j = 0; j < 13; j++) {
        int p = py + j*8;
        pak[j] = 0;
        if (p < 100) {
            int hy = p / 10, hx = p - hy*10;
            int gy = by + hy - 1, gx = bx + hx - 1;
            bool v = (gy >= 0 && gy < H_ && gx >= 0 && gx < W_);
            int pix = v ? (n*HW_ + gy*W_ + gx) : 0;
            pak[j] = ((pix*256 + lane) << 7) | (hy*12 + hx);
            ebits |= 1u << j;
            if (v) vbits |= 1u << j;
        }
    }

    auto load_chunk = [&](int cc, int b) {
        uint32_t soff0 = sbase + (uint32_t)(b * 32 * PL + lane * PL) * 4u;
        #pragma unroll
        for (int j = 0; j < 13; j++) {
            if (ebits >> j & 1) {
                uint32_t sa = soff0 + (uint32_t)(pak[j] & 127) * 4u;
                uint32_t sz = (vbits >> j & 1) ? 4u : 0u;
                cp4(sa, g_xn + (pak[j] >> 7) + cc, sz);
            }
        }
        asm volatile("cp.async.commit_group;");
    };

    load_chunk(0, 0);
    asm volatile("cp.async.wait_group 0;");
    __syncthreads();

    ull acc[4][4];                 // [px pair][oc slot]
    #pragma unroll
    for (int i = 0; i < 4; i++)
        #pragma unroll
        for (int o = 0; o < 4; o++) acc[i][o] = 0ull;

    int buf = 0;
    for (int cc = 0; cc < C1_; cc += 32) {
        if (cc + 32 < C1_) load_chunk(cc + 32, buf ^ 1);

        #pragma unroll 2
        for (int ci = 0; ci < 32; ci++) {
            const float* plane = &sIn[buf][ci * PL];
            const float* wb = &g_w1d[(size_t)((cc + ci)*9)*256 + lane*4];
            #pragma unroll
            for (int ky = 0; ky < 3; ky++) {
                const float* row = plane + (py + ky) * 12;
                ulonglong2 t0 = *(const ulonglong2*)row;        // (x0,x1)(x2,x3)
                ulonglong2 t1 = *(const ulonglong2*)(row + 4);  // (x4,x5)(x6,x7)
                ull u0 = t0.x, u1 = t0.y, u2 = t1.x, u3 = t1.y;
                ull u4 = *(const ull*)(row + 8);                // (x8,x9)
                float2 f0 = upk2(u0), f1 = upk2(u1), f2 = upk2(u2),
                       f3 = upk2(u3), f4 = upk2(u4);
                ull o0 = pk2(f0.y, f1.x), o1 = pk2(f1.y, f2.x);
                ull o2 = pk2(f2.y, f3.x), o3 = pk2(f3.y, f4.x);
                #pragma unroll
                for (int kx = 0; kx < 3; kx++) {
                    const float* wk = wb + (ky*3 + kx)*256;
                    ulonglong2 wlo = *(const ulonglong2*)wk;          // oc 2ocg, 2ocg+1 (dup)
                    ulonglong2 whi = *(const ulonglong2*)(wk + 128);  // oc 2ocg+64, +65 (dup)
                    ull p0, p1, p2, p3;
                    if (kx == 0)      { p0 = u0; p1 = u1; p2 = u2; p3 = u3; }
                    else if (kx == 1) { p0 = o0; p1 = o1; p2 = o2; p3 = o3; }
                    else              { p0 = u1; p1 = u2; p2 = u3; p3 = u4; }
                    fma2(acc[0][0], p0, wlo.x); fma2(acc[0][1], p0, wlo.y);
                    fma2(acc[0][2], p0, whi.x); fma2(acc[0][3], p0, whi.y);
                    fma2(acc[1][0], p1, wlo.x); fma2(acc[1][1], p1, wlo.y);
                    fma2(acc[1][2], p1, whi.x); fma2(acc[1][3], p1, whi.y);
                    fma2(acc[2][0], p2, wlo.x); fma2(acc[2][1], p2, wlo.y);
                    fma2(acc[2][2], p2, whi.x); fma2(acc[2][3], p2, whi.y);
                    fma2(acc[3][0], p3, wlo.x); fma2(acc[3][1], p3, wlo.y);
                    fma2(acc[3][2], p3, whi.x); fma2(acc[3][3], p3, whi.y);
                }
            }
        }

        if (cc + 32 < C1_) asm volatile("cp.async.wait_group 0;");
        __syncthreads();
        buf ^= 1;
    }

    // epilogue: bias + SiLU -> NHWC. oc set {2ocg, 2ocg+1, 2ocg+64, 2ocg+65}
    int oc0 = lane * 2;
    float b0 = g_b1f[oc0], b1 = g_b1f[oc0+1], b2 = g_b1f[oc0+64], b3 = g_b1f[oc0+65];
    int gy = by + py;
    size_t rowbase = (size_t)(n*HW_ + gy*W_ + bx)*CH_;
    #pragma unroll
    for (int j = 0; j < 4; j++) {
        float2 v0 = upk2(acc[j][0]), v1 = upk2(acc[j][1]);
        float2 v2 = upk2(acc[j][2]), v3 = upk2(acc[j][3]);
        size_t pb0 = rowbase + (size_t)(2*j)*CH_;
        size_t pb1 = pb0 + CH_;
        float2 e0 = {silu_f(v0.x + b0), silu_f(v1.x + b1)};
        float2 e1 = {silu_f(v2.x + b2), silu_f(v3.x + b3)};
        float2 f0 = {silu_f(v0.y + b0), silu_f(v1.y + b1)};
        float2 f1 = {silu_f(v2.y + b2), silu_f(v3.y + b3)};
        *(float2*)&g_y1[pb0 + oc0]      = e0;
        *(float2*)&g_y1[pb0 + oc0 + 64] = e1;
        *(float2*)&g_y1[pb1 + oc0]      = f0;
        *(float2*)&g_y1[pb1 + oc0 + 64] = f1;
    }
}

// ================= GEMM: out[M,256] = A[M,KD] @ B[KD,256] (+epilogue) =================
// MODE 0 (conv2):  A=g_y1  B=g_w2t  bias=g_b2f  SiLU -> g_y2
// MODE 1 (inproj): A=g_y2  B=g_inwt bias=ext    none -> g_xproj
// MODE 2 (outproj):A=g_dcn B=g_outwt bias=g_obf SiLU+resid -> ext out (NCHW)
template<int KD, int MODE>
__global__ __launch_bounds__(256) void gm(const float* __restrict__ bias_ext,
                                          float* __restrict__ out_ext,
                                          const float* __restrict__ resid_ext) {
    const float* A    = (MODE == 0) ? g_y1  : (MODE == 1 ? g_y2   : g_dcn);
    const float* B    = (MODE == 0) ? g_w2t : (MODE == 1 ? g_inwt : g_outwt);
    const float* bias = (MODE == 0) ? g_b2f : (MODE == 1 ? bias_ext : g_obf);
    float* C          = (MODE == 0) ? g_y2  : (MODE == 1 ? g_xproj : out_ext);

    __shared__ float As[16][68];
    __shared__ float Bs[16][136];
    int tid = threadIdx.x;
    int tx = tid & 15, ty = tid >> 4;
    int m0 = blockIdx.x * 64, n0 = blockIdx.y * 128;

    ull acc[4][4];
    #pragma unroll
    for (int i = 0; i < 4; i++)
        #pragma unroll
        for (int j = 0; j < 4; j++) acc[i][j] = 0ull;

    int ar = tid >> 2, ak = (tid & 3) * 4;
    int bk = tid >> 4, bn = (tid & 15) * 8;

    for (int k0 = 0; k0 < KD; k0 += 16) {
        float4 av = *(const float4*)&A[(size_t)(m0 + ar)*KD + k0 + ak];
        const float4* bp = (const float4*)&B[(size_t)(k0 + bk)*256 + n0 + bn];
        float4 bv0 = bp[0], bv1 = bp[1];
        As[ak+0][ar] = av.x; As[ak+1][ar] = av.y;
        As[ak+2][ar] = av.z; As[ak+3][ar] = av.w;
        *(float4*)&Bs[bk][bn]     = bv0;
        *(float4*)&Bs[bk][bn + 4] = bv1;
        __syncthreads();
        #pragma unroll
        for (int k = 0; k < 16; k++) {
            float4 a4 = *(const float4*)&As[k][ty*4];
            ull b[4];
            #pragma unroll
            for (int j = 0; j < 4; j++)
                b[j] = *(const ull*)&Bs[k][tx*8 + 2*j];
            ull ad0 = pk2(a4.x, a4.x), ad1 = pk2(a4.y, a4.y);
            ull ad2 = pk2(a4.z, a4.z), ad3 = pk2(a4.w, a4.w);
            #pragma unroll
            for (int j = 0; j < 4; j++) {
                fma2(acc[0][j], ad0, b[j]);
                fma2(acc[1][j], ad1, b[j]);
                fma2(acc[2][j], ad2, b[j]);
                fma2(acc[3][j], ad3, b[j]);
            }
        }
        __syncthreads();
    }

    #pragma unroll
    for (int i = 0; i < 4; i++) {
        int m = m0 + ty*4 + i;
        int nimg = m / HW_;
        int pp   = m - nimg*HW_;
        #pragma unroll
        for (int j = 0; j < 4; j++) {
            float2 v = upk2(acc[i][j]);
            int nn = n0 + tx*8 + 2*j;
            float r0 = v.x + bias[nn];
            float r1 = v.y + bias[nn+1];
            if (MODE == 0 || MODE == 2) { r0 = silu_f(r0); r1 = silu_f(r1); }
            if (MODE <= 1) {
                C[(size_t)m*256 + nn]     = r0;
                C[(size_t)m*256 + nn + 1] = r1;
            } else {
                size_t base = (size_t)(nimg*256 + nn)*HW_ + pp;
                C[base]       = resid_ext[base]       + r0;
                C[base + HW_] = resid_ext[base + HW_] + r1;
            }
        }
    }
}

// ================= depthwise 3x3 + bias + LayerNorm + GELU =================
__global__ __launch_bounds__(256) void p_dwlngelu(const float* __restrict__ dww,
                                                  const float* __restrict__ dwb,
                                                  const float* __restrict__ lng,
                                                  const float* __restrict__ lnb) {
    int p = blockIdx.x;
    int n = p / HW_, pp = p - n*HW_;
    int y = pp / W_, xx = pp - y*W_;
    int c = threadIdx.x;

    float acc = 0.0f;
    for (int ky = 0; ky < 3; ky++) {
        int gy = y + ky - 1;
        if (gy < 0 || gy >= H_) continue;
        for (int kx = 0; kx < 3; kx++) {
            int gx = xx + kx - 1;
            if (gx < 0 || gx >= W_) continue;
            acc += g_y2[(size_t)(n*HW_ + gy*W_ + gx)*C2_ + c] * dww[c*9 + ky*3 + kx];
        }
    }
    acc += dwb[c];

    __shared__ float red[8], red2[8];
    float v = acc;
    #pragma unroll
    for (int o = 16; o; o >>= 1) v += __shfl_xor_sync(0xffffffffu, v, o);
    if ((c & 31) == 0) red[c >> 5] = v;
    __syncthreads();
    float tot = 0.0f;
    #pragma unroll
    for (int i = 0; i < 8; i++) tot += red[i];
    float mu = tot * (1.0f/256.0f);

    float d = acc - mu;
    float v2 = d*d;
    #pragma unroll
    for (int o = 16; o; o >>= 1) v2 += __shfl_xor_sync(0xffffffffu, v2, o);
    if ((c & 31) == 0) red2[c >> 5] = v2;
    __syncthreads();
    float tot2 = 0.0f;
    #pragma unroll
    for (int i = 0; i < 8; i++) tot2 += red2[i];
    float var = tot2 * (1.0f/256.0f);

    float outv = d * rsqrtf(var + 1e-6f) * lng[c] + lnb[c];
    float gel = 0.5f * outv * (1.0f + erff(outv * 0.70710678118654752f));
    g_dw[(size_t)p*C2_ + c] = gel;
}

// ================= offset + mask heads (weights cached in smem, 32 px/block) ========
__global__ __launch_bounds__(256) void p_offmask2(const float* __restrict__ offw,
                                                  const float* __restrict__ offb,
                                                  const float* __restrict__ mskw,
                                                  const float* __restrict__ mskb) {
    __shared__ float wsm[27*256];
    __shared__ float sdw[256];
    __shared__ float sres[27];
    int tid = threadIdx.x;
    int warp = tid >> 5, lane = tid & 31;

    #pragma unroll
    for (int i = tid; i < 27*256; i += 256) {
        int r = i >> 8, c = i & 255;
        wsm[i] = (r < 18) ? offw[r*256 + c] : mskw[(r - 18)*256 + c];
    }
    __syncthreads();

    int p0 = blockIdx.x * 32;
    for (int pi = 0; pi < 32; pi++) {
        int p = p0 + pi;
        sdw[tid] = g_dw[(size_t)p*256 + tid];
        __syncthreads();
        for (int r = warp; r < 27; r += 8) {
            const float* wr = &wsm[r*256];
            float s = 0.0f;
            #pragma unroll
            for (int k = 0; k < 8; k++) s += sdw[lane + 32*k] * wr[lane + 32*k];
            #pragma unroll
            for (int o = 16; o; o >>= 1) s += __shfl_xor_sync(0xffffffffu, s, o);
            if (lane == 0) sres[r] = s;
        }
        __syncthreads();
        if (tid < 18) g_off[(size_t)p*18 + tid] = sres[tid] + offb[tid];
        if (tid == 0) {
            float l[9], mx = -1e30f;
            #pragma unroll
            for (int k = 0; k < 9; k++) { l[k] = sres[18+k] + mskb[k]; mx = fmaxf(mx, l[k]); }
            float se = 0.0f;
            #pragma unroll
            for (int k = 0; k < 9; k++) { l[k] = expf(l[k] - mx); se += l[k]; }
            float inv = 1.0f / se;
            #pragma unroll
            for (int k = 0; k < 9; k++) g_msk[(size_t)p*9 + k] = l[k]*inv;
        }
    }
}

// ================= DCNv3 core =================
__global__ __launch_bounds__(256) void p_dcn() {
    int p = blockIdx.x;
    int n = p / HW_, pp = p - n*HW_;
    int y = pp / W_, xx = pp - y*W_;
    int c = threadIdx.x;

    __shared__ float sw[9][4];
    __shared__ int   sx0[9], sy0[9];
    if (threadIdx.x < 9) {
        int k = threadIdx.x;
        float m  = g_msk[(size_t)p*9 + k];
        float ox = g_off[(size_t)p*18 + 2*k];
        float oy = g_off[(size_t)p*18 + 2*k + 1];
        float px = (float)xx + (float)(k/3) + ox;     // padded coords
        float py = (float)y  + (float)(k%3) + oy;
        float x0f = floorf(px), y0f = floorf(py);
        float lw = px - x0f, lh = py - y0f;
        sw[k][0] = m * (1.0f - lh) * (1.0f - lw);
        sw[k][1] = m * (1.0f - lh) * lw;
        sw[k][2] = m * lh * (1.0f - lw);
        sw[k][3] = m * lh * lw;
        sx0[k] = (int)x0f;
        sy0[k] = (int)y0f;
    }
    __syncthreads();

    const float* Xb = &g_xproj[(size_t)n * HW_ * C2_];
    float acc = 0.0f;
    for (int k = 0; k < 9; k++) {
        int x0 = sx0[k], y0 = sy0[k];
        #pragma unroll
        for (int t = 0; t < 4; t++) {
            int xi = x0 + (t & 1);
            int yi = y0 + (t >> 1);
            if (xi >= 1 && xi <= W_ && yi >= 1 && yi <= H_) {
                float val = Xb[(size_t)((yi-1)*W_ + (xi-1))*C2_ + c];
                acc = fmaf(sw[k][t], val, acc);
            }
        }
    }
    g_dcn[(size_t)p*C2_ + c] = acc;
}

// ---------------- launch ----------------
extern "C" void kernel_launch(void* const* d_in, const int* in_sizes, int n_in,
                              void* d_out, int out_size) {
    const float* x     = (const float*)d_in[0];
    const float* w1    = (const float*)d_in[1];
    const float* g1    = (const float*)d_in[2];
    const float* b1    = (const float*)d_in[3];
    const float* m1    = (const float*)d_in[4];
    const float* v1    = (const float*)d_in[5];
    const float* w2    = (const float*)d_in[6];
    const float* g2    = (const float*)d_in[7];
    const float* b2    = (const float*)d_in[8];
    const float* m2    = (const float*)d_in[9];
    const float* v2    = (const float*)d_in[10];
    const float* dw_w  = (const float*)d_in[11];
    const float* dw_b  = (const float*)d_in[12];
    const float* ln_g  = (const float*)d_in[13];
    const float* ln_b  = (const float*)d_in[14];
    const float* off_w = (const float*)d_in[15];
    const float* off_b = (const float*)d_in[16];
    const float* msk_w = (const float*)d_in[17];
    const float* msk_b = (const float*)d_in[18];
    const float* in_w  = (const float*)d_in[19];
    const float* in_b  = (const float*)d_in[20];
    const float* out_w = (const float*)d_in[21];
    const float* out_b = (const float*)d_in[22];
    const float* g3    = (const float*)d_in[23];
    const float* b3    = (const float*)d_in[24];
    const float* m3    = (const float*)d_in[25];
    const float* v3    = (const float*)d_in[26];
    float* out = (float*)d_out;

    pk_w1<<<(C1_*9*CH_ + 255)/256, 256>>>(w1, g1, b1, m1, v1);
    pk_lin<<<(C2_*C2_ + 255)/256, 256>>>(w2, g2, b2, m2, v2, in_w, out_w, out_b,
                                         g3, b3, m3, v3);
    k_tr<<<dim3(HW_/32, C1_/32, N_), dim3(32, 8)>>>(x);
    c1_fast<<<dim3(W_/8, H_/8, N_), 256>>>();
    gm<128, 0><<<dim3(M_/64, 2), 256>>>(nullptr, nullptr, nullptr);
    p_dwlngelu<<<M_, 256>>>(dw_w, dw_b, ln_g, ln_b);
    p_offmask2<<<M_/32, 256>>>(off_w, off_b, msk_w, msk_b);
    gm<256, 1><<<dim3(M_/64, 2), 256>>>(in_b, nullptr, nullptr);
    p_dcn<<<M_, 256>>>();
    gm<256, 2><<<dim3(M_/64, 2), 256>>>(nullptr, out, x);
}

// round 10
// speedup vs baseline: 1.2064x; 1.2064x over previous
#include <cuda_runtime.h>
#include <cuda_bf16.h>
#include <math.h>
#include <stdint.h>

// ---------------- problem constants ----------------
#define N_   4
#define C1_  256
#define C2_  256
#define CH_  128
#define H_   80
#define W_   80
#define HW_  6400
#define M_   (N_*HW_)      // 25600 pixels total
#define PL   124           // smem plane stride (floats) per ci: 10 rows x 12 + pad

// ---------------- scratch (referenced ONLY inside device code!) ----------------
__device__ float g_xn[M_*C1_];        // x in NHWC
__device__ float g_w1n[C1_*9*CH_];    // conv1 w, [ci][kk][oc], BN-folded (non-dup)
__device__ float g_b1f[CH_];
__device__ float g_w2t[CH_*C2_];      // conv2 w transposed [k][o], BN-folded
__device__ float g_b2f[C2_];
__device__ float g_inwt[C2_*C2_];     // in_w transposed [k][o]
__device__ float g_outwt[C2_*C2_];    // out_w transposed [k][o], BN3-folded
__device__ float g_obf[C2_];          // folded output bias
__device__ float g_y1[M_*CH_];        // conv1 out NHWC
__device__ float g_y2[M_*C2_];        // conv2 out NHWC
__device__ float g_dw[M_*C2_];        // dw+LN+GELU out NHWC
__device__ float g_xproj[M_*C2_];     // input_proj out NHWC
__device__ float g_dcn[M_*C2_];       // dcn out NHWC
__device__ float g_off[M_*18];
__device__ float g_msk[M_*9];

__device__ __forceinline__ float silu_f(float v) { return v / (1.0f + expf(-v)); }

// ---- f32x2 helpers ----
typedef unsigned long long ull;
__device__ __forceinline__ ull pk2(float lo, float hi) {
    ull r; asm("mov.b64 %0, {%1, %2};" : "=l"(r) : "f"(lo), "f"(hi)); return r;
}
__device__ __forceinline__ void fma2(ull& d, ull a, ull b) {
    asm("fma.rn.f32x2 %0, %1, %2, %0;" : "+l"(d) : "l"(a), "l"(b));
}
__device__ __forceinline__ float2 upk2(ull v) {
    float2 r; asm("mov.b64 {%0, %1}, %2;" : "=f"(r.x), "=f"(r.y) : "l"(v)); return r;
}
__device__ __forceinline__ uint32_t smem_u32(const void* p) {
    uint32_t a;
    asm("{ .reg .u64 t; cvta.to.shared.u64 t, %1; cvt.u32.u64 %0, t; }" : "=r"(a) : "l"(p));
    return a;
}
__device__ __forceinline__ void cp4(uint32_t sa, const float* ga, uint32_t sz) {
    asm volatile("cp.async.ca.shared.global [%0], [%1], 4, %2;\n"
                 :: "r"(sa), "l"(ga), "r"(sz));
}

// ================= pack kernels =================
__global__ void pk_w1(const float* __restrict__ w1, const float* __restrict__ g1,
                      const float* __restrict__ b1, const float* __restrict__ m1,
                      const float* __restrict__ v1) {
    int i = blockIdx.x * blockDim.x + threadIdx.x;
    if (i >= C1_*9*CH_) return;
    int oc = i & (CH_-1);
    int kidx = i >> 7;          // ci*9 + kk
    int ci = kidx / 9, kk = kidx - ci*9;
    float s = g1[oc] * rsqrtf(v1[oc] + 1e-5f);
    g_w1n[i] = w1[(size_t)(oc*C1_ + ci)*9 + kk] * s;
    if (i < CH_) g_b1f[i] = b1[i] - m1[i]*s;
}

__global__ void pk_lin(const float* __restrict__ w2, const float* __restrict__ g2,
                       const float* __restrict__ b2, const float* __restrict__ m2,
                       const float* __restrict__ v2, const float* __restrict__ inw,
                       const float* __restrict__ outw, const float* __restrict__ outb,
                       const float* __restrict__ g3, const float* __restrict__ b3,
                       const float* __restrict__ m3, const float* __restrict__ v3) {
    int i = blockIdx.x * blockDim.x + threadIdx.x;
    if (i >= C2_*C2_) return;
    int o = i & 255, k = i >> 8;
    g_inwt[i] = inw[(size_t)o*C2_ + k];
    float s3 = g3[o] * rsqrtf(v3[o] + 1e-5f);
    g_outwt[i] = outw[(size_t)o*C2_ + k] * s3;
    if (k < CH_) {
        float s2 = g2[o] * rsqrtf(v2[o] + 1e-5f);
        g_w2t[(size_t)k*C2_ + o] = w2[(size_t)o*CH_ + k] * s2;
    }
    if (i < C2_) {
        float s2 = g2[i] * rsqrtf(v2[i] + 1e-5f);
        g_b2f[i] = b2[i] - m2[i]*s2;
        float s3b = g3[i] * rsqrtf(v3[i] + 1e-5f);
        g_obf[i] = outb[i]*s3b + b3[i] - m3[i]*s3b;
    }
}

// ================= NCHW -> NHWC transpose =================
__global__ void k_tr(const float* __restrict__ x) {
    __shared__ float tile[32][33];
    int n  = blockIdx.z;
    int c0 = blockIdx.y * 32, p0 = blockIdx.x * 32;
    for (int r = threadIdx.y; r < 32; r += 8)
        tile[r][threadIdx.x] = x[(size_t)(n*C1_ + c0 + r)*HW_ + p0 + threadIdx.x];
    __syncthreads();
    for (int r = threadIdx.y; r < 32; r += 8)
        g_xn[(size_t)(n*HW_ + p0 + r)*C1_ + c0 + threadIdx.x] = tile[threadIdx.x][r];
}

// ================= conv1: 3x3 256->128, BN+SiLU, f32x2, NHWC =================
// 8x8 px tile x 128 oc. 256 threads: py = tid>>5 (warp-uniform row), lane = oc group.
// Thread: 4 px-pairs x 4 oc {2l, 2l+1, 2l+64, 2l+65}. Weights non-dup: float2 loads
// spanning 256B per warp (2 wavefronts each), duplicated to f32x2 in registers.
// cp.async double-buffered input staging; 3 blocks/SM for latency cover.
__global__ __launch_bounds__(256, 3) void c1_fast() {
    __shared__ float sIn[2][32*PL];
    int tid = threadIdx.x;
    int n = blockIdx.z;
    int by = blockIdx.y * 8, bx = blockIdx.x * 8;
    int py   = tid >> 5;          // 0..7, warp-uniform
    int lane = tid & 31;
    uint32_t sbase = smem_u32(sIn);

    // loader precompute: pak = ((pixel*256 + lane) << 7) | (hy*12 + hx)
    int pak[13]; unsigned ebits = 0, vbits = 0;
    #pragma unroll
    for (int j = 0; j < 13; j++) {
        int p = py + j*8;
        pak[j] = 0;
        if (p < 100) {
            int hy = p / 10, hx = p - hy*10;
            int gy = by + hy - 1, gx = bx + hx - 1;
            bool v = (gy >= 0 && gy < H_ && gx >= 0 && gx < W_);
            int pix = v ? (n*HW_ + gy*W_ + gx) : 0;
            pak[j] = ((pix*256 + lane) << 7) | (hy*12 + hx);
            ebits |= 1u << j;
            if (v) vbits |= 1u << j;
        }
    }

    auto load_chunk = [&](int cc, int b) {
        uint32_t soff0 = sbase + (uint32_t)(b * 32 * PL + lane * PL) * 4u;
        #pragma unroll
        for (int j = 0; j < 13; j++) {
            if (ebits >> j & 1) {
                uint32_t sa = soff0 + (uint32_t)(pak[j] & 127) * 4u;
                uint32_t sz = (vbits >> j & 1) ? 4u : 0u;
                cp4(sa, g_xn + (pak[j] >> 7) + cc, sz);
            }
        }
        asm volatile("cp.async.commit_group;");
    };

    load_chunk(0, 0);
    asm volatile("cp.async.wait_group 0;");
    __syncthreads();

    ull acc[4][4];                 // [px pair][oc slot]
    #pragma unroll
    for (int i = 0; i < 4; i++)
        #pragma unroll
        for (int o = 0; o < 4; o++) acc[i][o] = 0ull;

    int buf = 0;
    for (int cc = 0; cc < C1_; cc += 32) {
        if (cc + 32 < C1_) load_chunk(cc + 32, buf ^ 1);

        #pragma unroll 2
        for (int ci = 0; ci < 32; ci++) {
            const float* plane = &sIn[buf][ci * PL];
            const float* wb = &g_w1n[(size_t)((cc + ci)*9)*128 + lane*2];
            #pragma unroll
            for (int ky = 0; ky < 3; ky++) {
                const float* row = plane + (py + ky) * 12;
                ulonglong2 t0 = *(const ulonglong2*)row;        // (x0,x1)(x2,x3)
                ulonglong2 t1 = *(const ulonglong2*)(row + 4);  // (x4,x5)(x6,x7)
                ull u0 = t0.x, u1 = t0.y, u2 = t1.x, u3 = t1.y;
                ull u4 = *(const ull*)(row + 8);                // (x8,x9)
                float2 f0 = upk2(u0), f1 = upk2(u1), f2 = upk2(u2),
                       f3 = upk2(u3), f4 = upk2(u4);
                ull o0 = pk2(f0.y, f1.x), o1 = pk2(f1.y, f2.x);
                ull o2 = pk2(f2.y, f3.x), o3 = pk2(f3.y, f4.x);
                #pragma unroll
                for (int kx = 0; kx < 3; kx++) {
                    const float* wk = wb + (ky*3 + kx)*128;
                    float2 wl = *(const float2*)wk;          // oc 2l, 2l+1
                    float2 wh = *(const float2*)(wk + 64);   // oc 2l+64, 2l+65
                    ull w0 = pk2(wl.x, wl.x), w1 = pk2(wl.y, wl.y);
                    ull w2 = pk2(wh.x, wh.x), w3 = pk2(wh.y, wh.y);
                    ull p0, p1, p2, p3;
                    if (kx == 0)      { p0 = u0; p1 = u1; p2 = u2; p3 = u3; }
                    else if (kx == 1) { p0 = o0; p1 = o1; p2 = o2; p3 = o3; }
                    else              { p0 = u1; p1 = u2; p2 = u3; p3 = u4; }
                    fma2(acc[0][0], p0, w0); fma2(acc[0][1], p0, w1);
                    fma2(acc[0][2], p0, w2); fma2(acc[0][3], p0, w3);
                    fma2(acc[1][0], p1, w0); fma2(acc[1][1], p1, w1);
                    fma2(acc[1][2], p1, w2); fma2(acc[1][3], p1, w3);
                    fma2(acc[2][0], p2, w0); fma2(acc[2][1], p2, w1);
                    fma2(acc[2][2], p2, w2); fma2(acc[2][3], p2, w3);
                    fma2(acc[3][0], p3, w0); fma2(acc[3][1], p3, w1);
                    fma2(acc[3][2], p3, w2); fma2(acc[3][3], p3, w3);
                }
            }
        }

        if (cc + 32 < C1_) asm volatile("cp.async.wait_group 0;");
        __syncthreads();
        buf ^= 1;
    }

    // epilogue: bias + SiLU -> NHWC. oc set {2l, 2l+1, 2l+64, 2l+65}
    int oc0 = lane * 2;
    float b0 = g_b1f[oc0], b1 = g_b1f[oc0+1], b2 = g_b1f[oc0+64], b3 = g_b1f[oc0+65];
    int gy = by + py;
    size_t rowbase = (size_t)(n*HW_ + gy*W_ + bx)*CH_;
    #pragma unroll
    for (int j = 0; j < 4; j++) {
        float2 v0 = upk2(acc[j][0]), v1 = upk2(acc[j][1]);
        float2 v2 = upk2(acc[j][2]), v3 = upk2(acc[j][3]);
        size_t pb0 = rowbase + (size_t)(2*j)*CH_;
        size_t pb1 = pb0 + CH_;
        float2 e0 = {silu_f(v0.x + b0), silu_f(v1.x + b1)};
        float2 e1 = {silu_f(v2.x + b2), silu_f(v3.x + b3)};
        float2 f0 = {silu_f(v0.y + b0), silu_f(v1.y + b1)};
        float2 f1 = {silu_f(v2.y + b2), silu_f(v3.y + b3)};
        *(float2*)&g_y1[pb0 + oc0]      = e0;
        *(float2*)&g_y1[pb0 + oc0 + 64] = e1;
        *(float2*)&g_y1[pb1 + oc0]      = f0;
        *(float2*)&g_y1[pb1 + oc0 + 64] = f1;
    }
}

// ================= GEMM: out[M,256] = A[M,KD] @ B[KD,256] (+epilogue) =================
// MODE 0 (conv2):  A=g_y1  B=g_w2t  bias=g_b2f  SiLU -> g_y2
// MODE 1 (inproj): A=g_y2  B=g_inwt bias=ext    none -> g_xproj
// MODE 2 (outproj):A=g_dcn B=g_outwt bias=g_obf SiLU+resid -> ext out (NCHW)
template<int KD, int MODE>
__global__ __launch_bounds__(256) void gm(const float* __restrict__ bias_ext,
                                          float* __restrict__ out_ext,
                                          const float* __restrict__ resid_ext) {
    const float* A    = (MODE == 0) ? g_y1  : (MODE == 1 ? g_y2   : g_dcn);
    const float* B    = (MODE == 0) ? g_w2t : (MODE == 1 ? g_inwt : g_outwt);
    const float* bias = (MODE == 0) ? g_b2f : (MODE == 1 ? bias_ext : g_obf);
    float* C          = (MODE == 0) ? g_y2  : (MODE == 1 ? g_xproj : out_ext);

    __shared__ float As[16][68];
    __shared__ float Bs[16][136];
    int tid = threadIdx.x;
    int tx = tid & 15, ty = tid >> 4;
    int m0 = blockIdx.x * 64, n0 = blockIdx.y * 128;

    ull acc[4][4];
    #pragma unroll
    for (int i = 0; i < 4; i++)
        #pragma unroll
        for (int j = 0; j < 4; j++) acc[i][j] = 0ull;

    int ar = tid >> 2, ak = (tid & 3) * 4;
    int bk = tid >> 4, bn = (tid & 15) * 8;

    for (int k0 = 0; k0 < KD; k0 += 16) {
        float4 av = *(const float4*)&A[(size_t)(m0 + ar)*KD + k0 + ak];
        const float4* bp = (const float4*)&B[(size_t)(k0 + bk)*256 + n0 + bn];
        float4 bv0 = bp[0], bv1 = bp[1];
        As[ak+0][ar] = av.x; As[ak+1][ar] = av.y;
        As[ak+2][ar] = av.z; As[ak+3][ar] = av.w;
        *(float4*)&Bs[bk][bn]     = bv0;
        *(float4*)&Bs[bk][bn + 4] = bv1;
        __syncthreads();
        #pragma unroll
        for (int k = 0; k < 16; k++) {
            float4 a4 = *(const float4*)&As[k][ty*4];
            ull b[4];
            #pragma unroll
            for (int j = 0; j < 4; j++)
                b[j] = *(const ull*)&Bs[k][tx*8 + 2*j];
            ull ad0 = pk2(a4.x, a4.x), ad1 = pk2(a4.y, a4.y);
            ull ad2 = pk2(a4.z, a4.z), ad3 = pk2(a4.w, a4.w);
            #pragma unroll
            for (int j = 0; j < 4; j++) {
                fma2(acc[0][j], ad0, b[j]);
                fma2(acc[1][j], ad1, b[j]);
                fma2(acc[2][j], ad2, b[j]);
                fma2(acc[3][j], ad3, b[j]);
            }
        }
        __syncthreads();
    }

    #pragma unroll
    for (int i = 0; i < 4; i++) {
        int m = m0 + ty*4 + i;
        int nimg = m / HW_;
        int pp   = m - nimg*HW_;
        #pragma unroll
        for (int j = 0; j < 4; j++) {
            float2 v = upk2(acc[i][j]);
            int nn = n0 + tx*8 + 2*j;
            float r0 = v.x + bias[nn];
            float r1 = v.y + bias[nn+1];
            if (MODE == 0 || MODE == 2) { r0 = silu_f(r0); r1 = silu_f(r1); }
            if (MODE <= 1) {
                C[(size_t)m*256 + nn]     = r0;
                C[(size_t)m*256 + nn + 1] = r1;
            } else {
                size_t base = (size_t)(nimg*256 + nn)*HW_ + pp;
                C[base]       = resid_ext[base]       + r0;
                C[base + HW_] = resid_ext[base + HW_] + r1;
            }
        }
    }
}

// ================= depthwise 3x3 + bias + LayerNorm + GELU =================
__global__ __launch_bounds__(256) void p_dwlngelu(const float* __restrict__ dww,
                                                  const float* __restrict__ dwb,
                                                  const float* __restrict__ lng,
                                                  const float* __restrict__ lnb) {
    int p = blockIdx.x;
    int n = p / HW_, pp = p - n*HW_;
    int y = pp / W_, xx = pp - y*W_;
    int c = threadIdx.x;

    float acc = 0.0f;
    for (int ky = 0; ky < 3; ky++) {
        int gy = y + ky - 1;
        if (gy < 0 || gy >= H_) continue;
        for (int kx = 0; kx < 3; kx++) {
            int gx = xx + kx - 1;
            if (gx < 0 || gx >= W_) continue;
            acc += g_y2[(size_t)(n*HW_ + gy*W_ + gx)*C2_ + c] * dww[c*9 + ky*3 + kx];
        }
    }
    acc += dwb[c];

    __shared__ float red[8], red2[8];
    float v = acc;
    #pragma unroll
    for (int o = 16; o; o >>= 1) v += __shfl_xor_sync(0xffffffffu, v, o);
    if ((c & 31) == 0) red[c >> 5] = v;
    __syncthreads();
    float tot = 0.0f;
    #pragma unroll
    for (int i = 0; i < 8; i++) tot += red[i];
    float mu = tot * (1.0f/256.0f);

    float d = acc - mu;
    float v2 = d*d;
    #pragma unroll
    for (int o = 16; o; o >>= 1) v2 += __shfl_xor_sync(0xffffffffu, v2, o);
    if ((c & 31) == 0) red2[c >> 5] = v2;
    __syncthreads();
    float tot2 = 0.0f;
    #pragma unroll
    for (int i = 0; i < 8; i++) tot2 += red2[i];
    float var = tot2 * (1.0f/256.0f);

    float outv = d * rsqrtf(var + 1e-6f) * lng[c] + lnb[c];
    float gel = 0.5f * outv * (1.0f + erff(outv * 0.70710678118654752f));
    g_dw[(size_t)p*C2_ + c] = gel;
}

// ================= offset + mask heads (weights cached in smem, 32 px/block) ========
__global__ __launch_bounds__(256) void p_offmask2(const float* __restrict__ offw,
                                                  const float* __restrict__ offb,
                                                  const float* __restrict__ mskw,
                                                  const float* __restrict__ mskb) {
    __shared__ float wsm[27*256];
    __shared__ float sdw[256];
    __shared__ float sres[27];
    int tid = threadIdx.x;
    int warp = tid >> 5, lane = tid & 31;

    #pragma unroll
    for (int i = tid; i < 27*256; i += 256) {
        int r = i >> 8, c = i & 255;
        wsm[i] = (r < 18) ? offw[r*256 + c] : mskw[(r - 18)*256 + c];
    }
    __syncthreads();

    int p0 = blockIdx.x * 32;
    for (int pi = 0; pi < 32; pi++) {
        int p = p0 + pi;
        sdw[tid] = g_dw[(size_t)p*256 + tid];
        __syncthreads();
        for (int r = warp; r < 27; r += 8) {
            const float* wr = &wsm[r*256];
            float s = 0.0f;
            #pragma unroll
            for (int k = 0; k < 8; k++) s += sdw[lane + 32*k] * wr[lane + 32*k];
            #pragma unroll
            for (int o = 16; o; o >>= 1) s += __shfl_xor_sync(0xffffffffu, s, o);
            if (lane == 0) sres[r] = s;
        }
        __syncthreads();
        if (tid < 18) g_off[(size_t)p*18 + tid] = sres[tid] + offb[tid];
        if (tid == 0) {
            float l[9], mx = -1e30f;
            #pragma unroll
            for (int k = 0; k < 9; k++) { l[k] = sres[18+k] + mskb[k]; mx = fmaxf(mx, l[k]); }
            float se = 0.0f;
            #pragma unroll
            for (int k = 0; k < 9; k++) { l[k] = expf(l[k] - mx); se += l[k]; }
            float inv = 1.0f / se;
            #pragma unroll
            for (int k = 0; k < 9; k++) g_msk[(size_t)p*9 + k] = l[k]*inv;
        }
    }
}

// ================= DCNv3 core =================
__global__ __launch_bounds__(256) void p_dcn() {
    int p = blockIdx.x;
    int n = p / HW_, pp = p - n*HW_;
    int y = pp / W_, xx = pp - y*W_;
    int c = threadIdx.x;

    __shared__ float sw[9][4];
    __shared__ int   sx0[9], sy0[9];
    if (threadIdx.x < 9) {
        int k = threadIdx.x;
        float m  = g_msk[(size_t)p*9 + k];
        float ox = g_off[(size_t)p*18 + 2*k];
        float oy = g_off[(size_t)p*18 + 2*k + 1];
        float px = (float)xx + (float)(k/3) + ox;     // padded coords
        float py = (float)y  + (float)(k%3) + oy;
        float x0f = floorf(px), y0f = floorf(py);
        float lw = px - x0f, lh = py - y0f;
        sw[k][0] = m * (1.0f - lh) * (1.0f - lw);
        sw[k][1] = m * (1.0f - lh) * lw;
        sw[k][2] = m * lh * (1.0f - lw);
        sw[k][3] = m * lh * lw;
        sx0[k] = (int)x0f;
        sy0[k] = (int)y0f;
    }
    __syncthreads();

    const float* Xb = &g_xproj[(size_t)n * HW_ * C2_];
    float acc = 0.0f;
    for (int k = 0; k < 9; k++) {
        int x0 = sx0[k], y0 = sy0[k];
        #pragma unroll
        for (int t = 0; t < 4; t++) {
            int xi = x0 + (t & 1);
            int yi = y0 + (t >> 1);
            if (xi >= 1 && xi <= W_ && yi >= 1 && yi <= H_) {
                float val = Xb[(size_t)((yi-1)*W_ + (xi-1))*C2_ + c];
                acc = fmaf(sw[k][t], val, acc);
            }
        }
    }
    g_dcn[(size_t)p*C2_ + c] = acc;
}

// ---------------- launch ----------------
extern "C" void kernel_launch(void* const* d_in, const int* in_sizes, int n_in,
                              void* d_out, int out_size) {
    const float* x     = (const float*)d_in[0];
    const float* w1    = (const float*)d_in[1];
    const float* g1    = (const float*)d_in[2];
    const float* b1    = (const float*)d_in[3];
    const float* m1    = (const float*)d_in[4];
    const float* v1    = (const float*)d_in[5];
    const float* w2    = (const float*)d_in[6];
    const float* g2    = (const float*)d_in[7];
    const float* b2    = (const float*)d_in[8];
    const float* m2    = (const float*)d_in[9];
    const float* v2    = (const float*)d_in[10];
    const float* dw_w  = (const float*)d_in[11];
    const float* dw_b  = (const float*)d_in[12];
    const float* ln_g  = (const float*)d_in[13];
    const float* ln_b  = (const float*)d_in[14];
    const float* off_w = (const float*)d_in[15];
    const float* off_b = (const float*)d_in[16];
    const float* msk_w = (const float*)d_in[17];
    const float* msk_b = (const float*)d_in[18];
    const float* in_w  = (const float*)d_in[19];
    const float* in_b  = (const float*)d_in[20];
    const float* out_w = (const float*)d_in[21];
    const float* out_b = (const float*)d_in[22];
    const float* g3    = (const float*)d_in[23];
    const float* b3    = (const float*)d_in[24];
    const float* m3    = (const float*)d_in[25];
    const float* v3    = (const float*)d_in[26];
    float* out = (float*)d_out;

    pk_w1<<<(C1_*9*CH_ + 255)/256, 256>>>(w1, g1, b1, m1, v1);
    pk_lin<<<(C2_*C2_ + 255)/256, 256>>>(w2, g2, b2, m2, v2, in_w, out_w, out_b,
                                         g3, b3, m3, v3);
    k_tr<<<dim3(HW_/32, C1_/32, N_), dim3(32, 8)>>>(x);
    c1_fast<<<dim3(W_/8, H_/8, N_), 256>>>();
    gm<128, 0><<<dim3(M_/64, 2), 256>>>(nullptr, nullptr, nullptr);
    p_dwlngelu<<<M_, 256>>>(dw_w, dw_b, ln_g, ln_b);
    p_offmask2<<<M_/32, 256>>>(off_w, off_b, msk_w, msk_b);
    gm<256, 1><<<dim3(M_/64, 2), 256>>>(in_b, nullptr, nullptr);
    p_dcn<<<M_, 256>>>();
    gm<256, 2><<<dim3(M_/64, 2), 256>>>(nullptr, out, x);
}

// round 11
// speedup vs baseline: 1.2909x; 1.0700x over previous
#include <cuda_runtime.h>
#include <cuda_bf16.h>
#include <math.h>
#include <stdint.h>

// ---------------- problem constants ----------------
#define N_   4
#define C1_  256
#define C2_  256
#define CH_  128
#define H_   80
#define W_   80
#define HW_  6400
#define M_   (N_*HW_)      // 25600 pixels total
#define PL   124           // smem plane stride (floats) per ci: 10 rows x 12 + pad

// ---------------- scratch (referenced ONLY inside device code!) ----------------
__device__ float g_xn[M_*C1_];        // x in NHWC
__device__ float g_w1n[C1_*9*CH_];    // conv1 w, [ci][kk][oc], BN-folded
__device__ float g_b1f[CH_];
__device__ float g_w2t[CH_*C2_];      // conv2 w transposed [k][o], BN-folded
__device__ float g_b2f[C2_];
__device__ float g_inwt[C2_*C2_];     // in_w transposed [k][o]
__device__ float g_outwt[C2_*C2_];    // out_w transposed [k][o], BN3-folded
__device__ float g_obf[C2_];          // folded output bias
__device__ float g_y1[M_*CH_];        // conv1 out NHWC
__device__ float g_y2[M_*C2_];        // conv2 out NHWC
__device__ float g_dw[M_*C2_];        // dw+LN+GELU out NHWC
__device__ float g_xproj[M_*C2_];     // input_proj out NHWC
__device__ float g_dcn[M_*C2_];       // dcn out NHWC
__device__ float g_off[M_*18];
__device__ float g_msk[M_*9];

__device__ __forceinline__ float silu_f(float v) { return v / (1.0f + expf(-v)); }

// ---- f32x2 helpers ----
typedef unsigned long long ull;
__device__ __forceinline__ ull pk2(float lo, float hi) {
    ull r; asm("mov.b64 %0, {%1, %2};" : "=l"(r) : "f"(lo), "f"(hi)); return r;
}
__device__ __forceinline__ void fma2(ull& d, ull a, ull b) {
    asm("fma.rn.f32x2 %0, %1, %2, %0;" : "+l"(d) : "l"(a), "l"(b));
}
__device__ __forceinline__ float2 upk2(ull v) {
    float2 r; asm("mov.b64 {%0, %1}, %2;" : "=f"(r.x), "=f"(r.y) : "l"(v)); return r;
}
__device__ __forceinline__ uint32_t smem_u32(const void* p) {
    uint32_t a;
    asm("{ .reg .u64 t; cvta.to.shared.u64 t, %1; cvt.u32.u64 %0, t; }" : "=r"(a) : "l"(p));
    return a;
}
__device__ __forceinline__ void cp4(uint32_t sa, const float* ga, uint32_t sz) {
    asm volatile("cp.async.ca.shared.global [%0], [%1], 4, %2;\n"
                 :: "r"(sa), "l"(ga), "r"(sz));
}

// ================= pack kernels =================
__global__ void pk_w1(const float* __restrict__ w1, const float* __restrict__ g1,
                      const float* __restrict__ b1, const float* __restrict__ m1,
                      const float* __restrict__ v1) {
    int i = blockIdx.x * blockDim.x + threadIdx.x;
    if (i >= C1_*9*CH_) return;
    int oc = i & (CH_-1);
    int kidx = i >> 7;          // ci*9 + kk
    int ci = kidx / 9, kk = kidx - ci*9;
    float s = g1[oc] * rsqrtf(v1[oc] + 1e-5f);
    g_w1n[i] = w1[(size_t)(oc*C1_ + ci)*9 + kk] * s;
    if (i < CH_) g_b1f[i] = b1[i] - m1[i]*s;
}

__global__ void pk_lin(const float* __restrict__ w2, const float* __restrict__ g2,
                       const float* __restrict__ b2, const float* __restrict__ m2,
                       const float* __restrict__ v2, const float* __restrict__ inw,
                       const float* __restrict__ outw, const float* __restrict__ outb,
                       const float* __restrict__ g3, const float* __restrict__ b3,
                       const float* __restrict__ m3, const float* __restrict__ v3) {
    int i = blockIdx.x * blockDim.x + threadIdx.x;
    if (i >= C2_*C2_) return;
    int o = i & 255, k = i >> 8;
    g_inwt[i] = inw[(size_t)o*C2_ + k];
    float s3 = g3[o] * rsqrtf(v3[o] + 1e-5f);
    g_outwt[i] = outw[(size_t)o*C2_ + k] * s3;
    if (k < CH_) {
        float s2 = g2[o] * rsqrtf(v2[o] + 1e-5f);
        g_w2t[(size_t)k*C2_ + o] = w2[(size_t)o*CH_ + k] * s2;
    }
    if (i < C2_) {
        float s2 = g2[i] * rsqrtf(v2[i] + 1e-5f);
        g_b2f[i] = b2[i] - m2[i]*s2;
        float s3b = g3[i] * rsqrtf(v3[i] + 1e-5f);
        g_obf[i] = outb[i]*s3b + b3[i] - m3[i]*s3b;
    }
}

// ================= NCHW -> NHWC transpose =================
__global__ void k_tr(const float* __restrict__ x) {
    __shared__ float tile[32][33];
    int n  = blockIdx.z;
    int c0 = blockIdx.y * 32, p0 = blockIdx.x * 32;
    for (int r = threadIdx.y; r < 32; r += 8)
        tile[r][threadIdx.x] = x[(size_t)(n*C1_ + c0 + r)*HW_ + p0 + threadIdx.x];
    __syncthreads();
    for (int r = threadIdx.y; r < 32; r += 8)
        g_xn[(size_t)(n*HW_ + p0 + r)*C1_ + c0 + threadIdx.x] = tile[threadIdx.x][r];
}

// ================= conv1: 3x3 256->128, BN+SiLU, f32x2, NHWC (R10 verbatim) ==========
__global__ __launch_bounds__(256, 3) void c1_fast() {
    __shared__ float sIn[2][32*PL];
    int tid = threadIdx.x;
    int n = blockIdx.z;
    int by = blockIdx.y * 8, bx = blockIdx.x * 8;
    int py   = tid >> 5;          // 0..7, warp-uniform
    int lane = tid & 31;
    uint32_t sbase = smem_u32(sIn);

    int pak[13]; unsigned ebits = 0, vbits = 0;
    #pragma unroll
    for (int j = 0; j < 13; j++) {
        int p = py + j*8;
        pak[j] = 0;
        if (p < 100) {
            int hy = p / 10, hx = p - hy*10;
            int gy = by + hy - 1, gx = bx + hx - 1;
            bool v = (gy >= 0 && gy < H_ && gx >= 0 && gx < W_);
            int pix = v ? (n*HW_ + gy*W_ + gx) : 0;
            pak[j] = ((pix*256 + lane) << 7) | (hy*12 + hx);
            ebits |= 1u << j;
            if (v) vbits |= 1u << j;
        }
    }

    auto load_chunk = [&](int cc, int b) {
        uint32_t soff0 = sbase + (uint32_t)(b * 32 * PL + lane * PL) * 4u;
        #pragma unroll
        for (int j = 0; j < 13; j++) {
            if (ebits >> j & 1) {
                uint32_t sa = soff0 + (uint32_t)(pak[j] & 127) * 4u;
                uint32_t sz = (vbits >> j & 1) ? 4u : 0u;
                cp4(sa, g_xn + (pak[j] >> 7) + cc, sz);
            }
        }
        asm volatile("cp.async.commit_group;");
    };

    load_chunk(0, 0);
    asm volatile("cp.async.wait_group 0;");
    __syncthreads();

    ull acc[4][4];
    #pragma unroll
    for (int i = 0; i < 4; i++)
        #pragma unroll
        for (int o = 0; o < 4; o++) acc[i][o] = 0ull;

    int buf = 0;
    for (int cc = 0; cc < C1_; cc += 32) {
        if (cc + 32 < C1_) load_chunk(cc + 32, buf ^ 1);

        #pragma unroll 2
        for (int ci = 0; ci < 32; ci++) {
            const float* plane = &sIn[buf][ci * PL];
            const float* wb = &g_w1n[(size_t)((cc + ci)*9)*128 + lane*2];
            #pragma unroll
            for (int ky = 0; ky < 3; ky++) {
                const float* row = plane + (py + ky) * 12;
                ulonglong2 t0 = *(const ulonglong2*)row;
                ulonglong2 t1 = *(const ulonglong2*)(row + 4);
                ull u0 = t0.x, u1 = t0.y, u2 = t1.x, u3 = t1.y;
                ull u4 = *(const ull*)(row + 8);
                float2 f0 = upk2(u0), f1 = upk2(u1), f2 = upk2(u2),
                       f3 = upk2(u3), f4 = upk2(u4);
                ull o0 = pk2(f0.y, f1.x), o1 = pk2(f1.y, f2.x);
                ull o2 = pk2(f2.y, f3.x), o3 = pk2(f3.y, f4.x);
                #pragma unroll
                for (int kx = 0; kx < 3; kx++) {
                    const float* wk = wb + (ky*3 + kx)*128;
                    float2 wl = *(const float2*)wk;
                    float2 wh = *(const float2*)(wk + 64);
                    ull w0 = pk2(wl.x, wl.x), w1 = pk2(wl.y, wl.y);
                    ull w2 = pk2(wh.x, wh.x), w3 = pk2(wh.y, wh.y);
                    ull p0, p1, p2, p3;
                    if (kx == 0)      { p0 = u0; p1 = u1; p2 = u2; p3 = u3; }
                    else if (kx == 1) { p0 = o0; p1 = o1; p2 = o2; p3 = o3; }
                    else              { p0 = u1; p1 = u2; p2 = u3; p3 = u4; }
                    fma2(acc[0][0], p0, w0); fma2(acc[0][1], p0, w1);
                    fma2(acc[0][2], p0, w2); fma2(acc[0][3], p0, w3);
                    fma2(acc[1][0], p1, w0); fma2(acc[1][1], p1, w1);
                    fma2(acc[1][2], p1, w2); fma2(acc[1][3], p1, w3);
                    fma2(acc[2][0], p2, w0); fma2(acc[2][1], p2, w1);
                    fma2(acc[2][2], p2, w2); fma2(acc[2][3], p2, w3);
                    fma2(acc[3][0], p3, w0); fma2(acc[3][1], p3, w1);
                    fma2(acc[3][2], p3, w2); fma2(acc[3][3], p3, w3);
                }
            }
        }

        if (cc + 32 < C1_) asm volatile("cp.async.wait_group 0;");
        __syncthreads();
        buf ^= 1;
    }

    int oc0 = lane * 2;
    float b0 = g_b1f[oc0], b1 = g_b1f[oc0+1], b2 = g_b1f[oc0+64], b3 = g_b1f[oc0+65];
    int gy = by + py;
    size_t rowbase = (size_t)(n*HW_ + gy*W_ + bx)*CH_;
    #pragma unroll
    for (int j = 0; j < 4; j++) {
        float2 v0 = upk2(acc[j][0]), v1 = upk2(acc[j][1]);
        float2 v2 = upk2(acc[j][2]), v3 = upk2(acc[j][3]);
        size_t pb0 = rowbase + (size_t)(2*j)*CH_;
        size_t pb1 = pb0 + CH_;
        float2 e0 = {silu_f(v0.x + b0), silu_f(v1.x + b1)};
        float2 e1 = {silu_f(v2.x + b2), silu_f(v3.x + b3)};
        float2 f0 = {silu_f(v0.y + b0), silu_f(v1.y + b1)};
        float2 f1 = {silu_f(v2.y + b2), silu_f(v3.y + b3)};
        *(float2*)&g_y1[pb0 + oc0]      = e0;
        *(float2*)&g_y1[pb0 + oc0 + 64] = e1;
        *(float2*)&g_y1[pb1 + oc0]      = f0;
        *(float2*)&g_y1[pb1 + oc0 + 64] = f1;
    }
}

// ================= GEMM: out[M,256] = A[M,KD] @ B[KD,256], reg-double-buffered ======
// MODE 0 (conv2):  A=g_y1  B=g_w2t  bias=g_b2f  SiLU -> g_y2
// MODE 1 (inproj): A=g_y2  B=g_inwt bias=ext    none -> g_xproj
// MODE 2 (outproj):A=g_dcn B=g_outwt bias=g_obf SiLU+resid -> ext out (NCHW)
template<int KD, int MODE>
__global__ __launch_bounds__(256) void gm(const float* __restrict__ bias_ext,
                                          float* __restrict__ out_ext,
                                          const float* __restrict__ resid_ext) {
    const float* A    = (MODE == 0) ? g_y1  : (MODE == 1 ? g_y2   : g_dcn);
    const float* B    = (MODE == 0) ? g_w2t : (MODE == 1 ? g_inwt : g_outwt);
    const float* bias = (MODE == 0) ? g_b2f : (MODE == 1 ? bias_ext : g_obf);
    float* C          = (MODE == 0) ? g_y2  : (MODE == 1 ? g_xproj : out_ext);

    __shared__ float As[2][16][68];
    __shared__ float Bs[2][16][136];
    int tid = threadIdx.x;
    int tx = tid & 15, ty = tid >> 4;
    int m0 = blockIdx.x * 64, n0 = blockIdx.y * 128;

    ull acc[4][4];
    #pragma unroll
    for (int i = 0; i < 4; i++)
        #pragma unroll
        for (int j = 0; j < 4; j++) acc[i][j] = 0ull;

    int ar = tid >> 2, ak = (tid & 3) * 4;
    int bk = tid >> 4, bn = (tid & 15) * 8;

    // prefetch chunk 0
    float4 av  = *(const float4*)&A[(size_t)(m0 + ar)*KD + ak];
    float4 bv0 = *(const float4*)&B[(size_t)bk*256 + n0 + bn];
    float4 bv1 = *(const float4*)&B[(size_t)bk*256 + n0 + bn + 4];

    int buf = 0;
    for (int k0 = 0; k0 < KD; k0 += 16) {
        As[buf][ak+0][ar] = av.x; As[buf][ak+1][ar] = av.y;
        As[buf][ak+2][ar] = av.z; As[buf][ak+3][ar] = av.w;
        *(float4*)&Bs[buf][bk][bn]     = bv0;
        *(float4*)&Bs[buf][bk][bn + 4] = bv1;
        __syncthreads();
        if (k0 + 16 < KD) {
            av  = *(const float4*)&A[(size_t)(m0 + ar)*KD + k0 + 16 + ak];
            bv0 = *(const float4*)&B[(size_t)(k0 + 16 + bk)*256 + n0 + bn];
            bv1 = *(const float4*)&B[(size_t)(k0 + 16 + bk)*256 + n0 + bn + 4];
        }
        #pragma unroll
        for (int k = 0; k < 16; k++) {
            float4 a4 = *(const float4*)&As[buf][k][ty*4];
            ull b[4];
            #pragma unroll
            for (int j = 0; j < 4; j++)
                b[j] = *(const ull*)&Bs[buf][k][tx*8 + 2*j];
            ull ad0 = pk2(a4.x, a4.x), ad1 = pk2(a4.y, a4.y);
            ull ad2 = pk2(a4.z, a4.z), ad3 = pk2(a4.w, a4.w);
            #pragma unroll
            for (int j = 0; j < 4; j++) {
                fma2(acc[0][j], ad0, b[j]);
                fma2(acc[1][j], ad1, b[j]);
                fma2(acc[2][j], ad2, b[j]);
                fma2(acc[3][j], ad3, b[j]);
            }
        }
        buf ^= 1;
    }

    #pragma unroll
    for (int i = 0; i < 4; i++) {
        int m = m0 + ty*4 + i;
        int nimg = m / HW_;
        int pp   = m - nimg*HW_;
        #pragma unroll
        for (int j = 0; j < 4; j++) {
            float2 v = upk2(acc[i][j]);
            int nn = n0 + tx*8 + 2*j;
            float r0 = v.x + bias[nn];
            float r1 = v.y + bias[nn+1];
            if (MODE == 0 || MODE == 2) { r0 = silu_f(r0); r1 = silu_f(r1); }
            if (MODE <= 1) {
                C[(size_t)m*256 + nn]     = r0;
                C[(size_t)m*256 + nn + 1] = r1;
            } else {
                size_t base = (size_t)(nimg*256 + nn)*HW_ + pp;
                C[base]       = resid_ext[base]       + r0;
                C[base + HW_] = resid_ext[base + HW_] + r1;
            }
        }
    }
}

// ================= depthwise 3x3 + bias + LayerNorm + GELU (float2 channels) ========
__global__ __launch_bounds__(128) void p_dwlngelu2(const float* __restrict__ dww,
                                                   const float* __restrict__ dwb,
                                                   const float* __restrict__ lng,
                                                   const float* __restrict__ lnb) {
    int p = blockIdx.x;
    int n = p / HW_, pp = p - n*HW_;
    int y = pp / W_, xx = pp - y*W_;
    int c2 = threadIdx.x;          // 0..127
    int c0 = 2*c2;

    float2 acc = {0.0f, 0.0f};
    for (int ky = 0; ky < 3; ky++) {
        int gy = y + ky - 1;
        if (gy < 0 || gy >= H_) continue;
        for (int kx = 0; kx < 3; kx++) {
            int gx = xx + kx - 1;
            if (gx < 0 || gx >= W_) continue;
            float2 v = *(const float2*)&g_y2[(size_t)(n*HW_ + gy*W_ + gx)*C2_ + c0];
            int kk = ky*3 + kx;
            acc.x = fmaf(v.x, dww[c0*9 + kk], acc.x);
            acc.y = fmaf(v.y, dww[(c0+1)*9 + kk], acc.y);
        }
    }
    acc.x += dwb[c0];
    acc.y += dwb[c0+1];

    __shared__ float red[4], red2[4];
    int warp = c2 >> 5, lane = c2 & 31;
    float s = acc.x + acc.y;
    #pragma unroll
    for (int o = 16; o; o >>= 1) s += __shfl_xor_sync(0xffffffffu, s, o);
    if (lane == 0) red[warp] = s;
    __syncthreads();
    float mu = (red[0] + red[1] + red[2] + red[3]) * (1.0f/256.0f);

    float d0 = acc.x - mu, d1 = acc.y - mu;
    float v2 = d0*d0 + d1*d1;
    #pragma unroll
    for (int o = 16; o; o >>= 1) v2 += __shfl_xor_sync(0xffffffffu, v2, o);
    if (lane == 0) red2[warp] = v2;
    __syncthreads();
    float var = (red2[0] + red2[1] + red2[2] + red2[3]) * (1.0f/256.0f);
    float rs = rsqrtf(var + 1e-6f);

    float o0 = d0 * rs * lng[c0]   + lnb[c0];
    float o1 = d1 * rs * lng[c0+1] + lnb[c0+1];
    float2 g;
    g.x = 0.5f * o0 * (1.0f + erff(o0 * 0.70710678118654752f));
    g.y = 0.5f * o1 * (1.0f + erff(o1 * 0.70710678118654752f));
    *(float2*)&g_dw[(size_t)p*C2_ + c0] = g;
}

// ================= offset + mask heads (weights cached in smem, 32 px/block) ========
__global__ __launch_bounds__(256) void p_offmask2(const float* __restrict__ offw,
                                                  const float* __restrict__ offb,
                                                  const float* __restrict__ mskw,
                                                  const float* __restrict__ mskb) {
    __shared__ float wsm[27*256];
    __shared__ float sdw[256];
    __shared__ float sres[27];
    int tid = threadIdx.x;
    int warp = tid >> 5, lane = tid & 31;

    #pragma unroll
    for (int i = tid; i < 27*256; i += 256) {
        int r = i >> 8, c = i & 255;
        wsm[i] = (r < 18) ? offw[r*256 + c] : mskw[(r - 18)*256 + c];
    }
    __syncthreads();

    int p0 = blockIdx.x * 32;
    for (int pi = 0; pi < 32; pi++) {
        int p = p0 + pi;
        sdw[tid] = g_dw[(size_t)p*256 + tid];
        __syncthreads();
        for (int r = warp; r < 27; r += 8) {
            const float* wr = &wsm[r*256];
            float s = 0.0f;
            #pragma unroll
            for (int k = 0; k < 8; k++) s += sdw[lane + 32*k] * wr[lane + 32*k];
            #pragma unroll
            for (int o = 16; o; o >>= 1) s += __shfl_xor_sync(0xffffffffu, s, o);
            if (lane == 0) sres[r] = s;
        }
        __syncthreads();
        if (tid < 18) g_off[(size_t)p*18 + tid] = sres[tid] + offb[tid];
        if (tid == 0) {
            float l[9], mx = -1e30f;
            #pragma unroll
            for (int k = 0; k < 9; k++) { l[k] = sres[18+k] + mskb[k]; mx = fmaxf(mx, l[k]); }
            float se = 0.0f;
            #pragma unroll
            for (int k = 0; k < 9; k++) { l[k] = expf(l[k] - mx); se += l[k]; }
            float inv = 1.0f / se;
            #pragma unroll
            for (int k = 0; k < 9; k++) g_msk[(size_t)p*9 + k] = l[k]*inv;
        }
    }
}

// ================= DCNv3 core (2 pixels/block, float2 channels) =================
__global__ __launch_bounds__(256) void p_dcn2() {
    int tid  = threadIdx.x;
    int half = tid >> 7;           // 0,1 -> which pixel
    int c2   = tid & 127;          // channel pair index
    int p = blockIdx.x * 2 + half;
    int n = p / HW_, pp = p - n*HW_;
    int y = pp / W_, xx = pp - y*W_;

    __shared__ float sw[2][9][4];
    __shared__ int   sx0[2][9], sy0[2][9];
    if (c2 < 9) {
        int k = c2;
        float m  = g_msk[(size_t)p*9 + k];
        float ox = g_off[(size_t)p*18 + 2*k];
        float oy = g_off[(size_t)p*18 + 2*k + 1];
        float px = (float)xx + (float)(k/3) + ox;     // padded coords
        float py = (float)y  + (float)(k%3) + oy;
        float x0f = floorf(px), y0f = floorf(py);
        float lw = px - x0f, lh = py - y0f;
        sw[half][k][0] = m * (1.0f - lh) * (1.0f - lw);
        sw[half][k][1] = m * (1.0f - lh) * lw;
        sw[half][k][2] = m * lh * (1.0f - lw);
        sw[half][k][3] = m * lh * lw;
        sx0[half][k] = (int)x0f;
        sy0[half][k] = (int)y0f;
    }
    __syncthreads();

    const float* Xb = &g_xproj[(size_t)n * HW_ * C2_];
    float2 acc = {0.0f, 0.0f};
    for (int k = 0; k < 9; k++) {
        int x0 = sx0[half][k], y0 = sy0[half][k];
        #pragma unroll
        for (int t = 0; t < 4; t++) {
            int xi = x0 + (t & 1);
            int yi = y0 + (t >> 1);
            if (xi >= 1 && xi <= W_ && yi >= 1 && yi <= H_) {
                float2 v = *(const float2*)&Xb[(size_t)((yi-1)*W_ + (xi-1))*C2_ + 2*c2];
                float wv = sw[half][k][t];
                acc.x = fmaf(wv, v.x, acc.x);
                acc.y = fmaf(wv, v.y, acc.y);
            }
        }
    }
    *(float2*)&g_dcn[(size_t)p*C2_ + 2*c2] = acc;
}

// ---------------- launch ----------------
extern "C" void kernel_launch(void* const* d_in, const int* in_sizes, int n_in,
                              void* d_out, int out_size) {
    const float* x     = (const float*)d_in[0];
    const float* w1    = (const float*)d_in[1];
    const float* g1    = (const float*)d_in[2];
    const float* b1    = (const float*)d_in[3];
    const float* m1    = (const float*)d_in[4];
    const float* v1    = (const float*)d_in[5];
    const float* w2    = (const float*)d_in[6];
    const float* g2    = (const float*)d_in[7];
    const float* b2    = (const float*)d_in[8];
    const float* m2    = (const float*)d_in[9];
    const float* v2    = (const float*)d_in[10];
    const float* dw_w  = (const float*)d_in[11];
    const float* dw_b  = (const float*)d_in[12];
    const float* ln_g  = (const float*)d_in[13];
    const float* ln_b  = (const float*)d_in[14];
    const float* off_w = (const float*)d_in[15];
    const float* off_b = (const float*)d_in[16];
    const float* msk_w = (const float*)d_in[17];
    const float* msk_b = (const float*)d_in[18];
    const float* in_w  = (const float*)d_in[19];
    const float* in_b  = (const float*)d_in[20];
    const float* out_w = (const float*)d_in[21];
    const float* out_b = (const float*)d_in[22];
    const float* g3    = (const float*)d_in[23];
    const float* b3    = (const float*)d_in[24];
    const float* m3    = (const float*)d_in[25];
    const float* v3    = (const float*)d_in[26];
    float* out = (float*)d_out;

    pk_w1<<<(C1_*9*CH_ + 255)/256, 256>>>(w1, g1, b1, m1, v1);
    pk_lin<<<(C2_*C2_ + 255)/256, 256>>>(w2, g2, b2, m2, v2, in_w, out_w, out_b,
                                         g3, b3, m3, v3);
    k_tr<<<dim3(HW_/32, C1_/32, N_), dim3(32, 8)>>>(x);
    c1_fast<<<dim3(W_/8, H_/8, N_), 256>>>();
    gm<128, 0><<<dim3(M_/64, 2), 256>>>(nullptr, nullptr, nullptr);
    p_dwlngelu2<<<M_, 128>>>(dw_w, dw_b, ln_g, ln_b);
    p_offmask2<<<M_/32, 256>>>(off_w, off_b, msk_w, msk_b);
    gm<256, 1><<<dim3(M_/64, 2), 256>>>(in_b, nullptr, nullptr);
    p_dcn2<<<M_/2, 256>>>();
    gm<256, 2><<<dim3(M_/64, 2), 256>>>(nullptr, out, x);
}

// round 12
// speedup vs baseline: 1.7490x; 1.3549x over previous
#include <cuda_runtime.h>
#include <cuda_bf16.h>
#include <math.h>
#include <stdint.h>

// ---------------- problem constants ----------------
#define N_   4
#define C1_  256
#define C2_  256
#define CH_  128
#define H_   80
#define W_   80
#define HW_  6400
#define M_   (N_*HW_)      // 25600 pixels total
#define PL   136           // smem plane stride (floats): 10 rows x 12 + pad (bank-group aligned)

// ---------------- scratch (referenced ONLY inside device code!) ----------------
__device__ float g_xn[M_*C1_];        // x in NHWC
__device__ float g_w1m[9*32*16*64];   // conv1 w in mma-B-fragment order, tf32-rounded, BN-folded
__device__ float g_b1f[CH_];
__device__ float g_w2t[CH_*C2_];      // conv2 w transposed [k][o], BN-folded
__device__ float g_b2f[C2_];
__device__ float g_inwt[C2_*C2_];     // in_w transposed [k][o]
__device__ float g_outwt[C2_*C2_];    // out_w transposed [k][o], BN3-folded
__device__ float g_obf[C2_];          // folded output bias
__device__ float g_y1[M_*CH_];        // conv1 out NHWC
__device__ float g_y2[M_*C2_];        // conv2 out NHWC
__device__ float g_dw[M_*C2_];        // dw+LN+GELU out NHWC
__device__ float g_xproj[M_*C2_];     // input_proj out NHWC
__device__ float g_dcn[M_*C2_];       // dcn out NHWC
__device__ float g_off[M_*18];
__device__ float g_msk[M_*9];

__device__ __forceinline__ float silu_f(float v) { return v / (1.0f + expf(-v)); }

// ---- f32x2 helpers ----
typedef unsigned long long ull;
__device__ __forceinline__ ull pk2(float lo, float hi) {
    ull r; asm("mov.b64 %0, {%1, %2};" : "=l"(r) : "f"(lo), "f"(hi)); return r;
}
__device__ __forceinline__ void fma2(ull& d, ull a, ull b) {
    asm("fma.rn.f32x2 %0, %1, %2, %0;" : "+l"(d) : "l"(a), "l"(b));
}
__device__ __forceinline__ float2 upk2(ull v) {
    float2 r; asm("mov.b64 {%0, %1}, %2;" : "=f"(r.x), "=f"(r.y) : "l"(v)); return r;
}
__device__ __forceinline__ uint32_t smem_u32(const void* p) {
    uint32_t a;
    asm("{ .reg .u64 t; cvta.to.shared.u64 t, %1; cvt.u32.u64 %0, t; }" : "=r"(a) : "l"(p));
    return a;
}
__device__ __forceinline__ void cp4(uint32_t sa, const float* ga, uint32_t sz) {
    asm volatile("cp.async.ca.shared.global [%0], [%1], 4, %2;\n"
                 :: "r"(sa), "l"(ga), "r"(sz));
}
__device__ __forceinline__ uint32_t tf32_of(float f) {
    uint32_t r; asm("cvt.rna.tf32.f32 %0, %1;" : "=r"(r) : "f"(f)); return r;
}
__device__ __forceinline__ void mma_tf32(float* c, uint32_t a0, uint32_t a1,
                                         uint32_t a2, uint32_t a3,
                                         uint32_t b0, uint32_t b1) {
    asm volatile("mma.sync.aligned.m16n8k8.row.col.f32.tf32.tf32.f32 "
                 "{%0,%1,%2,%3}, {%4,%5,%6,%7}, {%8,%9}, {%0,%1,%2,%3};"
                 : "+f"(c[0]), "+f"(c[1]), "+f"(c[2]), "+f"(c[3])
                 : "r"(a0), "r"(a1), "r"(a2), "r"(a3), "r"(b0), "r"(b1));
}

// ================= pack kernels =================
// conv1 weights -> mma B-fragment layout, tf32-rounded, BN-folded.
// idx bits: [0]=s, [1:6]=lane, [6:10]=ntile, [10:15]=cg, [15:]=kk
// element = W[oc = ntile*8 + lane>>2][ci = cg*8 + (lane&3) + s*4][kk]
__global__ void pk_w1m(const float* __restrict__ w1, const float* __restrict__ g1,
                       const float* __restrict__ b1, const float* __restrict__ m1,
                       const float* __restrict__ v1) {
    int i = blockIdx.x * blockDim.x + threadIdx.x;
    if (i >= 9*32*16*64) return;
    int s     = i & 1;
    int lane  = (i >> 1) & 31;
    int ntile = (i >> 6) & 15;
    int cg    = (i >> 10) & 31;
    int kk    = i >> 15;
    int k  = (lane & 3) + s*4;
    int ci = cg*8 + k;
    int oc = ntile*8 + (lane >> 2);
    float sc = g1[oc] * rsqrtf(v1[oc] + 1e-5f);
    float v = w1[(size_t)(oc*C1_ + ci)*9 + kk] * sc;
    uint32_t t = tf32_of(v);
    g_w1m[i] = __uint_as_float(t);
    if (i < CH_) {
        float s0 = g1[i] * rsqrtf(v1[i] + 1e-5f);
        g_b1f[i] = b1[i] - m1[i]*s0;
    }
}

__global__ void pk_lin(const float* __restrict__ w2, const float* __restrict__ g2,
                       const float* __restrict__ b2, const float* __restrict__ m2,
                       const float* __restrict__ v2, const float* __restrict__ inw,
                       const float* __restrict__ outw, const float* __restrict__ outb,
                       const float* __restrict__ g3, const float* __restrict__ b3,
                       const float* __restrict__ m3, const float* __restrict__ v3) {
    int i = blockIdx.x * blockDim.x + threadIdx.x;
    if (i >= C2_*C2_) return;
    int o = i & 255, k = i >> 8;
    g_inwt[i] = inw[(size_t)o*C2_ + k];
    float s3 = g3[o] * rsqrtf(v3[o] + 1e-5f);
    g_outwt[i] = outw[(size_t)o*C2_ + k] * s3;
    if (k < CH_) {
        float s2 = g2[o] * rsqrtf(v2[o] + 1e-5f);
        g_w2t[(size_t)k*C2_ + o] = w2[(size_t)o*CH_ + k] * s2;
    }
    if (i < C2_) {
        float s2 = g2[i] * rsqrtf(v2[i] + 1e-5f);
        g_b2f[i] = b2[i] - m2[i]*s2;
        float s3b = g3[i] * rsqrtf(v3[i] + 1e-5f);
        g_obf[i] = outb[i]*s3b + b3[i] - m3[i]*s3b;
    }
}

// ================= NCHW -> NHWC transpose =================
__global__ void k_tr(const float* __restrict__ x) {
    __shared__ float tile[32][33];
    int n  = blockIdx.z;
    int c0 = blockIdx.y * 32, p0 = blockIdx.x * 32;
    for (int r = threadIdx.y; r < 32; r += 8)
        tile[r][threadIdx.x] = x[(size_t)(n*C1_ + c0 + r)*HW_ + p0 + threadIdx.x];
    __syncthreads();
    for (int r = threadIdx.y; r < 32; r += 8)
        g_xn[(size_t)(n*HW_ + p0 + r)*C1_ + c0 + threadIdx.x] = tile[threadIdx.x][r];
}

// ================= conv1: 3x3 256->128, tf32 mma, BN+SiLU, NHWC =================
// 8x8 px tile x 128 oc per block. 8 warps: warp = nh*4 + t;
//   t  = m-tile (pixel rows 2t, 2t+1; cols 0..7)   -> mma m16
//   nh = oc half (nh*64 .. +64, 8 n-tiles of 8 oc)
// K loop: ci-chunks of 32 (cp.async double-buffered, validated loader),
// inner: kk (3x3 tap) x 4 cig (8 ci each) -> mma k=8 steps.
__global__ __launch_bounds__(256, 3) void c1_tf32() {
    __shared__ float sIn[2][32*PL];
    int tid = threadIdx.x;
    int n = blockIdx.z;
    int by = blockIdx.y * 8, bx = blockIdx.x * 8;
    int warp = tid >> 5;
    int lane = tid & 31;
    int t  = warp & 3;
    int nh = warp >> 2;
    uint32_t sbase = smem_u32(sIn);

    // ---- loader (validated; py = warp acts as row index) ----
    int py = warp;
    int pak[13]; unsigned ebits = 0, vbits = 0;
    #pragma unroll
    for (int j = 0; j < 13; j++) {
        int p = py + j*8;
        pak[j] = 0;
        if (p < 100) {
            int hy = p / 10, hx = p - hy*10;
            int gy = by + hy - 1, gx = bx + hx - 1;
            bool v = (gy >= 0 && gy < H_ && gx >= 0 && gx < W_);
            int pix = v ? (n*HW_ + gy*W_ + gx) : 0;
            pak[j] = ((pix*256 + lane) << 7) | (hy*12 + hx);
            ebits |= 1u << j;
            if (v) vbits |= 1u << j;
        }
    }
    auto load_chunk = [&](int cc, int b) {
        uint32_t soff0 = sbase + (uint32_t)(b * 32 * PL + lane * PL) * 4u;
        #pragma unroll
        for (int j = 0; j < 13; j++) {
            if (ebits >> j & 1) {
                uint32_t sa = soff0 + (uint32_t)(pak[j] & 127) * 4u;
                uint32_t sz = (vbits >> j & 1) ? 4u : 0u;
                cp4(sa, g_xn + (pak[j] >> 7) + cc, sz);
            }
        }
        asm volatile("cp.async.commit_group;");
    };

    load_chunk(0, 0);
    asm volatile("cp.async.wait_group 0;");
    __syncthreads();

    // ---- accumulators: 8 n-tiles x 4 ----
    float acc[8][4];
    #pragma unroll
    for (int nt = 0; nt < 8; nt++)
        #pragma unroll
        for (int j = 0; j < 4; j++) acc[nt][j] = 0.0f;

    int arow = lane >> 2;      // pixel column 0..7
    int acix = lane & 3;       // ci offset within k-step
    int buf = 0;
    for (int cc = 0; cc < C1_; cc += 32) {
        if (cc + 32 < C1_) load_chunk(cc + 32, buf ^ 1);

        #pragma unroll 1
        for (int kk = 0; kk < 9; kk++) {
            int dy = kk / 3, dx = kk - 3*dy;
            int posb = (2*t + dy)*12 + arow + dx;      // a0 position in plane
            const float* wbase = &g_w1m[((size_t)(kk*32 + (cc >> 3))*16 + nh*8)*64 + lane*2];
            #pragma unroll
            for (int cig = 0; cig < 4; cig++) {
                const float* pl = &sIn[buf][(cig*8 + acix) * PL];
                uint32_t a0 = tf32_of(pl[posb]);
                uint32_t a1 = tf32_of(pl[posb + 12]);
                uint32_t a2 = tf32_of(pl[4*PL + posb]);
                uint32_t a3 = tf32_of(pl[4*PL + posb + 12]);
                const float* wp = wbase + (size_t)cig * (16*64);
                #pragma unroll
                for (int nt = 0; nt < 8; nt++) {
                    float2 bv = *(const float2*)(wp + nt*64);
                    mma_tf32(acc[nt], a0, a1, a2, a3,
                             __float_as_uint(bv.x), __float_as_uint(bv.y));
                }
            }
        }

        if (cc + 32 < C1_) asm volatile("cp.async.wait_group 0;");
        __syncthreads();
        buf ^= 1;
    }

    // ---- epilogue: bias + SiLU -> NHWC ----
    // c0,c1 -> pixel (row 2t,   col lane>>2), oc pair nh*64+nt*8+2*(lane&3)
    // c2,c3 -> pixel (row 2t+1, col lane>>2)
    int pxcol = lane >> 2;
    size_t px0 = (size_t)(n*HW_ + (by + 2*t)*W_ + bx + pxcol) * CH_;
    size_t px1 = px0 + (size_t)W_ * CH_;
    int ocb = nh*64 + 2*(lane & 3);
    #pragma unroll
    for (int nt = 0; nt < 8; nt++) {
        int oc = ocb + nt*8;
        float b0 = g_b1f[oc], b1 = g_b1f[oc+1];
        float2 r0 = {silu_f(acc[nt][0] + b0), silu_f(acc[nt][1] + b1)};
        float2 r1 = {silu_f(acc[nt][2] + b0), silu_f(acc[nt][3] + b1)};
        *(float2*)&g_y1[px0 + oc] = r0;
        *(float2*)&g_y1[px1 + oc] = r1;
    }
}

// ================= GEMM: out[M,256] = A[M,KD] @ B[KD,256], reg-double-buffered ======
template<int KD, int MODE>
__global__ __launch_bounds__(256) void gm(const float* __restrict__ bias_ext,
                                          float* __restrict__ out_ext,
                                          const float* __restrict__ resid_ext) {
    const float* A    = (MODE == 0) ? g_y1  : (MODE == 1 ? g_y2   : g_dcn);
    const float* B    = (MODE == 0) ? g_w2t : (MODE == 1 ? g_inwt : g_outwt);
    const float* bias = (MODE == 0) ? g_b2f : (MODE == 1 ? bias_ext : g_obf);
    float* C          = (MODE == 0) ? g_y2  : (MODE == 1 ? g_xproj : out_ext);

    __shared__ float As[2][16][68];
    __shared__ float Bs[2][16][136];
    int tid = threadIdx.x;
    int tx = tid & 15, ty = tid >> 4;
    int m0 = blockIdx.x * 64, n0 = blockIdx.y * 128;

    ull acc[4][4];
    #pragma unroll
    for (int i = 0; i < 4; i++)
        #pragma unroll
        for (int j = 0; j < 4; j++) acc[i][j] = 0ull;

    int ar = tid >> 2, ak = (tid & 3) * 4;
    int bk = tid >> 4, bn = (tid & 15) * 8;

    float4 av  = *(const float4*)&A[(size_t)(m0 + ar)*KD + ak];
    float4 bv0 = *(const float4*)&B[(size_t)bk*256 + n0 + bn];
    float4 bv1 = *(const float4*)&B[(size_t)bk*256 + n0 + bn + 4];

    int buf = 0;
    for (int k0 = 0; k0 < KD; k0 += 16) {
        As[buf][ak+0][ar] = av.x; As[buf][ak+1][ar] = av.y;
        As[buf][ak+2][ar] = av.z; As[buf][ak+3][ar] = av.w;
        *(float4*)&Bs[buf][bk][bn]     = bv0;
        *(float4*)&Bs[buf][bk][bn + 4] = bv1;
        __syncthreads();
        if (k0 + 16 < KD) {
            av  = *(const float4*)&A[(size_t)(m0 + ar)*KD + k0 + 16 + ak];
            bv0 = *(const float4*)&B[(size_t)(k0 + 16 + bk)*256 + n0 + bn];
            bv1 = *(const float4*)&B[(size_t)(k0 + 16 + bk)*256 + n0 + bn + 4];
        }
        #pragma unroll
        for (int k = 0; k < 16; k++) {
            float4 a4 = *(const float4*)&As[buf][k][ty*4];
            ull b[4];
            #pragma unroll
            for (int j = 0; j < 4; j++)
                b[j] = *(const ull*)&Bs[buf][k][tx*8 + 2*j];
            ull ad0 = pk2(a4.x, a4.x), ad1 = pk2(a4.y, a4.y);
            ull ad2 = pk2(a4.z, a4.z), ad3 = pk2(a4.w, a4.w);
            #pragma unroll
            for (int j = 0; j < 4; j++) {
                fma2(acc[0][j], ad0, b[j]);
                fma2(acc[1][j], ad1, b[j]);
                fma2(acc[2][j], ad2, b[j]);
                fma2(acc[3][j], ad3, b[j]);
            }
        }
        buf ^= 1;
    }

    #pragma unroll
    for (int i = 0; i < 4; i++) {
        int m = m0 + ty*4 + i;
        int nimg = m / HW_;
        int pp   = m - nimg*HW_;
        #pragma unroll
        for (int j = 0; j < 4; j++) {
            float2 v = upk2(acc[i][j]);
            int nn = n0 + tx*8 + 2*j;
            float r0 = v.x + bias[nn];
            float r1 = v.y + bias[nn+1];
            if (MODE == 0 || MODE == 2) { r0 = silu_f(r0); r1 = silu_f(r1); }
            if (MODE <= 1) {
                C[(size_t)m*256 + nn]     = r0;
                C[(size_t)m*256 + nn + 1] = r1;
            } else {
                size_t base = (size_t)(nimg*256 + nn)*HW_ + pp;
                C[base]       = resid_ext[base]       + r0;
                C[base + HW_] = resid_ext[base + HW_] + r1;
            }
        }
    }
}

// ================= depthwise 3x3 + bias + LayerNorm + GELU (float2 channels) ========
__global__ __launch_bounds__(128) void p_dwlngelu2(const float* __restrict__ dww,
                                                   const float* __restrict__ dwb,
                                                   const float* __restrict__ lng,
                                                   const float* __restrict__ lnb) {
    int p = blockIdx.x;
    int n = p / HW_, pp = p - n*HW_;
    int y = pp / W_, xx = pp - y*W_;
    int c2 = threadIdx.x;          // 0..127
    int c0 = 2*c2;

    float2 acc = {0.0f, 0.0f};
    for (int ky = 0; ky < 3; ky++) {
        int gy = y + ky - 1;
        if (gy < 0 || gy >= H_) continue;
        for (int kx = 0; kx < 3; kx++) {
            int gx = xx + kx - 1;
            if (gx < 0 || gx >= W_) continue;
            float2 v = *(const float2*)&g_y2[(size_t)(n*HW_ + gy*W_ + gx)*C2_ + c0];
            int kk = ky*3 + kx;
            acc.x = fmaf(v.x, dww[c0*9 + kk], acc.x);
            acc.y = fmaf(v.y, dww[(c0+1)*9 + kk], acc.y);
        }
    }
    acc.x += dwb[c0];
    acc.y += dwb[c0+1];

    __shared__ float red[4], red2[4];
    int warp = c2 >> 5, lane = c2 & 31;
    float s = acc.x + acc.y;
    #pragma unroll
    for (int o = 16; o; o >>= 1) s += __shfl_xor_sync(0xffffffffu, s, o);
    if (lane == 0) red[warp] = s;
    __syncthreads();
    float mu = (red[0] + red[1] + red[2] + red[3]) * (1.0f/256.0f);

    float d0 = acc.x - mu, d1 = acc.y - mu;
    float v2 = d0*d0 + d1*d1;
    #pragma unroll
    for (int o = 16; o; o >>= 1) v2 += __shfl_xor_sync(0xffffffffu, v2, o);
    if (lane == 0) red2[warp] = v2;
    __syncthreads();
    float var = (red2[0] + red2[1] + red2[2] + red2[3]) * (1.0f/256.0f);
    float rs = rsqrtf(var + 1e-6f);

    float o0 = d0 * rs * lng[c0]   + lnb[c0];
    float o1 = d1 * rs * lng[c0+1] + lnb[c0+1];
    float2 g;
    g.x = 0.5f * o0 * (1.0f + erff(o0 * 0.70710678118654752f));
    g.y = 0.5f * o1 * (1.0f + erff(o1 * 0.70710678118654752f));
    *(float2*)&g_dw[(size_t)p*C2_ + c0] = g;
}

// ================= offset + mask heads (weights cached in smem, 32 px/block) ========
__global__ __launch_bounds__(256) void p_offmask2(const float* __restrict__ offw,
                                                  const float* __restrict__ offb,
                                                  const float* __restrict__ mskw,
                                                  const float* __restrict__ mskb) {
    __shared__ float wsm[27*256];
    __shared__ float sdw[256];
    __shared__ float sres[27];
    int tid = threadIdx.x;
    int warp = tid >> 5, lane = tid & 31;

    #pragma unroll
    for (int i = tid; i < 27*256; i += 256) {
        int r = i >> 8, c = i & 255;
        wsm[i] = (r < 18) ? offw[r*256 + c] : mskw[(r - 18)*256 + c];
    }
    __syncthreads();

    int p0 = blockIdx.x * 32;
    for (int pi = 0; pi < 32; pi++) {
        int p = p0 + pi;
        sdw[tid] = g_dw[(size_t)p*256 + tid];
        __syncthreads();
        for (int r = warp; r < 27; r += 8) {
            const float* wr = &wsm[r*256];
            float s = 0.0f;
            #pragma unroll
            for (int k = 0; k < 8; k++) s += sdw[lane + 32*k] * wr[lane + 32*k];
            #pragma unroll
            for (int o = 16; o; o >>= 1) s += __shfl_xor_sync(0xffffffffu, s, o);
            if (lane == 0) sres[r] = s;
        }
        __syncthreads();
        if (tid < 18) g_off[(size_t)p*18 + tid] = sres[tid] + offb[tid];
        if (tid == 0) {
            float l[9], mx = -1e30f;
            #pragma unroll
            for (int k = 0; k < 9; k++) { l[k] = sres[18+k] + mskb[k]; mx = fmaxf(mx, l[k]); }
            float se = 0.0f;
            #pragma unroll
            for (int k = 0; k < 9; k++) { l[k] = expf(l[k] - mx); se += l[k]; }
            float inv = 1.0f / se;
            #pragma unroll
            for (int k = 0; k < 9; k++) g_msk[(size_t)p*9 + k] = l[k]*inv;
        }
    }
}

// ================= DCNv3 core (2 pixels/block, float2 channels) =================
__global__ __launch_bounds__(256) void p_dcn2() {
    int tid  = threadIdx.x;
    int half = tid >> 7;
    int c2   = tid & 127;
    int p = blockIdx.x * 2 + half;
    int n = p / HW_, pp = p - n*HW_;
    int y = pp / W_, xx = pp - y*W_;

    __shared__ float sw[2][9][4];
    __shared__ int   sx0[2][9], sy0[2][9];
    if (c2 < 9) {
        int k = c2;
        float m  = g_msk[(size_t)p*9 + k];
        float ox = g_off[(size_t)p*18 + 2*k];
        float oy = g_off[(size_t)p*18 + 2*k + 1];
        float px = (float)xx + (float)(k/3) + ox;
        float py = (float)y  + (float)(k%3) + oy;
        float x0f = floorf(px), y0f = floorf(py);
        float lw = px - x0f, lh = py - y0f;
        sw[half][k][0] = m * (1.0f - lh) * (1.0f - lw);
        sw[half][k][1] = m * (1.0f - lh) * lw;
        sw[half][k][2] = m * lh * (1.0f - lw);
        sw[half][k][3] = m * lh * lw;
        sx0[half][k] = (int)x0f;
        sy0[half][k] = (int)y0f;
    }
    __syncthreads();

    const float* Xb = &g_xproj[(size_t)n * HW_ * C2_];
    float2 acc = {0.0f, 0.0f};
    for (int k = 0; k < 9; k++) {
        int x0 = sx0[half][k], y0 = sy0[half][k];
        #pragma unroll
        for (int t = 0; t < 4; t++) {
            int xi = x0 + (t & 1);
            int yi = y0 + (t >> 1);
            if (xi >= 1 && xi <= W_ && yi >= 1 && yi <= H_) {
                float2 v = *(const float2*)&Xb[(size_t)((yi-1)*W_ + (xi-1))*C2_ + 2*c2];
                float wv = sw[half][k][t];
                acc.x = fmaf(wv, v.x, acc.x);
                acc.y = fmaf(wv, v.y, acc.y);
            }
        }
    }
    *(float2*)&g_dcn[(size_t)p*C2_ + 2*c2] = acc;
}

// ---------------- launch ----------------
extern "C" void kernel_launch(void* const* d_in, const int* in_sizes, int n_in,
                              void* d_out, int out_size) {
    const float* x     = (const float*)d_in[0];
    const float* w1    = (const float*)d_in[1];
    const float* g1    = (const float*)d_in[2];
    const float* b1    = (const float*)d_in[3];
    const float* m1    = (const float*)d_in[4];
    const float* v1    = (const float*)d_in[5];
    const float* w2    = (const float*)d_in[6];
    const float* g2    = (const float*)d_in[7];
    const float* b2    = (const float*)d_in[8];
    const float* m2    = (const float*)d_in[9];
    const float* v2    = (const float*)d_in[10];
    const float* dw_w  = (const float*)d_in[11];
    const float* dw_b  = (const float*)d_in[12];
    const float* ln_g  = (const float*)d_in[13];
    const float* ln_b  = (const float*)d_in[14];
    const float* off_w = (const float*)d_in[15];
    const float* off_b = (const float*)d_in[16];
    const float* msk_w = (const float*)d_in[17];
    const float* msk_b = (const float*)d_in[18];
    const float* in_w  = (const float*)d_in[19];
    const float* in_b  = (const float*)d_in[20];
    const float* out_w = (const float*)d_in[21];
    const float* out_b = (const float*)d_in[22];
    const float* g3    = (const float*)d_in[23];
    const float* b3    = (const float*)d_in[24];
    const float* m3    = (const float*)d_in[25];
    const float* v3    = (const float*)d_in[26];
    float* out = (float*)d_out;

    pk_w1m<<<(9*32*16*64 + 255)/256, 256>>>(w1, g1, b1, m1, v1);
    pk_lin<<<(C2_*C2_ + 255)/256, 256>>>(w2, g2, b2, m2, v2, in_w, out_w, out_b,
                                         g3, b3, m3, v3);
    k_tr<<<dim3(HW_/32, C1_/32, N_), dim3(32, 8)>>>(x);
    c1_tf32<<<dim3(W_/8, H_/8, N_), 256>>>();
    gm<128, 0><<<dim3(M_/64, 2), 256>>>(nullptr, nullptr, nullptr);
    p_dwlngelu2<<<M_, 128>>>(dw_w, dw_b, ln_g, ln_b);
    p_offmask2<<<M_/32, 256>>>(off_w, off_b, msk_w, msk_b);
    gm<256, 1><<<dim3(M_/64, 2), 256>>>(in_b, nullptr, nullptr);
    p_dcn2<<<M_/2, 256>>>();
    gm<256, 2><<<dim3(M_/64, 2), 256>>>(nullptr, out, x);
}

// round 13
// speedup vs baseline: 2.4519x; 1.4019x over previous
#include <cuda_runtime.h>
#include <cuda_bf16.h>
#include <math.h>
#include <stdint.h>

// ---------------- problem constants ----------------
#define N_   4
#define C1_  256
#define C2_  256
#define CH_  128
#define H_   80
#define W_   80
#define HW_  6400
#define M_   (N_*HW_)      // 25600 pixels total
#define PL   136           // conv1 smem plane stride

// ---------------- scratch (referenced ONLY inside device code!) ----------------
__device__ float g_xn[M_*C1_];        // x in NHWC
__device__ float g_w1m[9*32*16*64];   // conv1 w, mma-B fragments, tf32, BN-folded
__device__ float g_b1f[CH_];
__device__ float g_w2t[CH_*C2_];      // conv2 w [k][o], BN-folded
__device__ float g_b2f[C2_];
__device__ float g_inwt[C2_*C2_];     // in_w [k][o]
__device__ float g_outwt[C2_*C2_];    // out_w [k][o], BN3-folded
__device__ float g_obf[C2_];
__device__ float g_w2f[16*16*32*4];   // conv2 w fragments (kc16, ntp16, lane32, 4)
__device__ float g_inf[32*16*32*4];   // in_w fragments
__device__ float g_outf[32*16*32*4];  // out_w fragments
__device__ float g_y1[M_*CH_];
__device__ float g_y2[M_*C2_];
__device__ float g_dw[M_*C2_];
__device__ float g_xproj[M_*C2_];
__device__ float g_dcn[M_*C2_];
__device__ float g_off[M_*18];
__device__ float g_msk[M_*9];

__device__ __forceinline__ float silu_f(float v) { return v / (1.0f + expf(-v)); }

typedef unsigned long long ull;
__device__ __forceinline__ uint32_t smem_u32(const void* p) {
    uint32_t a;
    asm("{ .reg .u64 t; cvta.to.shared.u64 t, %1; cvt.u32.u64 %0, t; }" : "=r"(a) : "l"(p));
    return a;
}
__device__ __forceinline__ void cp4(uint32_t sa, const float* ga, uint32_t sz) {
    asm volatile("cp.async.ca.shared.global [%0], [%1], 4, %2;\n"
                 :: "r"(sa), "l"(ga), "r"(sz));
}
__device__ __forceinline__ uint32_t tf32_of(float f) {
    uint32_t r; asm("cvt.rna.tf32.f32 %0, %1;" : "=r"(r) : "f"(f)); return r;
}
__device__ __forceinline__ void mma_tf32(float* c, uint32_t a0, uint32_t a1,
                                         uint32_t a2, uint32_t a3,
                                         uint32_t b0, uint32_t b1) {
    asm volatile("mma.sync.aligned.m16n8k8.row.col.f32.tf32.tf32.f32 "
                 "{%0,%1,%2,%3}, {%4,%5,%6,%7}, {%8,%9}, {%0,%1,%2,%3};"
                 : "+f"(c[0]), "+f"(c[1]), "+f"(c[2]), "+f"(c[3])
                 : "r"(a0), "r"(a1), "r"(a2), "r"(a3), "r"(b0), "r"(b1));
}

// ================= pack kernels =================
__global__ void pk_w1m(const float* __restrict__ w1, const float* __restrict__ g1,
                       const float* __restrict__ b1, const float* __restrict__ m1,
                       const float* __restrict__ v1) {
    int i = blockIdx.x * blockDim.x + threadIdx.x;
    if (i >= 9*32*16*64) return;
    int s     = i & 1;
    int lane  = (i >> 1) & 31;
    int ntile = (i >> 6) & 15;
    int cg    = (i >> 10) & 31;
    int kk    = i >> 15;
    int k  = (lane & 3) + s*4;
    int ci = cg*8 + k;
    int oc = ntile*8 + (lane >> 2);
    float sc = g1[oc] * rsqrtf(v1[oc] + 1e-5f);
    float v = w1[(size_t)(oc*C1_ + ci)*9 + kk] * sc;
    g_w1m[i] = __uint_as_float(tf32_of(v));
    if (i < CH_) {
        float s0 = g1[i] * rsqrtf(v1[i] + 1e-5f);
        g_b1f[i] = b1[i] - m1[i]*s0;
    }
}

__global__ void pk_lin(const float* __restrict__ w2, const float* __restrict__ g2,
                       const float* __restrict__ b2, const float* __restrict__ m2,
                       const float* __restrict__ v2, const float* __restrict__ inw,
                       const float* __restrict__ outw, const float* __restrict__ outb,
                       const float* __restrict__ g3, const float* __restrict__ b3,
                       const float* __restrict__ m3, const float* __restrict__ v3) {
    int i = blockIdx.x * blockDim.x + threadIdx.x;
    if (i >= C2_*C2_) return;
    int o = i & 255, k = i >> 8;
    g_inwt[i] = inw[(size_t)o*C2_ + k];
    float s3 = g3[o] * rsqrtf(v3[o] + 1e-5f);
    g_outwt[i] = outw[(size_t)o*C2_ + k] * s3;
    if (k < CH_) {
        float s2 = g2[o] * rsqrtf(v2[o] + 1e-5f);
        g_w2t[(size_t)k*C2_ + o] = w2[(size_t)o*CH_ + k] * s2;
    }
    if (i < C2_) {
        float s2 = g2[i] * rsqrtf(v2[i] + 1e-5f);
        g_b2f[i] = b2[i] - m2[i]*s2;
        float s3b = g3[i] * rsqrtf(v3[i] + 1e-5f);
        g_obf[i] = outb[i]*s3b + b3[i] - m3[i]*s3b;
    }
}

// GEMM weight fragments: idx = (((kc*16 + ntp)*32 + lane)*4 + half*2 + s)
// value = W[k = kc*8 + (lane&3) + s*4][n = (ntp*2+half)*8 + (lane>>2)], tf32-rounded.
__global__ void pk_frag() {
    int i = blockIdx.x * blockDim.x + threadIdx.x;
    if (i >= 32*16*32*4) return;
    int s    = i & 1;
    int half = (i >> 1) & 1;
    int lane = (i >> 2) & 31;
    int ntp  = (i >> 7) & 15;
    int kc   = i >> 11;
    int k = kc*8 + (lane & 3) + s*4;
    int n = (ntp*2 + half)*8 + (lane >> 2);
    g_inf[i]  = __uint_as_float(tf32_of(g_inwt[(size_t)k*256 + n]));
    g_outf[i] = __uint_as_float(tf32_of(g_outwt[(size_t)k*256 + n]));
    if (kc < 16)
        g_w2f[i] = __uint_as_float(tf32_of(g_w2t[(size_t)k*256 + n]));
}

// ================= NCHW -> NHWC transpose =================
__global__ void k_tr(const float* __restrict__ x) {
    __shared__ float tile[32][33];
    int n  = blockIdx.z;
    int c0 = blockIdx.y * 32, p0 = blockIdx.x * 32;
    for (int r = threadIdx.y; r < 32; r += 8)
        tile[r][threadIdx.x] = x[(size_t)(n*C1_ + c0 + r)*HW_ + p0 + threadIdx.x];
    __syncthreads();
    for (int r = threadIdx.y; r < 32; r += 8)
        g_xn[(size_t)(n*HW_ + p0 + r)*C1_ + c0 + threadIdx.x] = tile[threadIdx.x][r];
}

// ================= conv1: 3x3 256->128, tf32 mma, BN+SiLU (R12 verbatim) =============
__global__ __launch_bounds__(256, 3) void c1_tf32() {
    __shared__ float sIn[2][32*PL];
    int tid = threadIdx.x;
    int n = blockIdx.z;
    int by = blockIdx.y * 8, bx = blockIdx.x * 8;
    int warp = tid >> 5;
    int lane = tid & 31;
    int t  = warp & 3;
    int nh = warp >> 2;
    uint32_t sbase = smem_u32(sIn);

    int py = warp;
    int pak[13]; unsigned ebits = 0, vbits = 0;
    #pragma unroll
    for (int j = 0; j < 13; j++) {
        int p = py + j*8;
        pak[j] = 0;
        if (p < 100) {
            int hy = p / 10, hx = p - hy*10;
            int gy = by + hy - 1, gx = bx + hx - 1;
            bool v = (gy >= 0 && gy < H_ && gx >= 0 && gx < W_);
            int pix = v ? (n*HW_ + gy*W_ + gx) : 0;
            pak[j] = ((pix*256 + lane) << 7) | (hy*12 + hx);
            ebits |= 1u << j;
            if (v) vbits |= 1u << j;
        }
    }
    auto load_chunk = [&](int cc, int b) {
        uint32_t soff0 = sbase + (uint32_t)(b * 32 * PL + lane * PL) * 4u;
        #pragma unroll
        for (int j = 0; j < 13; j++) {
            if (ebits >> j & 1) {
                uint32_t sa = soff0 + (uint32_t)(pak[j] & 127) * 4u;
                uint32_t sz = (vbits >> j & 1) ? 4u : 0u;
                cp4(sa, g_xn + (pak[j] >> 7) + cc, sz);
            }
        }
        asm volatile("cp.async.commit_group;");
    };

    load_chunk(0, 0);
    asm volatile("cp.async.wait_group 0;");
    __syncthreads();

    float acc[8][4];
    #pragma unroll
    for (int nt = 0; nt < 8; nt++)
        #pragma unroll
        for (int j = 0; j < 4; j++) acc[nt][j] = 0.0f;

    int arow = lane >> 2;
    int acix = lane & 3;
    int buf = 0;
    for (int cc = 0; cc < C1_; cc += 32) {
        if (cc + 32 < C1_) load_chunk(cc + 32, buf ^ 1);

        #pragma unroll 1
        for (int kk = 0; kk < 9; kk++) {
            int dy = kk / 3, dx = kk - 3*dy;
            int posb = (2*t + dy)*12 + arow + dx;
            const float* wbase = &g_w1m[((size_t)(kk*32 + (cc >> 3))*16 + nh*8)*64 + lane*2];
            #pragma unroll
            for (int cig = 0; cig < 4; cig++) {
                const float* pl = &sIn[buf][(cig*8 + acix) * PL];
                uint32_t a0 = tf32_of(pl[posb]);
                uint32_t a1 = tf32_of(pl[posb + 12]);
                uint32_t a2 = tf32_of(pl[4*PL + posb]);
                uint32_t a3 = tf32_of(pl[4*PL + posb + 12]);
                const float* wp = wbase + (size_t)cig * (16*64);
                #pragma unroll
                for (int nt = 0; nt < 8; nt++) {
                    float2 bv = *(const float2*)(wp + nt*64);
                    mma_tf32(acc[nt], a0, a1, a2, a3,
                             __float_as_uint(bv.x), __float_as_uint(bv.y));
                }
            }
        }

        if (cc + 32 < C1_) asm volatile("cp.async.wait_group 0;");
        __syncthreads();
        buf ^= 1;
    }

    int pxcol = lane >> 2;
    size_t px0 = (size_t)(n*HW_ + (by + 2*t)*W_ + bx + pxcol) * CH_;
    size_t px1 = px0 + (size_t)W_ * CH_;
    int ocb = nh*64 + 2*(lane & 3);
    #pragma unroll
    for (int nt = 0; nt < 8; nt++) {
        int oc = ocb + nt*8;
        float b0 = g_b1f[oc], b1 = g_b1f[oc+1];
        float2 r0 = {silu_f(acc[nt][0] + b0), silu_f(acc[nt][1] + b1)};
        float2 r1 = {silu_f(acc[nt][2] + b0), silu_f(acc[nt][3] + b1)};
        *(float2*)&g_y1[px0 + oc] = r0;
        *(float2*)&g_y1[px1 + oc] = r1;
    }
}

// ================= tf32 GEMM: out[M,256] = A[M,KD] @ W[KD,256] (+epilogue) ==========
// Block: 64 m-rows x 256 n, 8 warps = 4 m-tiles x 2 n-halves.
// Warp: m16 x n128 = 16 n-tiles; A staged in smem [64][36] (4m+k bank map),
// weights from pre-packed interleaved fragments (float4 = 2 n-tiles).
// MODE 0 (conv2):  A=g_y1  WF=g_w2f  bias=g_b2f  SiLU -> g_y2
// MODE 1 (inproj): A=g_y2  WF=g_inf  bias=ext    none -> g_xproj
// MODE 2 (outproj):A=g_dcn WF=g_outf bias=g_obf  SiLU+resid -> ext out (NCHW)
template<int KD, int MODE>
__global__ __launch_bounds__(256) void gmt(const float* __restrict__ bias_ext,
                                           float* __restrict__ out_ext,
                                           const float* __restrict__ resid_ext) {
    const float* A    = (MODE == 0) ? g_y1  : (MODE == 1 ? g_y2  : g_dcn);
    const float* WF   = (MODE == 0) ? g_w2f : (MODE == 1 ? g_inf : g_outf);
    const float* bias = (MODE == 0) ? g_b2f : (MODE == 1 ? bias_ext : g_obf);
    float* C          = (MODE == 0) ? g_y2  : (MODE == 1 ? g_xproj : out_ext);

    __shared__ float As[2][64][36];
    int tid = threadIdx.x;
    int warp = tid >> 5, lane = tid & 31;
    int t = warp & 3, nh = warp >> 2;
    int m0 = blockIdx.x * 64;

    float acc[16][4];
    #pragma unroll
    for (int j = 0; j < 16; j++)
        #pragma unroll
        for (int q = 0; q < 4; q++) acc[j][q] = 0.0f;

    int lr = tid >> 2;          // A row 0..63
    int lk = (tid & 3) * 8;     // A col 0,8,16,24

    float4 ra = *(const float4*)&A[(size_t)(m0 + lr)*KD + lk];
    float4 rb = *(const float4*)&A[(size_t)(m0 + lr)*KD + lk + 4];

    int am = 16*t + (lane >> 2);
    int buf = 0;
    for (int k0 = 0; k0 < KD; k0 += 32) {
        *(float4*)&As[buf][lr][lk]     = ra;
        *(float4*)&As[buf][lr][lk + 4] = rb;
        __syncthreads();
        if (k0 + 32 < KD) {
            ra = *(const float4*)&A[(size_t)(m0 + lr)*KD + k0 + 32 + lk];
            rb = *(const float4*)&A[(size_t)(m0 + lr)*KD + k0 + 32 + lk + 4];
        }
        #pragma unroll
        for (int ks = 0; ks < 4; ks++) {
            int kof = ks*8 + (lane & 3);
            uint32_t a0 = tf32_of(As[buf][am][kof]);
            uint32_t a1 = tf32_of(As[buf][am + 8][kof]);
            uint32_t a2 = tf32_of(As[buf][am][kof + 4]);
            uint32_t a3 = tf32_of(As[buf][am + 8][kof + 4]);
            int kc = (k0 >> 3) + ks;
            const float* wp = &WF[(((size_t)kc*16 + nh*8)*32 + lane)*4];
            #pragma unroll
            for (int jp = 0; jp < 8; jp++) {
                float4 bv = *(const float4*)(wp + jp*128);
                mma_tf32(acc[2*jp],   a0, a1, a2, a3,
                         __float_as_uint(bv.x), __float_as_uint(bv.y));
                mma_tf32(acc[2*jp+1], a0, a1, a2, a3,
                         __float_as_uint(bv.z), __float_as_uint(bv.w));
            }
        }
        buf ^= 1;
    }

    // epilogue: rows r0 = m0+16t+(lane>>2), r1 = r0+8; cols nn = nh*128 + j*8 + 2*(lane&3)
    int r0 = m0 + 16*t + (lane >> 2);
    int r1 = r0 + 8;
    int nimg = m0 / HW_;                 // blocks never straddle images (6400 % 64 == 0)
    int pp0 = r0 - nimg*HW_, pp1 = r1 - nimg*HW_;
    int ncb = nh*128 + 2*(lane & 3);
    #pragma unroll
    for (int j = 0; j < 16; j++) {
        int nn = ncb + j*8;
        float b0 = bias[nn], b1 = bias[nn+1];
        float v0 = acc[j][0] + b0, v1 = acc[j][1] + b1;   // row r0
        float v2 = acc[j][2] + b0, v3 = acc[j][3] + b1;   // row r1
        if (MODE == 0 || MODE == 2) {
            v0 = silu_f(v0); v1 = silu_f(v1);
            v2 = silu_f(v2); v3 = silu_f(v3);
        }
        if (MODE <= 1) {
            *(float2*)&C[(size_t)r0*256 + nn] = make_float2(v0, v1);
            *(float2*)&C[(size_t)r1*256 + nn] = make_float2(v2, v3);
        } else {
            size_t b0i = (size_t)(nimg*256 + nn)*HW_;
            C[b0i + pp0]        = resid_ext[b0i + pp0]        + v0;
            C[b0i + HW_ + pp0]  = resid_ext[b0i + HW_ + pp0]  + v1;
            C[b0i + pp1]        = resid_ext[b0i + pp1]        + v2;
            C[b0i + HW_ + pp1]  = resid_ext[b0i + HW_ + pp1]  + v3;
        }
    }
}

// ================= depthwise 3x3 + bias + LayerNorm + GELU (float2 channels) ========
__global__ __launch_bounds__(128) void p_dwlngelu2(const float* __restrict__ dww,
                                                   const float* __restrict__ dwb,
                                                   const float* __restrict__ lng,
                                                   const float* __restrict__ lnb) {
    int p = blockIdx.x;
    int n = p / HW_, pp = p - n*HW_;
    int y = pp / W_, xx = pp - y*W_;
    int c2 = threadIdx.x;
    int c0 = 2*c2;

    float2 acc = {0.0f, 0.0f};
    for (int ky = 0; ky < 3; ky++) {
        int gy = y + ky - 1;
        if (gy < 0 || gy >= H_) continue;
        for (int kx = 0; kx < 3; kx++) {
            int gx = xx + kx - 1;
            if (gx < 0 || gx >= W_) continue;
            float2 v = *(const float2*)&g_y2[(size_t)(n*HW_ + gy*W_ + gx)*C2_ + c0];
            int kk = ky*3 + kx;
            acc.x = fmaf(v.x, dww[c0*9 + kk], acc.x);
            acc.y = fmaf(v.y, dww[(c0+1)*9 + kk], acc.y);
        }
    }
    acc.x += dwb[c0];
    acc.y += dwb[c0+1];

    __shared__ float red[4], red2[4];
    int warp = c2 >> 5, lane = c2 & 31;
    float s = acc.x + acc.y;
    #pragma unroll
    for (int o = 16; o; o >>= 1) s += __shfl_xor_sync(0xffffffffu, s, o);
    if (lane == 0) red[warp] = s;
    __syncthreads();
    float mu = (red[0] + red[1] + red[2] + red[3]) * (1.0f/256.0f);

    float d0 = acc.x - mu, d1 = acc.y - mu;
    float v2 = d0*d0 + d1*d1;
    #pragma unroll
    for (int o = 16; o; o >>= 1) v2 += __shfl_xor_sync(0xffffffffu, v2, o);
    if (lane == 0) red2[warp] = v2;
    __syncthreads();
    float var = (red2[0] + red2[1] + red2[2] + red2[3]) * (1.0f/256.0f);
    float rs = rsqrtf(var + 1e-6f);

    float o0 = d0 * rs * lng[c0]   + lnb[c0];
    float o1 = d1 * rs * lng[c0+1] + lnb[c0+1];
    float2 g;
    g.x = 0.5f * o0 * (1.0f + erff(o0 * 0.70710678118654752f));
    g.y = 0.5f * o1 * (1.0f + erff(o1 * 0.70710678118654752f));
    *(float2*)&g_dw[(size_t)p*C2_ + c0] = g;
}

// ================= offset + mask heads (weights cached in smem, 32 px/block) ========
__global__ __launch_bounds__(256) void p_offmask2(const float* __restrict__ offw,
                                                  const float* __restrict__ offb,
                                                  const float* __restrict__ mskw,
                                                  const float* __restrict__ mskb) {
    __shared__ float wsm[27*256];
    __shared__ float sdw[256];
    __shared__ float sres[27];
    int tid = threadIdx.x;
    int warp = tid >> 5, lane = tid & 31;

    #pragma unroll
    for (int i = tid; i < 27*256; i += 256) {
        int r = i >> 8, c = i & 255;
        wsm[i] = (r < 18) ? offw[r*256 + c] : mskw[(r - 18)*256 + c];
    }
    __syncthreads();

    int p0 = blockIdx.x * 32;
    for (int pi = 0; pi < 32; pi++) {
        int p = p0 + pi;
        sdw[tid] = g_dw[(size_t)p*256 + tid];
        __syncthreads();
        for (int r = warp; r < 27; r += 8) {
            const float* wr = &wsm[r*256];
            float s = 0.0f;
            #pragma unroll
            for (int k = 0; k < 8; k++) s += sdw[lane + 32*k] * wr[lane + 32*k];
            #pragma unroll
            for (int o = 16; o; o >>= 1) s += __shfl_xor_sync(0xffffffffu, s, o);
            if (lane == 0) sres[r] = s;
        }
        __syncthreads();
        if (tid < 18) g_off[(size_t)p*18 + tid] = sres[tid] + offb[tid];
        if (tid == 0) {
            float l[9], mx = -1e30f;
            #pragma unroll
            for (int k = 0; k < 9; k++) { l[k] = sres[18+k] + mskb[k]; mx = fmaxf(mx, l[k]); }
            float se = 0.0f;
            #pragma unroll
            for (int k = 0; k < 9; k++) { l[k] = expf(l[k] - mx); se += l[k]; }
            float inv = 1.0f / se;
            #pragma unroll
            for (int k = 0; k < 9; k++) g_msk[(size_t)p*9 + k] = l[k]*inv;
        }
    }
}

// ================= DCNv3 core (2 pixels/block, float2 channels) =================
__global__ __launch_bounds__(256) void p_dcn2() {
    int tid  = threadIdx.x;
    int half = tid >> 7;
    int c2   = tid & 127;
    int p = blockIdx.x * 2 + half;
    int n = p / HW_, pp = p - n*HW_;
    int y = pp / W_, xx = pp - y*W_;

    __shared__ float sw[2][9][4];
    __shared__ int   sx0[2][9], sy0[2][9];
    if (c2 < 9) {
        int k = c2;
        float m  = g_msk[(size_t)p*9 + k];
        float ox = g_off[(size_t)p*18 + 2*k];
        float oy = g_off[(size_t)p*18 + 2*k + 1];
        float px = (float)xx + (float)(k/3) + ox;
        float py = (float)y  + (float)(k%3) + oy;
        float x0f = floorf(px), y0f = floorf(py);
        float lw = px - x0f, lh = py - y0f;
        sw[half][k][0] = m * (1.0f - lh) * (1.0f - lw);
        sw[half][k][1] = m * (1.0f - lh) * lw;
        sw[half][k][2] = m * lh * (1.0f - lw);
        sw[half][k][3] = m * lh * lw;
        sx0[half][k] = (int)x0f;
        sy0[half][k] = (int)y0f;
    }
    __syncthreads();

    const float* Xb = &g_xproj[(size_t)n * HW_ * C2_];
    float2 acc = {0.0f, 0.0f};
    for (int k = 0; k < 9; k++) {
        int x0 = sx0[half][k], y0 = sy0[half][k];
        #pragma unroll
        for (int t = 0; t < 4; t++) {
            int xi = x0 + (t & 1);
            int yi = y0 + (t >> 1);
            if (xi >= 1 && xi <= W_ && yi >= 1 && yi <= H_) {
                float2 v = *(const float2*)&Xb[(size_t)((yi-1)*W_ + (xi-1))*C2_ + 2*c2];
                float wv = sw[half][k][t];
                acc.x = fmaf(wv, v.x, acc.x);
                acc.y = fmaf(wv, v.y, acc.y);
            }
        }
    }
    *(float2*)&g_dcn[(size_t)p*C2_ + 2*c2] = acc;
}

// ---------------- launch ----------------
extern "C" void kernel_launch(void* const* d_in, const int* in_sizes, int n_in,
                              void* d_out, int out_size) {
    const float* x     = (const float*)d_in[0];
    const float* w1    = (const float*)d_in[1];
    const float* g1    = (const float*)d_in[2];
    const float* b1    = (const float*)d_in[3];
    const float* m1    = (const float*)d_in[4];
    const float* v1    = (const float*)d_in[5];
    const float* w2    = (const float*)d_in[6];
    const float* g2    = (const float*)d_in[7];
    const float* b2    = (const float*)d_in[8];
    const float* m2    = (const float*)d_in[9];
    const float* v2    = (const float*)d_in[10];
    const float* dw_w  = (const float*)d_in[11];
    const float* dw_b  = (const float*)d_in[12];
    const float* ln_g  = (const float*)d_in[13];
    const float* ln_b  = (const float*)d_in[14];
    const float* off_w = (const float*)d_in[15];
    const float* off_b = (const float*)d_in[16];
    const float* msk_w = (const float*)d_in[17];
    const float* msk_b = (const float*)d_in[18];
    const float* in_w  = (const float*)d_in[19];
    const float* in_b  = (const float*)d_in[20];
    const float* out_w = (const float*)d_in[21];
    const float* out_b = (const float*)d_in[22];
    const float* g3    = (const float*)d_in[23];
    const float* b3    = (const float*)d_in[24];
    const float* m3    = (const float*)d_in[25];
    const float* v3    = (const float*)d_in[26];
    float* out = (float*)d_out;

    pk_w1m<<<(9*32*16*64 + 255)/256, 256>>>(w1, g1, b1, m1, v1);
    pk_lin<<<(C2_*C2_ + 255)/256, 256>>>(w2, g2, b2, m2, v2, in_w, out_w, out_b,
                                         g3, b3, m3, v3);
    pk_frag<<<(32*16*32*4 + 255)/256, 256>>>();
    k_tr<<<dim3(HW_/32, C1_/32, N_), dim3(32, 8)>>>(x);
    c1_tf32<<<dim3(W_/8, H_/8, N_), 256>>>();
    gmt<128, 0><<<M_/64, 256>>>(nullptr, nullptr, nullptr);
    p_dwlngelu2<<<M_, 128>>>(dw_w, dw_b, ln_g, ln_b);
    p_offmask2<<<M_/32, 256>>>(off_w, off_b, msk_w, msk_b);
    gmt<256, 1><<<M_/64, 256>>>(in_b, nullptr, nullptr);
    p_dcn2<<<M_/2, 256>>>();
    gmt<256, 2><<<M_/64, 256>>>(nullptr, out, x);
}

// round 14
// speedup vs baseline: 2.5139x; 1.0253x over previous
#include <cuda_runtime.h>
#include <cuda_bf16.h>
#include <math.h>
#include <stdint.h>

// ---------------- problem constants ----------------
#define N_   4
#define C1_  256
#define C2_  256
#define CH_  128
#define H_   80
#define W_   80
#define HW_  6400
#define M_   (N_*HW_)      // 25600 pixels total
#define PL   136           // conv1 smem plane stride

// ---------------- scratch (referenced ONLY inside device code!) ----------------
__device__ float g_xn[M_*C1_];        // x in NHWC
__device__ float g_w1m[9*32*16*64];   // conv1 w, mma-B fragments, tf32, BN-folded
__device__ float g_b1f[CH_];
__device__ float g_w2t[CH_*C2_];      // conv2 w [k][o], BN-folded
__device__ float g_b2f[C2_];
__device__ float g_inwt[C2_*C2_];     // in_w [k][o]
__device__ float g_outwt[C2_*C2_];    // out_w [k][o], BN3-folded
__device__ float g_obf[C2_];
__device__ float g_w2f[16*16*32*4];   // conv2 w fragments
__device__ float g_inf[32*16*32*4];   // in_w fragments
__device__ float g_outf[32*16*32*4];  // out_w fragments
__device__ float g_y1[M_*CH_];
__device__ float g_y2[M_*C2_];
__device__ float g_dw[M_*C2_];
__device__ float g_xproj[M_*C2_];
__device__ float g_dcn[M_*C2_];
__device__ float g_off[M_*18];
__device__ float g_msk[M_*9];

__device__ __forceinline__ float silu_f(float v) { return v / (1.0f + expf(-v)); }

typedef unsigned long long ull;
__device__ __forceinline__ uint32_t smem_u32(const void* p) {
    uint32_t a;
    asm("{ .reg .u64 t; cvta.to.shared.u64 t, %1; cvt.u32.u64 %0, t; }" : "=r"(a) : "l"(p));
    return a;
}
__device__ __forceinline__ void cp4(uint32_t sa, const float* ga, uint32_t sz) {
    asm volatile("cp.async.ca.shared.global [%0], [%1], 4, %2;\n"
                 :: "r"(sa), "l"(ga), "r"(sz));
}
__device__ __forceinline__ void cp16(uint32_t sa, const float* ga) {
    asm volatile("cp.async.ca.shared.global [%0], [%1], 16;\n"
                 :: "r"(sa), "l"(ga));
}
__device__ __forceinline__ uint32_t tf32_of(float f) {
    uint32_t r; asm("cvt.rna.tf32.f32 %0, %1;" : "=r"(r) : "f"(f)); return r;
}
__device__ __forceinline__ void mma_tf32(float* c, uint32_t a0, uint32_t a1,
                                         uint32_t a2, uint32_t a3,
                                         uint32_t b0, uint32_t b1) {
    asm volatile("mma.sync.aligned.m16n8k8.row.col.f32.tf32.tf32.f32 "
                 "{%0,%1,%2,%3}, {%4,%5,%6,%7}, {%8,%9}, {%0,%1,%2,%3};"
                 : "+f"(c[0]), "+f"(c[1]), "+f"(c[2]), "+f"(c[3])
                 : "r"(a0), "r"(a1), "r"(a2), "r"(a3), "r"(b0), "r"(b1));
}

// ================= pack kernels =================
__global__ void pk_w1m(const float* __restrict__ w1, const float* __restrict__ g1,
                       const float* __restrict__ b1, const float* __restrict__ m1,
                       const float* __restrict__ v1) {
    int i = blockIdx.x * blockDim.x + threadIdx.x;
    if (i >= 9*32*16*64) return;
    int s     = i & 1;
    int lane  = (i >> 1) & 31;
    int ntile = (i >> 6) & 15;
    int cg    = (i >> 10) & 31;
    int kk    = i >> 15;
    int k  = (lane & 3) + s*4;
    int ci = cg*8 + k;
    int oc = ntile*8 + (lane >> 2);
    float sc = g1[oc] * rsqrtf(v1[oc] + 1e-5f);
    float v = w1[(size_t)(oc*C1_ + ci)*9 + kk] * sc;
    g_w1m[i] = __uint_as_float(tf32_of(v));
    if (i < CH_) {
        float s0 = g1[i] * rsqrtf(v1[i] + 1e-5f);
        g_b1f[i] = b1[i] - m1[i]*s0;
    }
}

__global__ void pk_lin(const float* __restrict__ w2, const float* __restrict__ g2,
                       const float* __restrict__ b2, const float* __restrict__ m2,
                       const float* __restrict__ v2, const float* __restrict__ inw,
                       const float* __restrict__ outw, const float* __restrict__ outb,
                       const float* __restrict__ g3, const float* __restrict__ b3,
                       const float* __restrict__ m3, const float* __restrict__ v3) {
    int i = blockIdx.x * blockDim.x + threadIdx.x;
    if (i >= C2_*C2_) return;
    int o = i & 255, k = i >> 8;
    g_inwt[i] = inw[(size_t)o*C2_ + k];
    float s3 = g3[o] * rsqrtf(v3[o] + 1e-5f);
    g_outwt[i] = outw[(size_t)o*C2_ + k] * s3;
    if (k < CH_) {
        float s2 = g2[o] * rsqrtf(v2[o] + 1e-5f);
        g_w2t[(size_t)k*C2_ + o] = w2[(size_t)o*CH_ + k] * s2;
    }
    if (i < C2_) {
        float s2 = g2[i] * rsqrtf(v2[i] + 1e-5f);
        g_b2f[i] = b2[i] - m2[i]*s2;
        float s3b = g3[i] * rsqrtf(v3[i] + 1e-5f);
        g_obf[i] = outb[i]*s3b + b3[i] - m3[i]*s3b;
    }
}

__global__ void pk_frag() {
    int i = blockIdx.x * blockDim.x + threadIdx.x;
    if (i >= 32*16*32*4) return;
    int s    = i & 1;
    int half = (i >> 1) & 1;
    int lane = (i >> 2) & 31;
    int ntp  = (i >> 7) & 15;
    int kc   = i >> 11;
    int k = kc*8 + (lane & 3) + s*4;
    int n = (ntp*2 + half)*8 + (lane >> 2);
    g_inf[i]  = __uint_as_float(tf32_of(g_inwt[(size_t)k*256 + n]));
    g_outf[i] = __uint_as_float(tf32_of(g_outwt[(size_t)k*256 + n]));
    if (kc < 16)
        g_w2f[i] = __uint_as_float(tf32_of(g_w2t[(size_t)k*256 + n]));
}

// ================= NCHW -> NHWC transpose =================
__global__ void k_tr(const float* __restrict__ x) {
    __shared__ float tile[32][33];
    int n  = blockIdx.z;
    int c0 = blockIdx.y * 32, p0 = blockIdx.x * 32;
    for (int r = threadIdx.y; r < 32; r += 8)
        tile[r][threadIdx.x] = x[(size_t)(n*C1_ + c0 + r)*HW_ + p0 + threadIdx.x];
    __syncthreads();
    for (int r = threadIdx.y; r < 32; r += 8)
        g_xn[(size_t)(n*HW_ + p0 + r)*C1_ + c0 + threadIdx.x] = tile[threadIdx.x][r];
}

// ================= conv1: 3x3 256->128, tf32 mma, smem-staged weights =============
// 8x8 px tile x 128 oc. 8 warps = 4 m-tiles x 2 oc halves.
// Weights: per (chunk, tap) a contiguous 16KB slab of g_w1m is cp.async-staged into
// smem (double-buffered per kk step); compute reads LDS.64 broadcast, no per-mma LDG.
// Dynamic smem: sIn 2x32xPL (34.8KB) + sW 2x4096 (32KB) = 67584 B.
extern __shared__ float c1smem[];
__global__ __launch_bounds__(256, 3) void c1_tf32() {
    float* sIn = c1smem;               // [2][32*PL]
    float* sW  = c1smem + 2*32*PL;     // [2][4096]
    int tid = threadIdx.x;
    int n = blockIdx.z;
    int by = blockIdx.y * 8, bx = blockIdx.x * 8;
    int warp = tid >> 5;
    int lane = tid & 31;
    int t  = warp & 3;
    int nh = warp >> 2;
    uint32_t sib = smem_u32(sIn);
    uint32_t swb = smem_u32(sW);

    // ---- input loader (validated) ----
    int py = warp;
    int pak[13]; unsigned ebits = 0, vbits = 0;
    #pragma unroll
    for (int j = 0; j < 13; j++) {
        int p = py + j*8;
        pak[j] = 0;
        if (p < 100) {
            int hy = p / 10, hx = p - hy*10;
            int gy = by + hy - 1, gx = bx + hx - 1;
            bool v = (gy >= 0 && gy < H_ && gx >= 0 && gx < W_);
            int pix = v ? (n*HW_ + gy*W_ + gx) : 0;
            pak[j] = ((pix*256 + lane) << 7) | (hy*12 + hx);
            ebits |= 1u << j;
            if (v) vbits |= 1u << j;
        }
    }
    auto load_input = [&](int cc, int b) {
        uint32_t soff0 = sib + (uint32_t)(b * 32 * PL + lane * PL) * 4u;
        #pragma unroll
        for (int j = 0; j < 13; j++) {
            if (ebits >> j & 1) {
                uint32_t sa = soff0 + (uint32_t)(pak[j] & 127) * 4u;
                uint32_t sz = (vbits >> j & 1) ? 4u : 0u;
                cp4(sa, g_xn + (pak[j] >> 7) + cc, sz);
            }
        }
        asm volatile("cp.async.commit_group;");
    };

    // ---- weight slab loader: (chunk c, tap kk) -> 4096 floats, contiguous ----
    auto load_w = [&](int c, int kk, int b) {
        const float* src = g_w1m + (size_t)(kk*32 + c*4)*1024 + tid*4;
        uint32_t dst = swb + (uint32_t)(b*4096 + tid*4)*4u;
        #pragma unroll
        for (int q = 0; q < 4; q++)
            cp16(dst + q*4096u, src + q*1024);
        asm volatile("cp.async.commit_group;");
    };

    load_input(0, 0);
    load_w(0, 0, 0);
    asm volatile("cp.async.wait_group 0;");
    __syncthreads();

    float acc[8][4];
    #pragma unroll
    for (int nt = 0; nt < 8; nt++)
        #pragma unroll
        for (int j = 0; j < 4; j++) acc[nt][j] = 0.0f;

    int arow = lane >> 2;
    int acix = lane & 3;
    int ib = 0, wb = 0;
    #pragma unroll 1
    for (int c = 0; c < 8; c++) {
        #pragma unroll 1
        for (int kk = 0; kk < 9; kk++) {
            bool last = (c == 7) && (kk == 8);
            if (!last) {
                int nc = c, nkk = kk + 1;
                if (nkk == 9) { nc = c + 1; nkk = 0; }
                load_w(nc, nkk, wb ^ 1);
            }
            if (kk == 0 && c < 7) load_input((c + 1)*32, ib ^ 1);

            int dy = kk / 3, dx = kk - 3*dy;
            int posb = (2*t + dy)*12 + arow + dx;
            #pragma unroll
            for (int cig = 0; cig < 4; cig++) {
                const float* pl = &sIn[(ib*32 + cig*8 + acix) * PL];
                uint32_t a0 = tf32_of(pl[posb]);
                uint32_t a1 = tf32_of(pl[posb + 12]);
                uint32_t a2 = tf32_of(pl[4*PL + posb]);
                uint32_t a3 = tf32_of(pl[4*PL + posb + 12]);
                const float* wp = &sW[wb*4096 + (cig*16 + nh*8)*64 + lane*2];
                #pragma unroll
                for (int nt = 0; nt < 8; nt++) {
                    float2 bv = *(const float2*)(wp + nt*64);
                    mma_tf32(acc[nt], a0, a1, a2, a3,
                             __float_as_uint(bv.x), __float_as_uint(bv.y));
                }
            }

            if (!last) asm volatile("cp.async.wait_group 0;");
            __syncthreads();
            wb ^= 1;
        }
        ib ^= 1;
    }

    int pxcol = lane >> 2;
    size_t px0 = (size_t)(n*HW_ + (by + 2*t)*W_ + bx + pxcol) * CH_;
    size_t px1 = px0 + (size_t)W_ * CH_;
    int ocb = nh*64 + 2*(lane & 3);
    #pragma unroll
    for (int nt = 0; nt < 8; nt++) {
        int oc = ocb + nt*8;
        float b0 = g_b1f[oc], b1 = g_b1f[oc+1];
        float2 r0 = {silu_f(acc[nt][0] + b0), silu_f(acc[nt][1] + b1)};
        float2 r1 = {silu_f(acc[nt][2] + b0), silu_f(acc[nt][3] + b1)};
        *(float2*)&g_y1[px0 + oc] = r0;
        *(float2*)&g_y1[px1 + oc] = r1;
    }
}

// ================= tf32 GEMM (R13 verbatim) =================
template<int KD, int MODE>
__global__ __launch_bounds__(256) void gmt(const float* __restrict__ bias_ext,
                                           float* __restrict__ out_ext,
                                           const float* __restrict__ resid_ext) {
    const float* A    = (MODE == 0) ? g_y1  : (MODE == 1 ? g_y2  : g_dcn);
    const float* WF   = (MODE == 0) ? g_w2f : (MODE == 1 ? g_inf : g_outf);
    const float* bias = (MODE == 0) ? g_b2f : (MODE == 1 ? bias_ext : g_obf);
    float* C          = (MODE == 0) ? g_y2  : (MODE == 1 ? g_xproj : out_ext);

    __shared__ float As[2][64][36];
    int tid = threadIdx.x;
    int warp = tid >> 5, lane = tid & 31;
    int t = warp & 3, nh = warp >> 2;
    int m0 = blockIdx.x * 64;

    float acc[16][4];
    #pragma unroll
    for (int j = 0; j < 16; j++)
        #pragma unroll
        for (int q = 0; q < 4; q++) acc[j][q] = 0.0f;

    int lr = tid >> 2;
    int lk = (tid & 3) * 8;

    float4 ra = *(const float4*)&A[(size_t)(m0 + lr)*KD + lk];
    float4 rb = *(const float4*)&A[(size_t)(m0 + lr)*KD + lk + 4];

    int am = 16*t + (lane >> 2);
    int buf = 0;
    for (int k0 = 0; k0 < KD; k0 += 32) {
        *(float4*)&As[buf][lr][lk]     = ra;
        *(float4*)&As[buf][lr][lk + 4] = rb;
        __syncthreads();
        if (k0 + 32 < KD) {
            ra = *(const float4*)&A[(size_t)(m0 + lr)*KD + k0 + 32 + lk];
            rb = *(const float4*)&A[(size_t)(m0 + lr)*KD + k0 + 32 + lk + 4];
        }
        #pragma unroll
        for (int ks = 0; ks < 4; ks++) {
            int kof = ks*8 + (lane & 3);
            uint32_t a0 = tf32_of(As[buf][am][kof]);
            uint32_t a1 = tf32_of(As[buf][am + 8][kof]);
            uint32_t a2 = tf32_of(As[buf][am][kof + 4]);
            uint32_t a3 = tf32_of(As[buf][am + 8][kof + 4]);
            int kc = (k0 >> 3) + ks;
            const float* wp = &WF[(((size_t)kc*16 + nh*8)*32 + lane)*4];
            #pragma unroll
            for (int jp = 0; jp < 8; jp++) {
                float4 bv = *(const float4*)(wp + jp*128);
                mma_tf32(acc[2*jp],   a0, a1, a2, a3,
                         __float_as_uint(bv.x), __float_as_uint(bv.y));
                mma_tf32(acc[2*jp+1], a0, a1, a2, a3,
                         __float_as_uint(bv.z), __float_as_uint(bv.w));
            }
        }
        buf ^= 1;
    }

    int r0 = m0 + 16*t + (lane >> 2);
    int r1 = r0 + 8;
    int nimg = m0 / HW_;
    int pp0 = r0 - nimg*HW_, pp1 = r1 - nimg*HW_;
    int ncb = nh*128 + 2*(lane & 3);
    #pragma unroll
    for (int j = 0; j < 16; j++) {
        int nn = ncb + j*8;
        float b0 = bias[nn], b1 = bias[nn+1];
        float v0 = acc[j][0] + b0, v1 = acc[j][1] + b1;
        float v2 = acc[j][2] + b0, v3 = acc[j][3] + b1;
        if (MODE == 0 || MODE == 2) {
            v0 = silu_f(v0); v1 = silu_f(v1);
            v2 = silu_f(v2); v3 = silu_f(v3);
        }
        if (MODE <= 1) {
            *(float2*)&C[(size_t)r0*256 + nn] = make_float2(v0, v1);
            *(float2*)&C[(size_t)r1*256 + nn] = make_float2(v2, v3);
        } else {
            size_t b0i = (size_t)(nimg*256 + nn)*HW_;
            C[b0i + pp0]        = resid_ext[b0i + pp0]        + v0;
            C[b0i + HW_ + pp0]  = resid_ext[b0i + HW_ + pp0]  + v1;
            C[b0i + pp1]        = resid_ext[b0i + pp1]        + v2;
            C[b0i + HW_ + pp1]  = resid_ext[b0i + HW_ + pp1]  + v3;
        }
    }
}

// ================= depthwise 3x3 + bias + LayerNorm + GELU =================
__global__ __launch_bounds__(128) void p_dwlngelu2(const float* __restrict__ dww,
                                                   const float* __restrict__ dwb,
                                                   const float* __restrict__ lng,
                                                   const float* __restrict__ lnb) {
    int p = blockIdx.x;
    int n = p / HW_, pp = p - n*HW_;
    int y = pp / W_, xx = pp - y*W_;
    int c2 = threadIdx.x;
    int c0 = 2*c2;

    float2 acc = {0.0f, 0.0f};
    for (int ky = 0; ky < 3; ky++) {
        int gy = y + ky - 1;
        if (gy < 0 || gy >= H_) continue;
        for (int kx = 0; kx < 3; kx++) {
            int gx = xx + kx - 1;
            if (gx < 0 || gx >= W_) continue;
            float2 v = *(const float2*)&g_y2[(size_t)(n*HW_ + gy*W_ + gx)*C2_ + c0];
            int kk = ky*3 + kx;
            acc.x = fmaf(v.x, dww[c0*9 + kk], acc.x);
            acc.y = fmaf(v.y, dww[(c0+1)*9 + kk], acc.y);
        }
    }
    acc.x += dwb[c0];
    acc.y += dwb[c0+1];

    __shared__ float red[4], red2[4];
    int warp = c2 >> 5, lane = c2 & 31;
    float s = acc.x + acc.y;
    #pragma unroll
    for (int o = 16; o; o >>= 1) s += __shfl_xor_sync(0xffffffffu, s, o);
    if (lane == 0) red[warp] = s;
    __syncthreads();
    float mu = (red[0] + red[1] + red[2] + red[3]) * (1.0f/256.0f);

    float d0 = acc.x - mu, d1 = acc.y - mu;
    float v2 = d0*d0 + d1*d1;
    #pragma unroll
    for (int o = 16; o; o >>= 1) v2 += __shfl_xor_sync(0xffffffffu, v2, o);
    if (lane == 0) red2[warp] = v2;
    __syncthreads();
    float var = (red2[0] + red2[1] + red2[2] + red2[3]) * (1.0f/256.0f);
    float rs = rsqrtf(var + 1e-6f);

    float o0 = d0 * rs * lng[c0]   + lnb[c0];
    float o1 = d1 * rs * lng[c0+1] + lnb[c0+1];
    float2 g;
    g.x = 0.5f * o0 * (1.0f + erff(o0 * 0.70710678118654752f));
    g.y = 0.5f * o1 * (1.0f + erff(o1 * 0.70710678118654752f));
    *(float2*)&g_dw[(size_t)p*C2_ + c0] = g;
}

// ================= offset + mask heads =================
__global__ __launch_bounds__(256) void p_offmask2(const float* __restrict__ offw,
                                                  const float* __restrict__ offb,
                                                  const float* __restrict__ mskw,
                                                  const float* __restrict__ mskb) {
    __shared__ float wsm[27*256];
    __shared__ float sdw[256];
    __shared__ float sres[27];
    int tid = threadIdx.x;
    int warp = tid >> 5, lane = tid & 31;

    #pragma unroll
    for (int i = tid; i < 27*256; i += 256) {
        int r = i >> 8, c = i & 255;
        wsm[i] = (r < 18) ? offw[r*256 + c] : mskw[(r - 18)*256 + c];
    }
    __syncthreads();

    int p0 = blockIdx.x * 32;
    for (int pi = 0; pi < 32; pi++) {
        int p = p0 + pi;
        sdw[tid] = g_dw[(size_t)p*256 + tid];
        __syncthreads();
        for (int r = warp; r < 27; r += 8) {
            const float* wr = &wsm[r*256];
            float s = 0.0f;
            #pragma unroll
            for (int k = 0; k < 8; k++) s += sdw[lane + 32*k] * wr[lane + 32*k];
            #pragma unroll
            for (int o = 16; o; o >>= 1) s += __shfl_xor_sync(0xffffffffu, s, o);
            if (lane == 0) sres[r] = s;
        }
        __syncthreads();
        if (tid < 18) g_off[(size_t)p*18 + tid] = sres[tid] + offb[tid];
        if (tid == 0) {
            float l[9], mx = -1e30f;
            #pragma unroll
            for (int k = 0; k < 9; k++) { l[k] = sres[18+k] + mskb[k]; mx = fmaxf(mx, l[k]); }
            float se = 0.0f;
            #pragma unroll
            for (int k = 0; k < 9; k++) { l[k] = expf(l[k] - mx); se += l[k]; }
            float inv = 1.0f / se;
            #pragma unroll
            for (int k = 0; k < 9; k++) g_msk[(size_t)p*9 + k] = l[k]*inv;
        }
        __syncthreads();
    }
}

// ================= DCNv3 core (2 pixels/block, float2 channels) =================
__global__ __launch_bounds__(256) void p_dcn2() {
    int tid  = threadIdx.x;
    int half = tid >> 7;
    int c2   = tid & 127;
    int p = blockIdx.x * 2 + half;
    int n = p / HW_, pp = p - n*HW_;
    int y = pp / W_, xx = pp - y*W_;

    __shared__ float sw[2][9][4];
    __shared__ int   sx0[2][9], sy0[2][9];
    if (c2 < 9) {
        int k = c2;
        float m  = g_msk[(size_t)p*9 + k];
        float ox = g_off[(size_t)p*18 + 2*k];
        float oy = g_off[(size_t)p*18 + 2*k + 1];
        float px = (float)xx + (float)(k/3) + ox;
        float py = (float)y  + (float)(k%3) + oy;
        float x0f = floorf(px), y0f = floorf(py);
        float lw = px - x0f, lh = py - y0f;
        sw[half][k][0] = m * (1.0f - lh) * (1.0f - lw);
        sw[half][k][1] = m * (1.0f - lh) * lw;
        sw[half][k][2] = m * lh * (1.0f - lw);
        sw[half][k][3] = m * lh * lw;
        sx0[half][k] = (int)x0f;
        sy0[half][k] = (int)y0f;
    }
    __syncthreads();

    const float* Xb = &g_xproj[(size_t)n * HW_ * C2_];
    float2 acc = {0.0f, 0.0f};
    for (int k = 0; k < 9; k++) {
        int x0 = sx0[half][k], y0 = sy0[half][k];
        #pragma unroll
        for (int t = 0; t < 4; t++) {
            int xi = x0 + (t & 1);
            int yi = y0 + (t >> 1);
            if (xi >= 1 && xi <= W_ && yi >= 1 && yi <= H_) {
                float2 v = *(const float2*)&Xb[(size_t)((yi-1)*W_ + (xi-1))*C2_ + 2*c2];
                float wv = sw[half][k][t];
                acc.x = fmaf(wv, v.x, acc.x);
                acc.y = fmaf(wv, v.y, acc.y);
            }
        }
    }
    *(float2*)&g_dcn[(size_t)p*C2_ + 2*c2] = acc;
}

// ---------------- launch ----------------
extern "C" void kernel_launch(void* const* d_in, const int* in_sizes, int n_in,
                              void* d_out, int out_size) {
    const float* x     = (const float*)d_in[0];
    const float* w1    = (const float*)d_in[1];
    const float* g1    = (const float*)d_in[2];
    const float* b1    = (const float*)d_in[3];
    const float* m1    = (const float*)d_in[4];
    const float* v1    = (const float*)d_in[5];
    const float* w2    = (const float*)d_in[6];
    const float* g2    = (const float*)d_in[7];
    const float* b2    = (const float*)d_in[8];
    const float* m2    = (const float*)d_in[9];
    const float* v2    = (const float*)d_in[10];
    const float* dw_w  = (const float*)d_in[11];
    const float* dw_b  = (const float*)d_in[12];
    const float* ln_g  = (const float*)d_in[13];
    const float* ln_b  = (const float*)d_in[14];
    const float* off_w = (const float*)d_in[15];
    const float* off_b = (const float*)d_in[16];
    const float* msk_w = (const float*)d_in[17];
    const float* msk_b = (const float*)d_in[18];
    const float* in_w  = (const float*)d_in[19];
    const float* in_b  = (const float*)d_in[20];
    const float* out_w = (const float*)d_in[21];
    const float* out_b = (const float*)d_in[22];
    const float* g3    = (const float*)d_in[23];
    const float* b3    = (const float*)d_in[24];
    const float* m3    = (const float*)d_in[25];
    const float* v3    = (const float*)d_in[26];
    float* out = (float*)d_out;

    const int C1SMEM = (2*32*PL + 2*4096) * 4;   // 67584 bytes
    cudaFuncSetAttribute(c1_tf32, cudaFuncAttributeMaxDynamicSharedMemorySize, C1SMEM);

    pk_w1m<<<(9*32*16*64 + 255)/256, 256>>>(w1, g1, b1, m1, v1);
    pk_lin<<<(C2_*C2_ + 255)/256, 256>>>(w2, g2, b2, m2, v2, in_w, out_w, out_b,
                                         g3, b3, m3, v3);
    pk_frag<<<(32*16*32*4 + 255)/256, 256>>>();
    k_tr<<<dim3(HW_/32, C1_/32, N_), dim3(32, 8)>>>(x);
    c1_tf32<<<dim3(W_/8, H_/8, N_), 256, C1SMEM>>>();
    gmt<128, 0><<<M_/64, 256>>>(nullptr, nullptr, nullptr);
    p_dwlngelu2<<<M_, 128>>>(dw_w, dw_b, ln_g, ln_b);
    p_offmask2<<<M_/32, 256>>>(off_w, off_b, msk_w, msk_b);
    gmt<256, 1><<<M_/64, 256>>>(in_b, nullptr, nullptr);
    p_dcn2<<<M_/2, 256>>>();
    gmt<256, 2><<<M_/64, 256>>>(nullptr, out, x);
}

// round 15
// speedup vs baseline: 2.6751x; 1.0641x over previous
#include <cuda_runtime.h>
#include <cuda_bf16.h>
#include <math.h>
#include <stdint.h>

// ---------------- problem constants ----------------
#define N_   4
#define C1_  256
#define C2_  256
#define CH_  128
#define H_   80
#define W_   80
#define HW_  6400
#define M_   (N_*HW_)      // 25600 pixels total
#define PL   136           // conv1 smem plane stride

// ---------------- scratch (referenced ONLY inside device code!) ----------------
__device__ float    g_xn[M_*C1_];       // x in NHWC
__device__ uint32_t g_w1b[9*16*16*32*2]; // conv1 w, bf16x2 mma-B fragments, BN-folded
__device__ float    g_b1f[CH_];
__device__ float    g_w2t[CH_*C2_];     // conv2 w [k][o], BN-folded
__device__ float    g_b2f[C2_];
__device__ float    g_inwt[C2_*C2_];    // in_w [k][o]
__device__ float    g_outwt[C2_*C2_];   // out_w [k][o], BN3-folded
__device__ float    g_obf[C2_];
__device__ float    g_w2f[16*16*32*4];  // conv2 w fragments (tf32)
__device__ float    g_inf[32*16*32*4];  // in_w fragments
__device__ float    g_outf[32*16*32*4]; // out_w fragments
__device__ float    g_y1[M_*CH_];
__device__ float    g_y2[M_*C2_];
__device__ float    g_dw[M_*C2_];
__device__ float    g_xproj[M_*C2_];
__device__ float    g_dcn[M_*C2_];
__device__ float    g_off[M_*18];
__device__ float    g_msk[M_*9];

__device__ __forceinline__ float silu_f(float v) { return v / (1.0f + expf(-v)); }

typedef unsigned long long ull;
__device__ __forceinline__ uint32_t smem_u32(const void* p) {
    uint32_t a;
    asm("{ .reg .u64 t; cvta.to.shared.u64 t, %1; cvt.u32.u64 %0, t; }" : "=r"(a) : "l"(p));
    return a;
}
__device__ __forceinline__ void cp4(uint32_t sa, const float* ga, uint32_t sz) {
    asm volatile("cp.async.ca.shared.global [%0], [%1], 4, %2;\n"
                 :: "r"(sa), "l"(ga), "r"(sz));
}
__device__ __forceinline__ void cp16(uint32_t sa, const void* ga) {
    asm volatile("cp.async.ca.shared.global [%0], [%1], 16;\n"
                 :: "r"(sa), "l"(ga));
}
__device__ __forceinline__ uint32_t tf32_of(float f) {
    uint32_t r; asm("cvt.rna.tf32.f32 %0, %1;" : "=r"(r) : "f"(f)); return r;
}
__device__ __forceinline__ uint32_t pkbf(float lo, float hi) {
    uint32_t r; asm("cvt.rn.bf16x2.f32 %0, %1, %2;" : "=r"(r) : "f"(hi), "f"(lo)); return r;
}
__device__ __forceinline__ void mma_tf32(float* c, uint32_t a0, uint32_t a1,
                                         uint32_t a2, uint32_t a3,
                                         uint32_t b0, uint32_t b1) {
    asm volatile("mma.sync.aligned.m16n8k8.row.col.f32.tf32.tf32.f32 "
                 "{%0,%1,%2,%3}, {%4,%5,%6,%7}, {%8,%9}, {%0,%1,%2,%3};"
                 : "+f"(c[0]), "+f"(c[1]), "+f"(c[2]), "+f"(c[3])
                 : "r"(a0), "r"(a1), "r"(a2), "r"(a3), "r"(b0), "r"(b1));
}
__device__ __forceinline__ void mma_bf16(float* c, uint32_t a0, uint32_t a1,
                                         uint32_t a2, uint32_t a3,
                                         uint32_t b0, uint32_t b1) {
    asm volatile("mma.sync.aligned.m16n8k16.row.col.f32.bf16.bf16.f32 "
                 "{%0,%1,%2,%3}, {%4,%5,%6,%7}, {%8,%9}, {%0,%1,%2,%3};"
                 : "+f"(c[0]), "+f"(c[1]), "+f"(c[2]), "+f"(c[3])
                 : "r"(a0), "r"(a1), "r"(a2), "r"(a3), "r"(b0), "r"(b1));
}

// ================= pack kernels =================
// conv1 weights -> bf16 m16n8k16 B-fragments, BN-folded.
// i bits: [0]=reg, [1:6]=lane, [6:10]=nt, [10:14]=cg, [14:]=kk
// reg r: k-pair base = (lane&3)*2 + r*8; oc = nt*8 + lane>>2; ci = cg*16 + kbase (+1)
__global__ void pk_w1b(const float* __restrict__ w1, const float* __restrict__ g1,
                       const float* __restrict__ b1, const float* __restrict__ m1,
                       const float* __restrict__ v1) {
    int i = blockIdx.x * blockDim.x + threadIdx.x;
    if (i >= 9*16*16*32*2) return;
    int reg  = i & 1;
    int lane = (i >> 1) & 31;
    int nt   = (i >> 6) & 15;
    int cg   = (i >> 10) & 15;
    int kk   = i >> 14;
    int oc = nt*8 + (lane >> 2);
    int ci0 = cg*16 + (lane & 3)*2 + reg*8;
    float sc = g1[oc] * rsqrtf(v1[oc] + 1e-5f);
    float v0 = w1[(size_t)(oc*C1_ + ci0)*9 + kk] * sc;
    float v1v = w1[(size_t)(oc*C1_ + ci0 + 1)*9 + kk] * sc;
    g_w1b[i] = pkbf(v0, v1v);
    if (i < CH_) {
        float s0 = g1[i] * rsqrtf(v1[i] + 1e-5f);
        g_b1f[i] = b1[i] - m1[i]*s0;
    }
}

__global__ void pk_lin(const float* __restrict__ w2, const float* __restrict__ g2,
                       const float* __restrict__ b2, const float* __restrict__ m2,
                       const float* __restrict__ v2, const float* __restrict__ inw,
                       const float* __restrict__ outw, const float* __restrict__ outb,
                       const float* __restrict__ g3, const float* __restrict__ b3,
                       const float* __restrict__ m3, const float* __restrict__ v3) {
    int i = blockIdx.x * blockDim.x + threadIdx.x;
    if (i >= C2_*C2_) return;
    int o = i & 255, k = i >> 8;
    g_inwt[i] = inw[(size_t)o*C2_ + k];
    float s3 = g3[o] * rsqrtf(v3[o] + 1e-5f);
    g_outwt[i] = outw[(size_t)o*C2_ + k] * s3;
    if (k < CH_) {
        float s2 = g2[o] * rsqrtf(v2[o] + 1e-5f);
        g_w2t[(size_t)k*C2_ + o] = w2[(size_t)o*CH_ + k] * s2;
    }
    if (i < C2_) {
        float s2 = g2[i] * rsqrtf(v2[i] + 1e-5f);
        g_b2f[i] = b2[i] - m2[i]*s2;
        float s3b = g3[i] * rsqrtf(v3[i] + 1e-5f);
        g_obf[i] = outb[i]*s3b + b3[i] - m3[i]*s3b;
    }
}

__global__ void pk_frag() {
    int i = blockIdx.x * blockDim.x + threadIdx.x;
    if (i >= 32*16*32*4) return;
    int s    = i & 1;
    int half = (i >> 1) & 1;
    int lane = (i >> 2) & 31;
    int ntp  = (i >> 7) & 15;
    int kc   = i >> 11;
    int k = kc*8 + (lane & 3) + s*4;
    int n = (ntp*2 + half)*8 + (lane >> 2);
    g_inf[i]  = __uint_as_float(tf32_of(g_inwt[(size_t)k*256 + n]));
    g_outf[i] = __uint_as_float(tf32_of(g_outwt[(size_t)k*256 + n]));
    if (kc < 16)
        g_w2f[i] = __uint_as_float(tf32_of(g_w2t[(size_t)k*256 + n]));
}

// ================= NCHW -> NHWC transpose =================
__global__ void k_tr(const float* __restrict__ x) {
    __shared__ float tile[32][33];
    int n  = blockIdx.z;
    int c0 = blockIdx.y * 32, p0 = blockIdx.x * 32;
    for (int r = threadIdx.y; r < 32; r += 8)
        tile[r][threadIdx.x] = x[(size_t)(n*C1_ + c0 + r)*HW_ + p0 + threadIdx.x];
    __syncthreads();
    for (int r = threadIdx.y; r < 32; r += 8)
        g_xn[(size_t)(n*HW_ + p0 + r)*C1_ + c0 + threadIdx.x] = tile[threadIdx.x][r];
}

// ================= conv1: 3x3 256->128, bf16 mma m16n8k16, BN+SiLU =============
// Same structure as R14 (validated loader, per-(chunk,tap) slab staging), but bf16:
// half the mma count (2 k16 steps per 32-ci chunk), 8KB slabs.
// Dynamic smem: sIn 2x32xPL fp32 (34816B) + sW 2x2048 u32 (16384B) = 51200B.
extern __shared__ float c1smem[];
__global__ __launch_bounds__(256, 3) void c1_bf16() {
    float*    sIn = c1smem;                          // [2][32*PL]
    uint32_t* sW  = (uint32_t*)(c1smem + 2*32*PL);   // [2][2048]
    int tid = threadIdx.x;
    int n = blockIdx.z;
    int by = blockIdx.y * 8, bx = blockIdx.x * 8;
    int warp = tid >> 5;
    int lane = tid & 31;
    int t  = warp & 3;
    int nh = warp >> 2;
    uint32_t sib = smem_u32(sIn);
    uint32_t swb = smem_u32(sW);

    // ---- input loader (validated) ----
    int py = warp;
    int pak[13]; unsigned ebits = 0, vbits = 0;
    #pragma unroll
    for (int j = 0; j < 13; j++) {
        int p = py + j*8;
        pak[j] = 0;
        if (p < 100) {
            int hy = p / 10, hx = p - hy*10;
            int gy = by + hy - 1, gx = bx + hx - 1;
            bool v = (gy >= 0 && gy < H_ && gx >= 0 && gx < W_);
            int pix = v ? (n*HW_ + gy*W_ + gx) : 0;
            pak[j] = ((pix*256 + lane) << 7) | (hy*12 + hx);
            ebits |= 1u << j;
            if (v) vbits |= 1u << j;
        }
    }
    auto load_input = [&](int cc, int b) {
        uint32_t soff0 = sib + (uint32_t)(b * 32 * PL + lane * PL) * 4u;
        #pragma unroll
        for (int j = 0; j < 13; j++) {
            if (ebits >> j & 1) {
                uint32_t sa = soff0 + (uint32_t)(pak[j] & 127) * 4u;
                uint32_t sz = (vbits >> j & 1) ? 4u : 0u;
                cp4(sa, g_xn + (pak[j] >> 7) + cc, sz);
            }
        }
        asm volatile("cp.async.commit_group;");
    };

    // ---- weight slab: (chunk c, tap kk) -> 2048 u32 contiguous (cg pair 2c,2c+1) ----
    auto load_w = [&](int c, int kk, int b) {
        const uint32_t* src = g_w1b + (size_t)(kk*16 + c*2)*1024 + tid*8;
        uint32_t dst = swb + (uint32_t)(b*2048 + tid*8)*4u;
        cp16(dst, src);
        cp16(dst + 16u, src + 4);
        asm volatile("cp.async.commit_group;");
    };

    load_input(0, 0);
    load_w(0, 0, 0);
    asm volatile("cp.async.wait_group 0;");
    __syncthreads();

    float acc[8][4];
    #pragma unroll
    for (int nt = 0; nt < 8; nt++)
        #pragma unroll
        for (int j = 0; j < 4; j++) acc[nt][j] = 0.0f;

    int arow = lane >> 2;
    int ib = 0, wb = 0;
    #pragma unroll 1
    for (int c = 0; c < 8; c++) {
        #pragma unroll 1
        for (int kk = 0; kk < 9; kk++) {
            bool last = (c == 7) && (kk == 8);
            if (!last) {
                int nc = c, nkk = kk + 1;
                if (nkk == 9) { nc = c + 1; nkk = 0; }
                load_w(nc, nkk, wb ^ 1);
            }
            if (kk == 0 && c < 7) load_input((c + 1)*32, ib ^ 1);

            int dy = kk / 3, dx = kk - 3*dy;
            int posb = (2*t + dy)*12 + arow + dx;
            #pragma unroll
            for (int cig = 0; cig < 2; cig++) {
                const float* pl = &sIn[(ib*32 + cig*16 + 2*(lane & 3)) * PL];
                uint32_t a0 = pkbf(pl[posb],            pl[PL + posb]);
                uint32_t a1 = pkbf(pl[posb + 12],       pl[PL + posb + 12]);
                uint32_t a2 = pkbf(pl[8*PL + posb],     pl[9*PL + posb]);
                uint32_t a3 = pkbf(pl[8*PL + posb + 12],pl[9*PL + posb + 12]);
                const uint32_t* wp = &sW[wb*2048 + cig*1024 + nh*8*64 + lane*2];
                #pragma unroll
                for (int nt = 0; nt < 8; nt++) {
                    uint2 bb = *(const uint2*)(wp + nt*64);
                    mma_bf16(acc[nt], a0, a1, a2, a3, bb.x, bb.y);
                }
            }

            if (!last) asm volatile("cp.async.wait_group 0;");
            __syncthreads();
            wb ^= 1;
        }
        ib ^= 1;
    }

    int pxcol = lane >> 2;
    size_t px0 = (size_t)(n*HW_ + (by + 2*t)*W_ + bx + pxcol) * CH_;
    size_t px1 = px0 + (size_t)W_ * CH_;
    int ocb = nh*64 + 2*(lane & 3);
    #pragma unroll
    for (int nt = 0; nt < 8; nt++) {
        int oc = ocb + nt*8;
        float b0 = g_b1f[oc], b1 = g_b1f[oc+1];
        float2 r0 = {silu_f(acc[nt][0] + b0), silu_f(acc[nt][1] + b1)};
        float2 r1 = {silu_f(acc[nt][2] + b0), silu_f(acc[nt][3] + b1)};
        *(float2*)&g_y1[px0 + oc] = r0;
        *(float2*)&g_y1[px1 + oc] = r1;
    }
}

// ================= tf32 GEMM (R13 verbatim) =================
template<int KD, int MODE>
__global__ __launch_bounds__(256) void gmt(const float* __restrict__ bias_ext,
                                           float* __restrict__ out_ext,
                                           const float* __restrict__ resid_ext) {
    const float* A    = (MODE == 0) ? g_y1  : (MODE == 1 ? g_y2  : g_dcn);
    const float* WF   = (MODE == 0) ? g_w2f : (MODE == 1 ? g_inf : g_outf);
    const float* bias = (MODE == 0) ? g_b2f : (MODE == 1 ? bias_ext : g_obf);
    float* C          = (MODE == 0) ? g_y2  : (MODE == 1 ? g_xproj : out_ext);

    __shared__ float As[2][64][36];
    int tid = threadIdx.x;
    int warp = tid >> 5, lane = tid & 31;
    int t = warp & 3, nh = warp >> 2;
    int m0 = blockIdx.x * 64;

    float acc[16][4];
    #pragma unroll
    for (int j = 0; j < 16; j++)
        #pragma unroll
        for (int q = 0; q < 4; q++) acc[j][q] = 0.0f;

    int lr = tid >> 2;
    int lk = (tid & 3) * 8;

    float4 ra = *(const float4*)&A[(size_t)(m0 + lr)*KD + lk];
    float4 rb = *(const float4*)&A[(size_t)(m0 + lr)*KD + lk + 4];

    int am = 16*t + (lane >> 2);
    int buf = 0;
    for (int k0 = 0; k0 < KD; k0 += 32) {
        *(float4*)&As[buf][lr][lk]     = ra;
        *(float4*)&As[buf][lr][lk + 4] = rb;
        __syncthreads();
        if (k0 + 32 < KD) {
            ra = *(const float4*)&A[(size_t)(m0 + lr)*KD + k0 + 32 + lk];
            rb = *(const float4*)&A[(size_t)(m0 + lr)*KD + k0 + 32 + lk + 4];
        }
        #pragma unroll
        for (int ks = 0; ks < 4; ks++) {
            int kof = ks*8 + (lane & 3);
            uint32_t a0 = tf32_of(As[buf][am][kof]);
            uint32_t a1 = tf32_of(As[buf][am + 8][kof]);
            uint32_t a2 = tf32_of(As[buf][am][kof + 4]);
            uint32_t a3 = tf32_of(As[buf][am + 8][kof + 4]);
            int kc = (k0 >> 3) + ks;
            const float* wp = &WF[(((size_t)kc*16 + nh*8)*32 + lane)*4];
            #pragma unroll
            for (int jp = 0; jp < 8; jp++) {
                float4 bv = *(const float4*)(wp + jp*128);
                mma_tf32(acc[2*jp],   a0, a1, a2, a3,
                         __float_as_uint(bv.x), __float_as_uint(bv.y));
                mma_tf32(acc[2*jp+1], a0, a1, a2, a3,
                         __float_as_uint(bv.z), __float_as_uint(bv.w));
            }
        }
        buf ^= 1;
    }

    int r0 = m0 + 16*t + (lane >> 2);
    int r1 = r0 + 8;
    int nimg = m0 / HW_;
    int pp0 = r0 - nimg*HW_, pp1 = r1 - nimg*HW_;
    int ncb = nh*128 + 2*(lane & 3);
    #pragma unroll
    for (int j = 0; j < 16; j++) {
        int nn = ncb + j*8;
        float b0 = bias[nn], b1 = bias[nn+1];
        float v0 = acc[j][0] + b0, v1 = acc[j][1] + b1;
        float v2 = acc[j][2] + b0, v3 = acc[j][3] + b1;
        if (MODE == 0 || MODE == 2) {
            v0 = silu_f(v0); v1 = silu_f(v1);
            v2 = silu_f(v2); v3 = silu_f(v3);
        }
        if (MODE <= 1) {
            *(float2*)&C[(size_t)r0*256 + nn] = make_float2(v0, v1);
            *(float2*)&C[(size_t)r1*256 + nn] = make_float2(v2, v3);
        } else {
            size_t b0i = (size_t)(nimg*256 + nn)*HW_;
            C[b0i + pp0]        = resid_ext[b0i + pp0]        + v0;
            C[b0i + HW_ + pp0]  = resid_ext[b0i + HW_ + pp0]  + v1;
            C[b0i + pp1]        = resid_ext[b0i + pp1]        + v2;
            C[b0i + HW_ + pp1]  = resid_ext[b0i + HW_ + pp1]  + v3;
        }
    }
}

// ================= depthwise 3x3 + bias + LayerNorm + GELU =================
__global__ __launch_bounds__(128) void p_dwlngelu2(const float* __restrict__ dww,
                                                   const float* __restrict__ dwb,
                                                   const float* __restrict__ lng,
                                                   const float* __restrict__ lnb) {
    int p = blockIdx.x;
    int n = p / HW_, pp = p - n*HW_;
    int y = pp / W_, xx = pp - y*W_;
    int c2 = threadIdx.x;
    int c0 = 2*c2;

    float2 acc = {0.0f, 0.0f};
    for (int ky = 0; ky < 3; ky++) {
        int gy = y + ky - 1;
        if (gy < 0 || gy >= H_) continue;
        for (int kx = 0; kx < 3; kx++) {
            int gx = xx + kx - 1;
            if (gx < 0 || gx >= W_) continue;
            float2 v = *(const float2*)&g_y2[(size_t)(n*HW_ + gy*W_ + gx)*C2_ + c0];
            int kk = ky*3 + kx;
            acc.x = fmaf(v.x, dww[c0*9 + kk], acc.x);
            acc.y = fmaf(v.y, dww[(c0+1)*9 + kk], acc.y);
        }
    }
    acc.x += dwb[c0];
    acc.y += dwb[c0+1];

    __shared__ float red[4], red2[4];
    int warp = c2 >> 5, lane = c2 & 31;
    float s = acc.x + acc.y;
    #pragma unroll
    for (int o = 16; o; o >>= 1) s += __shfl_xor_sync(0xffffffffu, s, o);
    if (lane == 0) red[warp] = s;
    __syncthreads();
    float mu = (red[0] + red[1] + red[2] + red[3]) * (1.0f/256.0f);

    float d0 = acc.x - mu, d1 = acc.y - mu;
    float v2 = d0*d0 + d1*d1;
    #pragma unroll
    for (int o = 16; o; o >>= 1) v2 += __shfl_xor_sync(0xffffffffu, v2, o);
    if (lane == 0) red2[warp] = v2;
    __syncthreads();
    float var = (red2[0] + red2[1] + red2[2] + red2[3]) * (1.0f/256.0f);
    float rs = rsqrtf(var + 1e-6f);

    float o0 = d0 * rs * lng[c0]   + lnb[c0];
    float o1 = d1 * rs * lng[c0+1] + lnb[c0+1];
    float2 g;
    g.x = 0.5f * o0 * (1.0f + erff(o0 * 0.70710678118654752f));
    g.y = 0.5f * o1 * (1.0f + erff(o1 * 0.70710678118654752f));
    *(float2*)&g_dw[(size_t)p*C2_ + c0] = g;
}

// ================= offset + mask heads =================
__global__ __launch_bounds__(256) void p_offmask2(const float* __restrict__ offw,
                                                  const float* __restrict__ offb,
                                                  const float* __restrict__ mskw,
                                                  const float* __restrict__ mskb) {
    __shared__ float wsm[27*256];
    __shared__ float sdw[256];
    __shared__ float sres[27];
    int tid = threadIdx.x;
    int warp = tid >> 5, lane = tid & 31;

    #pragma unroll
    for (int i = tid; i < 27*256; i += 256) {
        int r = i >> 8, c = i & 255;
        wsm[i] = (r < 18) ? offw[r*256 + c] : mskw[(r - 18)*256 + c];
    }
    __syncthreads();

    int p0 = blockIdx.x * 32;
    for (int pi = 0; pi < 32; pi++) {
        int p = p0 + pi;
        sdw[tid] = g_dw[(size_t)p*256 + tid];
        __syncthreads();
        for (int r = warp; r < 27; r += 8) {
            const float* wr = &wsm[r*256];
            float s = 0.0f;
            #pragma unroll
            for (int k = 0; k < 8; k++) s += sdw[lane + 32*k] * wr[lane + 32*k];
            #pragma unroll
            for (int o = 16; o; o >>= 1) s += __shfl_xor_sync(0xffffffffu, s, o);
            if (lane == 0) sres[r] = s;
        }
        __syncthreads();
        if (tid < 18) g_off[(size_t)p*18 + tid] = sres[tid] + offb[tid];
        if (tid == 0) {
            float l[9], mx = -1e30f;
            #pragma unroll
            for (int k = 0; k < 9; k++) { l[k] = sres[18+k] + mskb[k]; mx = fmaxf(mx, l[k]); }
            float se = 0.0f;
            #pragma unroll
            for (int k = 0; k < 9; k++) { l[k] = expf(l[k] - mx); se += l[k]; }
            float inv = 1.0f / se;
            #pragma unroll
            for (int k = 0; k < 9; k++) g_msk[(size_t)p*9 + k] = l[k]*inv;
        }
        __syncthreads();
    }
}

// ================= DCNv3 core (2 pixels/block, float2 channels) =================
__global__ __launch_bounds__(256) void p_dcn2() {
    int tid  = threadIdx.x;
    int half = tid >> 7;
    int c2   = tid & 127;
    int p = blockIdx.x * 2 + half;
    int n = p / HW_, pp = p - n*HW_;
    int y = pp / W_, xx = pp - y*W_;

    __shared__ float sw[2][9][4];
    __shared__ int   sx0[2][9], sy0[2][9];
    if (c2 < 9) {
        int k = c2;
        float m  = g_msk[(size_t)p*9 + k];
        float ox = g_off[(size_t)p*18 + 2*k];
        float oy = g_off[(size_t)p*18 + 2*k + 1];
        float px = (float)xx + (float)(k/3) + ox;
        float py = (float)y  + (float)(k%3) + oy;
        float x0f = floorf(px), y0f = floorf(py);
        float lw = px - x0f, lh = py - y0f;
        sw[half][k][0] = m * (1.0f - lh) * (1.0f - lw);
        sw[half][k][1] = m * (1.0f - lh) * lw;
        sw[half][k][2] = m * lh * (1.0f - lw);
        sw[half][k][3] = m * lh * lw;
        sx0[half][k] = (int)x0f;
        sy0[half][k] = (int)y0f;
    }
    __syncthreads();

    const float* Xb = &g_xproj[(size_t)n * HW_ * C2_];
    float2 acc = {0.0f, 0.0f};
    for (int k = 0; k < 9; k++) {
        int x0 = sx0[half][k], y0 = sy0[half][k];
        #pragma unroll
        for (int t = 0; t < 4; t++) {
            int xi = x0 + (t & 1);
            int yi = y0 + (t >> 1);
            if (xi >= 1 && xi <= W_ && yi >= 1 && yi <= H_) {
                float2 v = *(const float2*)&Xb[(size_t)((yi-1)*W_ + (xi-1))*C2_ + 2*c2];
                float wv = sw[half][k][t];
                acc.x = fmaf(wv, v.x, acc.x);
                acc.y = fmaf(wv, v.y, acc.y);
            }
        }
    }
    *(float2*)&g_dcn[(size_t)p*C2_ + 2*c2] = acc;
}

// ---------------- launch ----------------
extern "C" void kernel_launch(void* const* d_in, const int* in_sizes, int n_in,
                              void* d_out, int out_size) {
    const float* x     = (const float*)d_in[0];
    const float* w1    = (const float*)d_in[1];
    const float* g1    = (const float*)d_in[2];
    const float* b1    = (const float*)d_in[3];
    const float* m1    = (const float*)d_in[4];
    const float* v1    = (const float*)d_in[5];
    const float* w2    = (const float*)d_in[6];
    const float* g2    = (const float*)d_in[7];
    const float* b2    = (const float*)d_in[8];
    const float* m2    = (const float*)d_in[9];
    const float* v2    = (const float*)d_in[10];
    const float* dw_w  = (const float*)d_in[11];
    const float* dw_b  = (const float*)d_in[12];
    const float* ln_g  = (const float*)d_in[13];
    const float* ln_b  = (const float*)d_in[14];
    const float* off_w = (const float*)d_in[15];
    const float* off_b = (const float*)d_in[16];
    const float* msk_w = (const float*)d_in[17];
    const float* msk_b = (const float*)d_in[18];
    const float* in_w  = (const float*)d_in[19];
    const float* in_b  = (const float*)d_in[20];
    const float* out_w = (const float*)d_in[21];
    const float* out_b = (const float*)d_in[22];
    const float* g3    = (const float*)d_in[23];
    const float* b3    = (const float*)d_in[24];
    const float* m3    = (const float*)d_in[25];
    const float* v3    = (const float*)d_in[26];
    float* out = (float*)d_out;

    const int C1SMEM = (2*32*PL)*4 + (2*2048)*4;   // 51200 bytes
    cudaFuncSetAttribute(c1_bf16, cudaFuncAttributeMaxDynamicSharedMemorySize, C1SMEM);

    pk_w1b<<<(9*16*16*32*2 + 255)/256, 256>>>(w1, g1, b1, m1, v1);
    pk_lin<<<(C2_*C2_ + 255)/256, 256>>>(w2, g2, b2, m2, v2, in_w, out_w, out_b,
                                         g3, b3, m3, v3);
    pk_frag<<<(32*16*32*4 + 255)/256, 256>>>();
    k_tr<<<dim3(HW_/32, C1_/32, N_), dim3(32, 8)>>>(x);
    c1_bf16<<<dim3(W_/8, H_/8, N_), 256, C1SMEM>>>();
    gmt<128, 0><<<M_/64, 256>>>(nullptr, nullptr, nullptr);
    p_dwlngelu2<<<M_, 128>>>(dw_w, dw_b, ln_g, ln_b);
    p_offmask2<<<M_/32, 256>>>(off_w, off_b, msk_w, msk_b);
    gmt<256, 1><<<M_/64, 256>>>(in_b, nullptr, nullptr);
    p_dcn2<<<M_/2, 256>>>();
    gmt<256, 2><<<M_/64, 256>>>(nullptr, out, x);
}

// round 16
// speedup vs baseline: 3.3151x; 1.2393x over previous
#include <cuda_runtime.h>
#include <cuda_bf16.h>
#include <math.h>
#include <stdint.h>

// ---------------- problem constants ----------------
#define N_   4
#define C1_  256
#define C2_  256
#define CH_  128
#define H_   80
#define W_   80
#define HW_  6400
#define M_   (N_*HW_)      // 25600 pixels total
#define PL   136           // conv1 smem plane stride

// ---------------- scratch (referenced ONLY inside device code!) ----------------
__device__ float    g_xn[M_*C1_];        // x in NHWC
__device__ uint32_t g_w1b[9*16*16*32*2]; // conv1 w, bf16x2 mma-B fragments, BN-folded
__device__ float    g_b1f[CH_];
__device__ float    g_w2t[CH_*C2_];      // conv2 w [k][o], BN-folded
__device__ float    g_b2f[C2_];
__device__ float    g_inwt[C2_*C2_];     // in_w [k][o]
__device__ float    g_outwt[C2_*C2_];    // out_w [k][o], BN3-folded
__device__ float    g_obf[C2_];
__device__ uint32_t g_w2fb[8*16*32*4];   // conv2 bf16 fragments (kc8, ntp16, lane32, 4)
__device__ uint32_t g_infb[16*16*32*4];  // in_w bf16 fragments
__device__ uint32_t g_outfb[16*16*32*4]; // out_w bf16 fragments
__device__ float    g_y1[M_*CH_];
__device__ float    g_y2[M_*C2_];
__device__ float    g_dw[M_*C2_];
__device__ float    g_xproj[M_*C2_];
__device__ float    g_dcn[M_*C2_];
__device__ float    g_off[M_*18];
__device__ float    g_msk[M_*9];

__device__ __forceinline__ float silu_f(float v) { return v / (1.0f + expf(-v)); }

typedef unsigned long long ull;
__device__ __forceinline__ uint32_t smem_u32(const void* p) {
    uint32_t a;
    asm("{ .reg .u64 t; cvta.to.shared.u64 t, %1; cvt.u32.u64 %0, t; }" : "=r"(a) : "l"(p));
    return a;
}
__device__ __forceinline__ void cp4(uint32_t sa, const float* ga, uint32_t sz) {
    asm volatile("cp.async.ca.shared.global [%0], [%1], 4, %2;\n"
                 :: "r"(sa), "l"(ga), "r"(sz));
}
__device__ __forceinline__ void cp16(uint32_t sa, const void* ga) {
    asm volatile("cp.async.ca.shared.global [%0], [%1], 16;\n"
                 :: "r"(sa), "l"(ga));
}
__device__ __forceinline__ uint32_t pkbf(float lo, float hi) {
    uint32_t r; asm("cvt.rn.bf16x2.f32 %0, %1, %2;" : "=r"(r) : "f"(hi), "f"(lo)); return r;
}
__device__ __forceinline__ void mma_bf16(float* c, uint32_t a0, uint32_t a1,
                                         uint32_t a2, uint32_t a3,
                                         uint32_t b0, uint32_t b1) {
    asm volatile("mma.sync.aligned.m16n8k16.row.col.f32.bf16.bf16.f32 "
                 "{%0,%1,%2,%3}, {%4,%5,%6,%7}, {%8,%9}, {%0,%1,%2,%3};"
                 : "+f"(c[0]), "+f"(c[1]), "+f"(c[2]), "+f"(c[3])
                 : "r"(a0), "r"(a1), "r"(a2), "r"(a3), "r"(b0), "r"(b1));
}

// ================= pack kernels =================
// conv1 weights -> bf16 m16n8k16 B-fragments, BN-folded (validated R15 layout).
__global__ void pk_w1b(const float* __restrict__ w1, const float* __restrict__ g1,
                       const float* __restrict__ b1, const float* __restrict__ m1,
                       const float* __restrict__ v1) {
    int i = blockIdx.x * blockDim.x + threadIdx.x;
    if (i >= 9*16*16*32*2) return;
    int reg  = i & 1;
    int lane = (i >> 1) & 31;
    int nt   = (i >> 6) & 15;
    int cg   = (i >> 10) & 15;
    int kk   = i >> 14;
    int oc = nt*8 + (lane >> 2);
    int ci0 = cg*16 + (lane & 3)*2 + reg*8;
    float sc = g1[oc] * rsqrtf(v1[oc] + 1e-5f);
    float v0 = w1[(size_t)(oc*C1_ + ci0)*9 + kk] * sc;
    float v1v = w1[(size_t)(oc*C1_ + ci0 + 1)*9 + kk] * sc;
    g_w1b[i] = pkbf(v0, v1v);
    if (i < CH_) {
        float s0 = g1[i] * rsqrtf(v1[i] + 1e-5f);
        g_b1f[i] = b1[i] - m1[i]*s0;
    }
}

__global__ void pk_lin(const float* __restrict__ w2, const float* __restrict__ g2,
                       const float* __restrict__ b2, const float* __restrict__ m2,
                       const float* __restrict__ v2, const float* __restrict__ inw,
                       const float* __restrict__ outw, const float* __restrict__ outb,
                       const float* __restrict__ g3, const float* __restrict__ b3,
                       const float* __restrict__ m3, const float* __restrict__ v3) {
    int i = blockIdx.x * blockDim.x + threadIdx.x;
    if (i >= C2_*C2_) return;
    int o = i & 255, k = i >> 8;
    g_inwt[i] = inw[(size_t)o*C2_ + k];
    float s3 = g3[o] * rsqrtf(v3[o] + 1e-5f);
    g_outwt[i] = outw[(size_t)o*C2_ + k] * s3;
    if (k < CH_) {
        float s2 = g2[o] * rsqrtf(v2[o] + 1e-5f);
        g_w2t[(size_t)k*C2_ + o] = w2[(size_t)o*CH_ + k] * s2;
    }
    if (i < C2_) {
        float s2 = g2[i] * rsqrtf(v2[i] + 1e-5f);
        g_b2f[i] = b2[i] - m2[i]*s2;
        float s3b = g3[i] * rsqrtf(v3[i] + 1e-5f);
        g_obf[i] = outb[i]*s3b + b3[i] - m3[i]*s3b;
    }
}

// GEMM bf16 B-fragments: idx = (((kc*16 + ntp)*32 + lane)*4 + half*2 + reg)
// packs W[k][n],W[k+1][n] with k = kc*16 + (lane&3)*2 + reg*8,
// n = (ntp*2 + half)*8 + (lane>>2).  (uint4 per lane = 2 n-tiles)
__global__ void pk_fragb() {
    int i = blockIdx.x * blockDim.x + threadIdx.x;
    if (i >= 16*16*32*4) return;
    int reg  = i & 1;
    int half = (i >> 1) & 1;
    int lane = (i >> 2) & 31;
    int ntp  = (i >> 7) & 15;
    int kc   = i >> 11;
    int k = kc*16 + (lane & 3)*2 + reg*8;
    int n = (ntp*2 + half)*8 + (lane >> 2);
    g_infb[i]  = pkbf(g_inwt[(size_t)k*256 + n],  g_inwt[(size_t)(k+1)*256 + n]);
    g_outfb[i] = pkbf(g_outwt[(size_t)k*256 + n], g_outwt[(size_t)(k+1)*256 + n]);
    if (kc < 8)
        g_w2fb[i] = pkbf(g_w2t[(size_t)k*256 + n], g_w2t[(size_t)(k+1)*256 + n]);
}

// ================= NCHW -> NHWC transpose =================
__global__ void k_tr(const float* __restrict__ x) {
    __shared__ float tile[32][33];
    int n  = blockIdx.z;
    int c0 = blockIdx.y * 32, p0 = blockIdx.x * 32;
    for (int r = threadIdx.y; r < 32; r += 8)
        tile[r][threadIdx.x] = x[(size_t)(n*C1_ + c0 + r)*HW_ + p0 + threadIdx.x];
    __syncthreads();
    for (int r = threadIdx.y; r < 32; r += 8)
        g_xn[(size_t)(n*HW_ + p0 + r)*C1_ + c0 + threadIdx.x] = tile[threadIdx.x][r];
}

// ================= conv1: 3x3 256->128, bf16 mma m16n8k16 (R15 verbatim) =============
extern __shared__ float c1smem[];
__global__ __launch_bounds__(256, 3) void c1_bf16() {
    float*    sIn = c1smem;                          // [2][32*PL]
    uint32_t* sW  = (uint32_t*)(c1smem + 2*32*PL);   // [2][2048]
    int tid = threadIdx.x;
    int n = blockIdx.z;
    int by = blockIdx.y * 8, bx = blockIdx.x * 8;
    int warp = tid >> 5;
    int lane = tid & 31;
    int t  = warp & 3;
    int nh = warp >> 2;
    uint32_t sib = smem_u32(sIn);
    uint32_t swb = smem_u32(sW);

    int py = warp;
    int pak[13]; unsigned ebits = 0, vbits = 0;
    #pragma unroll
    for (int j = 0; j < 13; j++) {
        int p = py + j*8;
        pak[j] = 0;
        if (p < 100) {
            int hy = p / 10, hx = p - hy*10;
            int gy = by + hy - 1, gx = bx + hx - 1;
            bool v = (gy >= 0 && gy < H_ && gx >= 0 && gx < W_);
            int pix = v ? (n*HW_ + gy*W_ + gx) : 0;
            pak[j] = ((pix*256 + lane) << 7) | (hy*12 + hx);
            ebits |= 1u << j;
            if (v) vbits |= 1u << j;
        }
    }
    auto load_input = [&](int cc, int b) {
        uint32_t soff0 = sib + (uint32_t)(b * 32 * PL + lane * PL) * 4u;
        #pragma unroll
        for (int j = 0; j < 13; j++) {
            if (ebits >> j & 1) {
                uint32_t sa = soff0 + (uint32_t)(pak[j] & 127) * 4u;
                uint32_t sz = (vbits >> j & 1) ? 4u : 0u;
                cp4(sa, g_xn + (pak[j] >> 7) + cc, sz);
            }
        }
        asm volatile("cp.async.commit_group;");
    };
    auto load_w = [&](int c, int kk, int b) {
        const uint32_t* src = g_w1b + (size_t)(kk*16 + c*2)*1024 + tid*8;
        uint32_t dst = swb + (uint32_t)(b*2048 + tid*8)*4u;
        cp16(dst, src);
        cp16(dst + 16u, src + 4);
        asm volatile("cp.async.commit_group;");
    };

    load_input(0, 0);
    load_w(0, 0, 0);
    asm volatile("cp.async.wait_group 0;");
    __syncthreads();

    float acc[8][4];
    #pragma unroll
    for (int nt = 0; nt < 8; nt++)
        #pragma unroll
        for (int j = 0; j < 4; j++) acc[nt][j] = 0.0f;

    int arow = lane >> 2;
    int ib = 0, wb = 0;
    #pragma unroll 1
    for (int c = 0; c < 8; c++) {
        #pragma unroll 1
        for (int kk = 0; kk < 9; kk++) {
            bool last = (c == 7) && (kk == 8);
            if (!last) {
                int nc = c, nkk = kk + 1;
                if (nkk == 9) { nc = c + 1; nkk = 0; }
                load_w(nc, nkk, wb ^ 1);
            }
            if (kk == 0 && c < 7) load_input((c + 1)*32, ib ^ 1);

            int dy = kk / 3, dx = kk - 3*dy;
            int posb = (2*t + dy)*12 + arow + dx;
            #pragma unroll
            for (int cig = 0; cig < 2; cig++) {
                const float* pl = &sIn[(ib*32 + cig*16 + 2*(lane & 3)) * PL];
                uint32_t a0 = pkbf(pl[posb],            pl[PL + posb]);
                uint32_t a1 = pkbf(pl[posb + 12],       pl[PL + posb + 12]);
                uint32_t a2 = pkbf(pl[8*PL + posb],     pl[9*PL + posb]);
                uint32_t a3 = pkbf(pl[8*PL + posb + 12],pl[9*PL + posb + 12]);
                const uint32_t* wp = &sW[wb*2048 + cig*1024 + nh*8*64 + lane*2];
                #pragma unroll
                for (int nt = 0; nt < 8; nt++) {
                    uint2 bb = *(const uint2*)(wp + nt*64);
                    mma_bf16(acc[nt], a0, a1, a2, a3, bb.x, bb.y);
                }
            }

            if (!last) asm volatile("cp.async.wait_group 0;");
            __syncthreads();
            wb ^= 1;
        }
        ib ^= 1;
    }

    int pxcol = lane >> 2;
    size_t px0 = (size_t)(n*HW_ + (by + 2*t)*W_ + bx + pxcol) * CH_;
    size_t px1 = px0 + (size_t)W_ * CH_;
    int ocb = nh*64 + 2*(lane & 3);
    #pragma unroll
    for (int nt = 0; nt < 8; nt++) {
        int oc = ocb + nt*8;
        float b0 = g_b1f[oc], b1 = g_b1f[oc+1];
        float2 r0 = {silu_f(acc[nt][0] + b0), silu_f(acc[nt][1] + b1)};
        float2 r1 = {silu_f(acc[nt][2] + b0), silu_f(acc[nt][3] + b1)};
        *(float2*)&g_y1[px0 + oc] = r0;
        *(float2*)&g_y1[px1 + oc] = r1;
    }
}

// ================= bf16 GEMM: out[M,256] = A[M,KD] @ W[KD,256] (+epilogue) ==========
// Same block/warp shape & epilogue as R13 tf32 version; k16 halves mma count.
// MODE 0 (conv2):  A=g_y1  WF=g_w2fb  bias=g_b2f  SiLU -> g_y2
// MODE 1 (inproj): A=g_y2  WF=g_infb  bias=ext    none -> g_xproj
// MODE 2 (outproj):A=g_dcn WF=g_outfb bias=g_obf  SiLU+resid -> ext out (NCHW)
template<int KD, int MODE>
__global__ __launch_bounds__(256) void gmb(const float* __restrict__ bias_ext,
                                           float* __restrict__ out_ext,
                                           const float* __restrict__ resid_ext) {
    const float* A     = (MODE == 0) ? g_y1   : (MODE == 1 ? g_y2   : g_dcn);
    const uint32_t* WF = (MODE == 0) ? g_w2fb : (MODE == 1 ? g_infb : g_outfb);
    const float* bias  = (MODE == 0) ? g_b2f  : (MODE == 1 ? bias_ext : g_obf);
    float* C           = (MODE == 0) ? g_y2   : (MODE == 1 ? g_xproj : out_ext);

    __shared__ float As[2][64][36];
    int tid = threadIdx.x;
    int warp = tid >> 5, lane = tid & 31;
    int t = warp & 3, nh = warp >> 2;
    int m0 = blockIdx.x * 64;

    float acc[16][4];
    #pragma unroll
    for (int j = 0; j < 16; j++)
        #pragma unroll
        for (int q = 0; q < 4; q++) acc[j][q] = 0.0f;

    int lr = tid >> 2;
    int lk = (tid & 3) * 8;

    float4 ra = *(const float4*)&A[(size_t)(m0 + lr)*KD + lk];
    float4 rb = *(const float4*)&A[(size_t)(m0 + lr)*KD + lk + 4];

    int am = 16*t + (lane >> 2);
    int buf = 0;
    for (int k0 = 0; k0 < KD; k0 += 32) {
        *(float4*)&As[buf][lr][lk]     = ra;
        *(float4*)&As[buf][lr][lk + 4] = rb;
        __syncthreads();
        if (k0 + 32 < KD) {
            ra = *(const float4*)&A[(size_t)(m0 + lr)*KD + k0 + 32 + lk];
            rb = *(const float4*)&A[(size_t)(m0 + lr)*KD + k0 + 32 + lk + 4];
        }
        #pragma unroll
        for (int ks = 0; ks < 2; ks++) {
            int kof = ks*16 + (lane & 3)*2;
            float2 f0 = *(const float2*)&As[buf][am][kof];
            float2 f1 = *(const float2*)&As[buf][am + 8][kof];
            float2 f2 = *(const float2*)&As[buf][am][kof + 8];
            float2 f3 = *(const float2*)&As[buf][am + 8][kof + 8];
            uint32_t a0 = pkbf(f0.x, f0.y);
            uint32_t a1 = pkbf(f1.x, f1.y);
            uint32_t a2 = pkbf(f2.x, f2.y);
            uint32_t a3 = pkbf(f3.x, f3.y);
            int kc = (k0 >> 4) + ks;
            const uint32_t* wp = &WF[(((size_t)kc*16 + nh*8)*32 + lane)*4];
            #pragma unroll
            for (int jp = 0; jp < 8; jp++) {
                uint4 bb = *(const uint4*)(wp + jp*128);
                mma_bf16(acc[2*jp],   a0, a1, a2, a3, bb.x, bb.y);
                mma_bf16(acc[2*jp+1], a0, a1, a2, a3, bb.z, bb.w);
            }
        }
        buf ^= 1;
    }

    int r0 = m0 + 16*t + (lane >> 2);
    int r1 = r0 + 8;
    int nimg = m0 / HW_;
    int pp0 = r0 - nimg*HW_, pp1 = r1 - nimg*HW_;
    int ncb = nh*128 + 2*(lane & 3);
    #pragma unroll
    for (int j = 0; j < 16; j++) {
        int nn = ncb + j*8;
        float b0 = bias[nn], b1 = bias[nn+1];
        float v0 = acc[j][0] + b0, v1 = acc[j][1] + b1;
        float v2 = acc[j][2] + b0, v3 = acc[j][3] + b1;
        if (MODE == 0 || MODE == 2) {
            v0 = silu_f(v0); v1 = silu_f(v1);
            v2 = silu_f(v2); v3 = silu_f(v3);
        }
        if (MODE <= 1) {
            *(float2*)&C[(size_t)r0*256 + nn] = make_float2(v0, v1);
            *(float2*)&C[(size_t)r1*256 + nn] = make_float2(v2, v3);
        } else {
            size_t b0i = (size_t)(nimg*256 + nn)*HW_;
            C[b0i + pp0]        = resid_ext[b0i + pp0]        + v0;
            C[b0i + HW_ + pp0]  = resid_ext[b0i + HW_ + pp0]  + v1;
            C[b0i + pp1]        = resid_ext[b0i + pp1]        + v2;
            C[b0i + HW_ + pp1]  = resid_ext[b0i + HW_ + pp1]  + v3;
        }
    }
}

// ================= depthwise 3x3 + bias + LayerNorm + GELU =================
__global__ __launch_bounds__(128) void p_dwlngelu2(const float* __restrict__ dww,
                                                   const float* __restrict__ dwb,
                                                   const float* __restrict__ lng,
                                                   const float* __restrict__ lnb) {
    int p = blockIdx.x;
    int n = p / HW_, pp = p - n*HW_;
    int y = pp / W_, xx = pp - y*W_;
    int c2 = threadIdx.x;
    int c0 = 2*c2;

    float2 acc = {0.0f, 0.0f};
    for (int ky = 0; ky < 3; ky++) {
        int gy = y + ky - 1;
        if (gy < 0 || gy >= H_) continue;
        for (int kx = 0; kx < 3; kx++) {
            int gx = xx + kx - 1;
            if (gx < 0 || gx >= W_) continue;
            float2 v = *(const float2*)&g_y2[(size_t)(n*HW_ + gy*W_ + gx)*C2_ + c0];
            int kk = ky*3 + kx;
            acc.x = fmaf(v.x, dww[c0*9 + kk], acc.x);
            acc.y = fmaf(v.y, dww[(c0+1)*9 + kk], acc.y);
        }
    }
    acc.x += dwb[c0];
    acc.y += dwb[c0+1];

    __shared__ float red[4], red2[4];
    int warp = c2 >> 5, lane = c2 & 31;
    float s = acc.x + acc.y;
    #pragma unroll
    for (int o = 16; o; o >>= 1) s += __shfl_xor_sync(0xffffffffu, s, o);
    if (lane == 0) red[warp] = s;
    __syncthreads();
    float mu = (red[0] + red[1] + red[2] + red[3]) * (1.0f/256.0f);

    float d0 = acc.x - mu, d1 = acc.y - mu;
    float v2 = d0*d0 + d1*d1;
    #pragma unroll
    for (int o = 16; o; o >>= 1) v2 += __shfl_xor_sync(0xffffffffu, v2, o);
    if (lane == 0) red2[warp] = v2;
    __syncthreads();
    float var = (red2[0] + red2[1] + red2[2] + red2[3]) * (1.0f/256.0f);
    float rs = rsqrtf(var + 1e-6f);

    float o0 = d0 * rs * lng[c0]   + lnb[c0];
    float o1 = d1 * rs * lng[c0+1] + lnb[c0+1];
    float2 g;
    g.x = 0.5f * o0 * (1.0f + erff(o0 * 0.70710678118654752f));
    g.y = 0.5f * o1 * (1.0f + erff(o1 * 0.70710678118654752f));
    *(float2*)&g_dw[(size_t)p*C2_ + c0] = g;
}

// ================= offset + mask heads =================
__global__ __launch_bounds__(256) void p_offmask2(const float* __restrict__ offw,
                                                  const float* __restrict__ offb,
                                                  const float* __restrict__ mskw,
                                                  const float* __restrict__ mskb) {
    __shared__ float wsm[27*256];
    __shared__ float sdw[256];
    __shared__ float sres[27];
    int tid = threadIdx.x;
    int warp = tid >> 5, lane = tid & 31;

    #pragma unroll
    for (int i = tid; i < 27*256; i += 256) {
        int r = i >> 8, c = i & 255;
        wsm[i] = (r < 18) ? offw[r*256 + c] : mskw[(r - 18)*256 + c];
    }
    __syncthreads();

    int p0 = blockIdx.x * 32;
    for (int pi = 0; pi < 32; pi++) {
        int p = p0 + pi;
        sdw[tid] = g_dw[(size_t)p*256 + tid];
        __syncthreads();
        for (int r = warp; r < 27; r += 8) {
            const float* wr = &wsm[r*256];
            float s = 0.0f;
            #pragma unroll
            for (int k = 0; k < 8; k++) s += sdw[lane + 32*k] * wr[lane + 32*k];
            #pragma unroll
            for (int o = 16; o; o >>= 1) s += __shfl_xor_sync(0xffffffffu, s, o);
            if (lane == 0) sres[r] = s;
        }
        __syncthreads();
        if (tid < 18) g_off[(size_t)p*18 + tid] = sres[tid] + offb[tid];
        if (tid == 0) {
            float l[9], mx = -1e30f;
            #pragma unroll
            for (int k = 0; k < 9; k++) { l[k] = sres[18+k] + mskb[k]; mx = fmaxf(mx, l[k]); }
            float se = 0.0f;
            #pragma unroll
            for (int k = 0; k < 9; k++) { l[k] = expf(l[k] - mx); se += l[k]; }
            float inv = 1.0f / se;
            #pragma unroll
            for (int k = 0; k < 9; k++) g_msk[(size_t)p*9 + k] = l[k]*inv;
        }
        __syncthreads();
    }
}

// ================= DCNv3 core (4 pixels/block, float4 channels) =================
__global__ __launch_bounds__(256) void p_dcn4() {
    int tid  = threadIdx.x;
    int half = tid >> 6;           // 0..3 -> pixel within block
    int c4   = tid & 63;           // channel quad index
    int p = blockIdx.x * 4 + half;
    int n = p / HW_, pp = p - n*HW_;
    int y = pp / W_, xx = pp - y*W_;

    __shared__ float sw[4][9][4];
    __shared__ int   sx0[4][9], sy0[4][9];
    if (c4 < 9) {
        int k = c4;
        float m  = g_msk[(size_t)p*9 + k];
        float ox = g_off[(size_t)p*18 + 2*k];
        float oy = g_off[(size_t)p*18 + 2*k + 1];
        float px = (float)xx + (float)(k/3) + ox;
        float py = (float)y  + (float)(k%3) + oy;
        float x0f = floorf(px), y0f = floorf(py);
        float lw = px - x0f, lh = py - y0f;
        sw[half][k][0] = m * (1.0f - lh) * (1.0f - lw);
        sw[half][k][1] = m * (1.0f - lh) * lw;
        sw[half][k][2] = m * lh * (1.0f - lw);
        sw[half][k][3] = m * lh * lw;
        sx0[half][k] = (int)x0f;
        sy0[half][k] = (int)y0f;
    }
    __syncthreads();

    const float* Xb = &g_xproj[(size_t)n * HW_ * C2_];
    float4 acc = {0.0f, 0.0f, 0.0f, 0.0f};
    for (int k = 0; k < 9; k++) {
        int x0 = sx0[half][k], y0 = sy0[half][k];
        #pragma unroll
        for (int t = 0; t < 4; t++) {
            int xi = x0 + (t & 1);
            int yi = y0 + (t >> 1);
            if (xi >= 1 && xi <= W_ && yi >= 1 && yi <= H_) {
                float4 v = *(const float4*)&Xb[(size_t)((yi-1)*W_ + (xi-1))*C2_ + 4*c4];
                float wv = sw[half][k][t];
                acc.x = fmaf(wv, v.x, acc.x);
                acc.y = fmaf(wv, v.y, acc.y);
                acc.z = fmaf(wv, v.z, acc.z);
                acc.w = fmaf(wv, v.w, acc.w);
            }
        }
    }
    *(float4*)&g_dcn[(size_t)p*C2_ + 4*c4] = acc;
}

// ---------------- launch ----------------
extern "C" void kernel_launch(void* const* d_in, const int* in_sizes, int n_in,
                              void* d_out, int out_size) {
    const float* x     = (const float*)d_in[0];
    const float* w1    = (const float*)d_in[1];
    const float* g1    = (const float*)d_in[2];
    const float* b1    = (const float*)d_in[3];
    const float* m1    = (const float*)d_in[4];
    const float* v1    = (const float*)d_in[5];
    const float* w2    = (const float*)d_in[6];
    const float* g2    = (const float*)d_in[7];
    const float* b2    = (const float*)d_in[8];
    const float* m2    = (const float*)d_in[9];
    const float* v2    = (const float*)d_in[10];
    const float* dw_w  = (const float*)d_in[11];
    const float* dw_b  = (const float*)d_in[12];
    const float* ln_g  = (const float*)d_in[13];
    const float* ln_b  = (const float*)d_in[14];
    const float* off_w = (const float*)d_in[15];
    const float* off_b = (const float*)d_in[16];
    const float* msk_w = (const float*)d_in[17];
    const float* msk_b = (const float*)d_in[18];
    const float* in_w  = (const float*)d_in[19];
    const float* in_b  = (const float*)d_in[20];
    const float* out_w = (const float*)d_in[21];
    const float* out_b = (const float*)d_in[22];
    const float* g3    = (const float*)d_in[23];
    const float* b3    = (const float*)d_in[24];
    const float* m3    = (const float*)d_in[25];
    const float* v3    = (const float*)d_in[26];
    float* out = (float*)d_out;

    const int C1SMEM = (2*32*PL)*4 + (2*2048)*4;   // 51200 bytes
    cudaFuncSetAttribute(c1_bf16, cudaFuncAttributeMaxDynamicSharedMemorySize, C1SMEM);

    pk_w1b<<<(9*16*16*32*2 + 255)/256, 256>>>(w1, g1, b1, m1, v1);
    pk_lin<<<(C2_*C2_ + 255)/256, 256>>>(w2, g2, b2, m2, v2, in_w, out_w, out_b,
                                         g3, b3, m3, v3);
    pk_fragb<<<(16*16*32*4 + 255)/256, 256>>>();
    k_tr<<<dim3(HW_/32, C1_/32, N_), dim3(32, 8)>>>(x);
    c1_bf16<<<dim3(W_/8, H_/8, N_), 256, C1SMEM>>>();
    gmb<128, 0><<<M_/64, 256>>>(nullptr, nullptr, nullptr);
    p_dwlngelu2<<<M_, 128>>>(dw_w, dw_b, ln_g, ln_b);
    p_offmask2<<<M_/32, 256>>>(off_w, off_b, msk_w, msk_b);
    gmb<256, 1><<<M_/64, 256>>>(in_b, nullptr, nullptr);
    p_dcn4<<<M_/4, 256>>>();
    gmb<256, 2><<<M_/64, 256>>>(nullptr, out, x);
}

// round 17
// speedup vs baseline: 3.6345x; 1.0963x over previous
#include <cuda_runtime.h>
#include <cuda_bf16.h>
#include <math.h>
#include <stdint.h>

// ---------------- problem constants ----------------
#define N_   4
#define C1_  256
#define C2_  256
#define CH_  128
#define H_   80
#define W_   80
#define HW_  6400
#define M_   (N_*HW_)      // 25600 pixels total
#define PLB  136           // conv1 smem plane stride (u32 units, pair planes)

// ---------------- scratch (referenced ONLY inside device code!) ----------------
__device__ uint32_t g_xb[M_*128];        // x in NHWC, bf16x2 channel pairs
__device__ uint32_t g_w1b[9*16*16*32*2]; // conv1 w, bf16x2 mma-B fragments, BN-folded
__device__ float    g_b1f[CH_];
__device__ float    g_w2t[CH_*C2_];      // conv2 w [k][o], BN-folded
__device__ float    g_b2f[C2_];
__device__ float    g_inwt[C2_*C2_];     // in_w [k][o]
__device__ float    g_outwt[C2_*C2_];    // out_w [k][o], BN3-folded
__device__ float    g_obf[C2_];
__device__ uint32_t g_w2fb[8*16*32*4];   // conv2 bf16 fragments
__device__ uint32_t g_infb[16*16*32*4];  // in_w bf16 fragments
__device__ uint32_t g_outfb[16*16*32*4]; // out_w bf16 fragments
__device__ float    g_y1[M_*CH_];
__device__ float    g_y2[M_*C2_];
__device__ float    g_dw[M_*C2_];
__device__ float    g_xproj[M_*C2_];
__device__ float    g_dcn[M_*C2_];
__device__ float    g_off[M_*18];
__device__ float    g_msk[M_*9];

__device__ __forceinline__ float silu_f(float v) { return v / (1.0f + expf(-v)); }

typedef unsigned long long ull;
__device__ __forceinline__ uint32_t smem_u32(const void* p) {
    uint32_t a;
    asm("{ .reg .u64 t; cvta.to.shared.u64 t, %1; cvt.u32.u64 %0, t; }" : "=r"(a) : "l"(p));
    return a;
}
__device__ __forceinline__ void cp4(uint32_t sa, const void* ga, uint32_t sz) {
    asm volatile("cp.async.ca.shared.global [%0], [%1], 4, %2;\n"
                 :: "r"(sa), "l"(ga), "r"(sz));
}
__device__ __forceinline__ void cp16(uint32_t sa, const void* ga) {
    asm volatile("cp.async.ca.shared.global [%0], [%1], 16;\n"
                 :: "r"(sa), "l"(ga));
}
__device__ __forceinline__ uint32_t pkbf(float lo, float hi) {
    uint32_t r; asm("cvt.rn.bf16x2.f32 %0, %1, %2;" : "=r"(r) : "f"(hi), "f"(lo)); return r;
}
__device__ __forceinline__ void mma_bf16(float* c, uint32_t a0, uint32_t a1,
                                         uint32_t a2, uint32_t a3,
                                         uint32_t b0, uint32_t b1) {
    asm volatile("mma.sync.aligned.m16n8k16.row.col.f32.bf16.bf16.f32 "
                 "{%0,%1,%2,%3}, {%4,%5,%6,%7}, {%8,%9}, {%0,%1,%2,%3};"
                 : "+f"(c[0]), "+f"(c[1]), "+f"(c[2]), "+f"(c[3])
                 : "r"(a0), "r"(a1), "r"(a2), "r"(a3), "r"(b0), "r"(b1));
}

// ================= pack kernels =================
__global__ void pk_w1b(const float* __restrict__ w1, const float* __restrict__ g1,
                       const float* __restrict__ b1, const float* __restrict__ m1,
                       const float* __restrict__ v1) {
    int i = blockIdx.x * blockDim.x + threadIdx.x;
    if (i >= 9*16*16*32*2) return;
    int reg  = i & 1;
    int lane = (i >> 1) & 31;
    int nt   = (i >> 6) & 15;
    int cg   = (i >> 10) & 15;
    int kk   = i >> 14;
    int oc = nt*8 + (lane >> 2);
    int ci0 = cg*16 + (lane & 3)*2 + reg*8;
    float sc = g1[oc] * rsqrtf(v1[oc] + 1e-5f);
    float v0 = w1[(size_t)(oc*C1_ + ci0)*9 + kk] * sc;
    float v1v = w1[(size_t)(oc*C1_ + ci0 + 1)*9 + kk] * sc;
    g_w1b[i] = pkbf(v0, v1v);
    if (i < CH_) {
        float s0 = g1[i] * rsqrtf(v1[i] + 1e-5f);
        g_b1f[i] = b1[i] - m1[i]*s0;
    }
}

__global__ void pk_lin(const float* __restrict__ w2, const float* __restrict__ g2,
                       const float* __restrict__ b2, const float* __restrict__ m2,
                       const float* __restrict__ v2, const float* __restrict__ inw,
                       const float* __restrict__ outw, const float* __restrict__ outb,
                       const float* __restrict__ g3, const float* __restrict__ b3,
                       const float* __restrict__ m3, const float* __restrict__ v3) {
    int i = blockIdx.x * blockDim.x + threadIdx.x;
    if (i >= C2_*C2_) return;
    int o = i & 255, k = i >> 8;
    g_inwt[i] = inw[(size_t)o*C2_ + k];
    float s3 = g3[o] * rsqrtf(v3[o] + 1e-5f);
    g_outwt[i] = outw[(size_t)o*C2_ + k] * s3;
    if (k < CH_) {
        float s2 = g2[o] * rsqrtf(v2[o] + 1e-5f);
        g_w2t[(size_t)k*C2_ + o] = w2[(size_t)o*CH_ + k] * s2;
    }
    if (i < C2_) {
        float s2 = g2[i] * rsqrtf(v2[i] + 1e-5f);
        g_b2f[i] = b2[i] - m2[i]*s2;
        float s3b = g3[i] * rsqrtf(v3[i] + 1e-5f);
        g_obf[i] = outb[i]*s3b + b3[i] - m3[i]*s3b;
    }
}

__global__ void pk_fragb() {
    int i = blockIdx.x * blockDim.x + threadIdx.x;
    if (i >= 16*16*32*4) return;
    int reg  = i & 1;
    int half = (i >> 1) & 1;
    int lane = (i >> 2) & 31;
    int ntp  = (i >> 7) & 15;
    int kc   = i >> 11;
    int k = kc*16 + (lane & 3)*2 + reg*8;
    int n = (ntp*2 + half)*8 + (lane >> 2);
    g_infb[i]  = pkbf(g_inwt[(size_t)k*256 + n],  g_inwt[(size_t)(k+1)*256 + n]);
    g_outfb[i] = pkbf(g_outwt[(size_t)k*256 + n], g_outwt[(size_t)(k+1)*256 + n]);
    if (kc < 8)
        g_w2fb[i] = pkbf(g_w2t[(size_t)k*256 + n], g_w2t[(size_t)(k+1)*256 + n]);
}

// ================= NCHW -> NHWC bf16x2-pair transpose =================
__global__ void k_trb(const float* __restrict__ x) {
    __shared__ float tile[32][33];        // [channel][pixel]
    int n  = blockIdx.z;
    int c0 = blockIdx.y * 32, p0 = blockIdx.x * 32;
    for (int r = threadIdx.y; r < 32; r += 8)
        tile[r][threadIdx.x] = x[(size_t)(n*C1_ + c0 + r)*HW_ + p0 + threadIdx.x];
    __syncthreads();
    int tid = threadIdx.y*32 + threadIdx.x;
    int j = tid & 15, pxb = tid >> 4;
    #pragma unroll
    for (int q = 0; q < 2; q++) {
        int px = pxb + q*16;
        uint32_t v = pkbf(tile[2*j][px], tile[2*j+1][px]);
        g_xb[(size_t)(n*HW_ + p0 + px)*128 + (c0 >> 1) + j] = v;
    }
}

// ================= conv1: 3x3 256->128, bf16 mma, row-batched taps =============
// 8x8 px tile x 128 oc; 8 warps = 4 m-tiles x 2 oc halves.
// Input staged as bf16x2 channel-pair planes (direct u32 a-frag LDS, no cvt).
// Weights staged 3 taps (one kernel row) per barrier: 24 iterations total.
// Dynamic smem: sInB 2x16xPLB u32 (17408B) + sW 2x3x2048 u32 (49152B) = 66560B.
extern __shared__ uint32_t c1smem[];
__global__ __launch_bounds__(256, 3) void c1_bf16() {
    uint32_t* sInB = c1smem;                 // [2][16*PLB]
    uint32_t* sW   = c1smem + 2*16*PLB;      // [2][3*2048]
    int tid = threadIdx.x;
    int n = blockIdx.z;
    int by = blockIdx.y * 8, bx = blockIdx.x * 8;
    int warp = tid >> 5;
    int lane = tid & 31;
    int t  = warp & 3;
    int nh = warp >> 2;
    uint32_t sib = smem_u32(sInB);
    uint32_t swb = smem_u32(sW);

    // ---- input loader: lane = (s:1)(pr:4); 7 pixel slots each ----
    int py = warp;
    int s  = lane >> 4;
    int pr = lane & 15;
    int pak[7]; unsigned ebits = 0, vbits = 0;
    #pragma unroll
    for (int j = 0; j < 7; j++) {
        int q = 2*j + s;
        int p = py + q*8;
        pak[j] = 0;
        if (p < 100) {
            int hy = p / 10, hx = p - hy*10;
            int gy = by + hy - 1, gx = bx + hx - 1;
            bool v = (gy >= 0 && gy < H_ && gx >= 0 && gx < W_);
            int pix = v ? (n*HW_ + gy*W_ + gx) : 0;
            pak[j] = ((pix*128 + pr) << 7) | (hy*12 + hx);
            ebits |= 1u << j;
            if (v) vbits |= 1u << j;
        }
    }
    auto load_input = [&](int cc, int b) {
        uint32_t soff0 = sib + (uint32_t)(b*16*PLB + pr*PLB) * 4u;
        #pragma unroll
        for (int j = 0; j < 7; j++) {
            if (ebits >> j & 1) {
                uint32_t sa = soff0 + (uint32_t)(pak[j] & 127) * 4u;
                uint32_t sz = (vbits >> j & 1) ? 4u : 0u;
                cp4(sa, g_xb + (pak[j] >> 7) + (cc >> 1), sz);
            }
        }
        asm volatile("cp.async.commit_group;");
    };

    // ---- weight row loader: 3 slabs (taps dy*3+0..2) of chunk c ----
    auto load_w3 = [&](int c, int dy, int b) {
        #pragma unroll
        for (int s3 = 0; s3 < 3; s3++) {
            const uint32_t* src = g_w1b + (size_t)((dy*3 + s3)*16 + c*2)*1024 + tid*8;
            uint32_t dst = swb + (uint32_t)(b*6144 + s3*2048 + tid*8)*4u;
            cp16(dst, src);
            cp16(dst + 16u, src + 4);
        }
        asm volatile("cp.async.commit_group;");
    };

    load_input(0, 0);
    load_w3(0, 0, 0);
    asm volatile("cp.async.wait_group 0;");
    __syncthreads();

    float acc[8][4];
    #pragma unroll
    for (int nt = 0; nt < 8; nt++)
        #pragma unroll
        for (int j = 0; j < 4; j++) acc[nt][j] = 0.0f;

    int arow = lane >> 2;
    int ib = 0, wb = 0;
    #pragma unroll 1
    for (int c = 0; c < 8; c++) {
        #pragma unroll 1
        for (int dy = 0; dy < 3; dy++) {
            bool last = (c == 7) && (dy == 2);
            if (!last) {
                int nc = c, ndy = dy + 1;
                if (ndy == 3) { nc = c + 1; ndy = 0; }
                load_w3(nc, ndy, wb ^ 1);
            }
            if (dy == 0 && c < 7) load_input((c + 1)*32, ib ^ 1);

            int rowb = (2*t + dy)*12 + arow;
            #pragma unroll
            for (int dx = 0; dx < 3; dx++) {
                int posb = rowb + dx;
                #pragma unroll
                for (int cig = 0; cig < 2; cig++) {
                    const uint32_t* pl = &sInB[(ib*16 + cig*8 + (lane & 3)) * PLB];
                    uint32_t a0 = pl[posb];
                    uint32_t a1 = pl[posb + 12];
                    uint32_t a2 = pl[4*PLB + posb];
                    uint32_t a3 = pl[4*PLB + posb + 12];
                    const uint32_t* wp = &sW[wb*6144 + dx*2048 + cig*1024 + nh*512 + lane*2];
                    #pragma unroll
                    for (int nt = 0; nt < 8; nt++) {
                        uint2 bb = *(const uint2*)(wp + nt*64);
                        mma_bf16(acc[nt], a0, a1, a2, a3, bb.x, bb.y);
                    }
                }
            }

            if (!last) asm volatile("cp.async.wait_group 0;");
            __syncthreads();
            wb ^= 1;
        }
        ib ^= 1;
    }

    int pxcol = lane >> 2;
    size_t px0 = (size_t)(n*HW_ + (by + 2*t)*W_ + bx + pxcol) * CH_;
    size_t px1 = px0 + (size_t)W_ * CH_;
    int ocb = nh*64 + 2*(lane & 3);
    #pragma unroll
    for (int nt = 0; nt < 8; nt++) {
        int oc = ocb + nt*8;
        float b0 = g_b1f[oc], b1 = g_b1f[oc+1];
        float2 r0 = {silu_f(acc[nt][0] + b0), silu_f(acc[nt][1] + b1)};
        float2 r1 = {silu_f(acc[nt][2] + b0), silu_f(acc[nt][3] + b1)};
        *(float2*)&g_y1[px0 + oc] = r0;
        *(float2*)&g_y1[px1 + oc] = r1;
    }
}

// ================= bf16 GEMM (R16 verbatim) =================
template<int KD, int MODE>
__global__ __launch_bounds__(256) void gmb(const float* __restrict__ bias_ext,
                                           float* __restrict__ out_ext,
                                           const float* __restrict__ resid_ext) {
    const float* A     = (MODE == 0) ? g_y1   : (MODE == 1 ? g_y2   : g_dcn);
    const uint32_t* WF = (MODE == 0) ? g_w2fb : (MODE == 1 ? g_infb : g_outfb);
    const float* bias  = (MODE == 0) ? g_b2f  : (MODE == 1 ? bias_ext : g_obf);
    float* C           = (MODE == 0) ? g_y2   : (MODE == 1 ? g_xproj : out_ext);

    __shared__ float As[2][64][36];
    int tid = threadIdx.x;
    int warp = tid >> 5, lane = tid & 31;
    int t = warp & 3, nh = warp >> 2;
    int m0 = blockIdx.x * 64;

    float acc[16][4];
    #pragma unroll
    for (int j = 0; j < 16; j++)
        #pragma unroll
        for (int q = 0; q < 4; q++) acc[j][q] = 0.0f;

    int lr = tid >> 2;
    int lk = (tid & 3) * 8;

    float4 ra = *(const float4*)&A[(size_t)(m0 + lr)*KD + lk];
    float4 rb = *(const float4*)&A[(size_t)(m0 + lr)*KD + lk + 4];

    int am = 16*t + (lane >> 2);
    int buf = 0;
    for (int k0 = 0; k0 < KD; k0 += 32) {
        *(float4*)&As[buf][lr][lk]     = ra;
        *(float4*)&As[buf][lr][lk + 4] = rb;
        __syncthreads();
        if (k0 + 32 < KD) {
            ra = *(const float4*)&A[(size_t)(m0 + lr)*KD + k0 + 32 + lk];
            rb = *(const float4*)&A[(size_t)(m0 + lr)*KD + k0 + 32 + lk + 4];
        }
        #pragma unroll
        for (int ks = 0; ks < 2; ks++) {
            int kof = ks*16 + (lane & 3)*2;
            float2 f0 = *(const float2*)&As[buf][am][kof];
            float2 f1 = *(const float2*)&As[buf][am + 8][kof];
            float2 f2 = *(const float2*)&As[buf][am][kof + 8];
            float2 f3 = *(const float2*)&As[buf][am + 8][kof + 8];
            uint32_t a0 = pkbf(f0.x, f0.y);
            uint32_t a1 = pkbf(f1.x, f1.y);
            uint32_t a2 = pkbf(f2.x, f2.y);
            uint32_t a3 = pkbf(f3.x, f3.y);
            int kc = (k0 >> 4) + ks;
            const uint32_t* wp = &WF[(((size_t)kc*16 + nh*8)*32 + lane)*4];
            #pragma unroll
            for (int jp = 0; jp < 8; jp++) {
                uint4 bb = *(const uint4*)(wp + jp*128);
                mma_bf16(acc[2*jp],   a0, a1, a2, a3, bb.x, bb.y);
                mma_bf16(acc[2*jp+1], a0, a1, a2, a3, bb.z, bb.w);
            }
        }
        buf ^= 1;
    }

    int r0 = m0 + 16*t + (lane >> 2);
    int r1 = r0 + 8;
    int nimg = m0 / HW_;
    int pp0 = r0 - nimg*HW_, pp1 = r1 - nimg*HW_;
    int ncb = nh*128 + 2*(lane & 3);
    #pragma unroll
    for (int j = 0; j < 16; j++) {
        int nn = ncb + j*8;
        float b0 = bias[nn], b1 = bias[nn+1];
        float v0 = acc[j][0] + b0, v1 = acc[j][1] + b1;
        float v2 = acc[j][2] + b0, v3 = acc[j][3] + b1;
        if (MODE == 0 || MODE == 2) {
            v0 = silu_f(v0); v1 = silu_f(v1);
            v2 = silu_f(v2); v3 = silu_f(v3);
        }
        if (MODE <= 1) {
            *(float2*)&C[(size_t)r0*256 + nn] = make_float2(v0, v1);
            *(float2*)&C[(size_t)r1*256 + nn] = make_float2(v2, v3);
        } else {
            size_t b0i = (size_t)(nimg*256 + nn)*HW_;
            C[b0i + pp0]        = resid_ext[b0i + pp0]        + v0;
            C[b0i + HW_ + pp0]  = resid_ext[b0i + HW_ + pp0]  + v1;
            C[b0i + pp1]        = resid_ext[b0i + pp1]        + v2;
            C[b0i + HW_ + pp1]  = resid_ext[b0i + HW_ + pp1]  + v3;
        }
    }
}

// ================= depthwise 3x3 + bias + LayerNorm + GELU =================
__global__ __launch_bounds__(128) void p_dwlngelu2(const float* __restrict__ dww,
                                                   const float* __restrict__ dwb,
                                                   const float* __restrict__ lng,
                                                   const float* __restrict__ lnb) {
    int p = blockIdx.x;
    int n = p / HW_, pp = p - n*HW_;
    int y = pp / W_, xx = pp - y*W_;
    int c2 = threadIdx.x;
    int c0 = 2*c2;

    float2 acc = {0.0f, 0.0f};
    for (int ky = 0; ky < 3; ky++) {
        int gy = y + ky - 1;
        if (gy < 0 || gy >= H_) continue;
        for (int kx = 0; kx < 3; kx++) {
            int gx = xx + kx - 1;
            if (gx < 0 || gx >= W_) continue;
            float2 v = *(const float2*)&g_y2[(size_t)(n*HW_ + gy*W_ + gx)*C2_ + c0];
            int kk = ky*3 + kx;
            acc.x = fmaf(v.x, dww[c0*9 + kk], acc.x);
            acc.y = fmaf(v.y, dww[(c0+1)*9 + kk], acc.y);
        }
    }
    acc.x += dwb[c0];
    acc.y += dwb[c0+1];

    __shared__ float red[4], red2[4];
    int warp = c2 >> 5, lane = c2 & 31;
    float s = acc.x + acc.y;
    #pragma unroll
    for (int o = 16; o; o >>= 1) s += __shfl_xor_sync(0xffffffffu, s, o);
    if (lane == 0) red[warp] = s;
    __syncthreads();
    float mu = (red[0] + red[1] + red[2] + red[3]) * (1.0f/256.0f);

    float d0 = acc.x - mu, d1 = acc.y - mu;
    float v2 = d0*d0 + d1*d1;
    #pragma unroll
    for (int o = 16; o; o >>= 1) v2 += __shfl_xor_sync(0xffffffffu, v2, o);
    if (lane == 0) red2[warp] = v2;
    __syncthreads();
    float var = (red2[0] + red2[1] + red2[2] + red2[3]) * (1.0f/256.0f);
    float rs = rsqrtf(var + 1e-6f);

    float o0 = d0 * rs * lng[c0]   + lnb[c0];
    float o1 = d1 * rs * lng[c0+1] + lnb[c0+1];
    float2 g;
    g.x = 0.5f * o0 * (1.0f + erff(o0 * 0.70710678118654752f));
    g.y = 0.5f * o1 * (1.0f + erff(o1 * 0.70710678118654752f));
    *(float2*)&g_dw[(size_t)p*C2_ + c0] = g;
}

// ================= offset + mask heads =================
__global__ __launch_bounds__(256) void p_offmask2(const float* __restrict__ offw,
                                                  const float* __restrict__ offb,
                                                  const float* __restrict__ mskw,
                                                  const float* __restrict__ mskb) {
    __shared__ float wsm[27*256];
    __shared__ float sdw[256];
    __shared__ float sres[27];
    int tid = threadIdx.x;
    int warp = tid >> 5, lane = tid & 31;

    #pragma unroll
    for (int i = tid; i < 27*256; i += 256) {
        int r = i >> 8, c = i & 255;
        wsm[i] = (r < 18) ? offw[r*256 + c] : mskw[(r - 18)*256 + c];
    }
    __syncthreads();

    int p0 = blockIdx.x * 32;
    for (int pi = 0; pi < 32; pi++) {
        int p = p0 + pi;
        sdw[tid] = g_dw[(size_t)p*256 + tid];
        __syncthreads();
        for (int r = warp; r < 27; r += 8) {
            const float* wr = &wsm[r*256];
            float s = 0.0f;
            #pragma unroll
            for (int k = 0; k < 8; k++) s += sdw[lane + 32*k] * wr[lane + 32*k];
            #pragma unroll
            for (int o = 16; o; o >>= 1) s += __shfl_xor_sync(0xffffffffu, s, o);
            if (lane == 0) sres[r] = s;
        }
        __syncthreads();
        if (tid < 18) g_off[(size_t)p*18 + tid] = sres[tid] + offb[tid];
        if (tid == 0) {
            float l[9], mx = -1e30f;
            #pragma unroll
            for (int k = 0; k < 9; k++) { l[k] = sres[18+k] + mskb[k]; mx = fmaxf(mx, l[k]); }
            float se = 0.0f;
            #pragma unroll
            for (int k = 0; k < 9; k++) { l[k] = expf(l[k] - mx); se += l[k]; }
            float inv = 1.0f / se;
            #pragma unroll
            for (int k = 0; k < 9; k++) g_msk[(size_t)p*9 + k] = l[k]*inv;
        }
        __syncthreads();
    }
}

// ================= DCNv3 core (4 pixels/block, float4 channels) =================
__global__ __launch_bounds__(256) void p_dcn4() {
    int tid  = threadIdx.x;
    int half = tid >> 6;
    int c4   = tid & 63;
    int p = blockIdx.x * 4 + half;
    int n = p / HW_, pp = p - n*HW_;
    int y = pp / W_, xx = pp - y*W_;

    __shared__ float sw[4][9][4];
    __shared__ int   sx0[4][9], sy0[4][9];
    if (c4 < 9) {
        int k = c4;
        float m  = g_msk[(size_t)p*9 + k];
        float ox = g_off[(size_t)p*18 + 2*k];
        float oy = g_off[(size_t)p*18 + 2*k + 1];
        float px = (float)xx + (float)(k/3) + ox;
        float py = (float)y  + (float)(k%3) + oy;
        float x0f = floorf(px), y0f = floorf(py);
        float lw = px - x0f, lh = py - y0f;
        sw[half][k][0] = m * (1.0f - lh) * (1.0f - lw);
        sw[half][k][1] = m * (1.0f - lh) * lw;
        sw[half][k][2] = m * lh * (1.0f - lw);
        sw[half][k][3] = m * lh * lw;
        sx0[half][k] = (int)x0f;
        sy0[half][k] = (int)y0f;
    }
    __syncthreads();

    const float* Xb = &g_xproj[(size_t)n * HW_ * C2_];
    float4 acc = {0.0f, 0.0f, 0.0f, 0.0f};
    for (int k = 0; k < 9; k++) {
        int x0 = sx0[half][k], y0 = sy0[half][k];
        #pragma unroll
        for (int t = 0; t < 4; t++) {
            int xi = x0 + (t & 1);
            int yi = y0 + (t >> 1);
            if (xi >= 1 && xi <= W_ && yi >= 1 && yi <= H_) {
                float4 v = *(const float4*)&Xb[(size_t)((yi-1)*W_ + (xi-1))*C2_ + 4*c4];
                float wv = sw[half][k][t];
                acc.x = fmaf(wv, v.x, acc.x);
                acc.y = fmaf(wv, v.y, acc.y);
                acc.z = fmaf(wv, v.z, acc.z);
                acc.w = fmaf(wv, v.w, acc.w);
            }
        }
    }
    *(float4*)&g_dcn[(size_t)p*C2_ + 4*c4] = acc;
}

// ---------------- launch ----------------
extern "C" void kernel_launch(void* const* d_in, const int* in_sizes, int n_in,
                              void* d_out, int out_size) {
    const float* x     = (const float*)d_in[0];
    const float* w1    = (const float*)d_in[1];
    const float* g1    = (const float*)d_in[2];
    const float* b1    = (const float*)d_in[3];
    const float* m1    = (const float*)d_in[4];
    const float* v1    = (const float*)d_in[5];
    const float* w2    = (const float*)d_in[6];
    const float* g2    = (const float*)d_in[7];
    const float* b2    = (const float*)d_in[8];
    const float* m2    = (const float*)d_in[9];
    const float* v2    = (const float*)d_in[10];
    const float* dw_w  = (const float*)d_in[11];
    const float* dw_b  = (const float*)d_in[12];
    const float* ln_g  = (const float*)d_in[13];
    const float* ln_b  = (const float*)d_in[14];
    const float* off_w = (const float*)d_in[15];
    const float* off_b = (const float*)d_in[16];
    const float* msk_w = (const float*)d_in[17];
    const float* msk_b = (const float*)d_in[18];
    const float* in_w  = (const float*)d_in[19];
    const float* in_b  = (const float*)d_in[20];
    const float* out_w = (const float*)d_in[21];
    const float* out_b = (const float*)d_in[22];
    const float* g3    = (const float*)d_in[23];
    const float* b3    = (const float*)d_in[24];
    const float* m3    = (const float*)d_in[25];
    const float* v3    = (const float*)d_in[26];
    float* out = (float*)d_out;

    const int C1SMEM = (2*16*PLB + 2*3*2048) * 4;   // 66560 bytes
    cudaFuncSetAttribute(c1_bf16, cudaFuncAttributeMaxDynamicSharedMemorySize, C1SMEM);

    pk_w1b<<<(9*16*16*32*2 + 255)/256, 256>>>(w1, g1, b1, m1, v1);
    pk_lin<<<(C2_*C2_ + 255)/256, 256>>>(w2, g2, b2, m2, v2, in_w, out_w, out_b,
                                         g3, b3, m3, v3);
    pk_fragb<<<(16*16*32*4 + 255)/256, 256>>>();
    k_trb<<<dim3(HW_/32, C1_/32, N_), dim3(32, 8)>>>(x);
    c1_bf16<<<dim3(W_/8, H_/8, N_), 256, C1SMEM>>>();
    gmb<128, 0><<<M_/64, 256>>>(nullptr, nullptr, nullptr);
    p_dwlngelu2<<<M_, 128>>>(dw_w, dw_b, ln_g, ln_b);
    p_offmask2<<<M_/32, 256>>>(off_w, off_b, msk_w, msk_b);
    gmb<256, 1><<<M_/64, 256>>>(in_b, nullptr, nullptr);
    p_dcn4<<<M_/4, 256>>>();
    gmb<256, 2><<<M_/64, 256>>>(nullptr, out, x);
}